// round 1
// baseline (speedup 1.0000x reference)
#include <cuda_runtime.h>
#include <math.h>

typedef unsigned long long ull;

#define NB   16384
#define DD   512
#define NE   8
#define NH1  1024
#define NH2  512
#define TT1  256
#define TT2  128
#define PEN  5
#define KAIT 2560   // D*PE

// ---- output layout (tuple flattened in order) ----
#define O0 ((size_t)0)                       // pctr        [B]
#define O1 ((size_t)NB)                      // pcvr        [B]
#define O2 ((size_t)2*NB)                    // pconversion [B]
#define O3 ((size_t)3*NB)                    // task_fea t0 [B,512]
#define O4 (O3 + (size_t)NB*512)             // task_fea t1 [B,512]
#define O5 (O4 + (size_t)NB*512)             // ctask       [B,512]
#define O6 (O5 + (size_t)NB*512)             // th2 t0      [B,128]
#define O7 (O6 + (size_t)NB*128)             // th2 t1      [B,128]
#define O8 (O7 + (size_t)NB*128)             // ch2         [B,128]

// ---- scratch (static device globals; no allocation) ----
__device__ float g_H   [(size_t)NE*NB*NH1];   // 512 MB, reused as CH
__device__ float g_FEA [(size_t)NE*NB*NH2];   // 256 MB, reused as CFEA
__device__ float g_AIT [(size_t)NB*KAIT];     // 160 MB
__device__ float g_TH1 [(size_t)2*NB*TT1];
__device__ float g_CH1 [(size_t)NB*TT1];
__device__ float g_GATES[(size_t)NB*2*8];
__device__ float g_CGATE[(size_t)NB*8];

// ---- f32x2 helpers (packed dual-FMA; 2x FFMA throughput on sm_103a) ----
__device__ __forceinline__ ull pk2(float lo, float hi) {
    ull r;
    asm("mov.b64 %0, {%1, %2};" : "=l"(r) : "f"(lo), "f"(hi));
    return r;
}
__device__ __forceinline__ void fma2(ull& d, ull a, ull b) {
    asm("fma.rn.f32x2 %0, %1, %2, %0;" : "+l"(d) : "l"(a), "l"(b));
}
__device__ __forceinline__ void upk2(ull v, float& lo, float& hi) {
    unsigned int a, b;
    asm("mov.b64 {%0, %1}, %2;" : "=r"(a), "=r"(b) : "l"(v));
    lo = __uint_as_float(a); hi = __uint_as_float(b);
}

// ============================================================
// Tiled SGEMM: C[z] = relu(A[z] @ W[z] + bias[z])
// A row-major [M,K], W row-major [K,N]. 128x128x16 tiles, 8x8/thread.
// Requires M%128==0, N%128==0, K%16==0 (all shapes here comply).
// ============================================================
__global__ void __launch_bounds__(256, 2) gemm_bias_relu(
    const float* __restrict__ A, const float* __restrict__ W,
    const float* __restrict__ bias, float* __restrict__ C,
    int M, int N, int K,
    size_t sA, size_t sW, size_t sB, size_t sC)
{
    const int BK = 16;
    __shared__ float As[BK][128];
    __shared__ float Ws[BK][128];

    int z = blockIdx.z;
    A    += (size_t)z * sA;
    W    += (size_t)z * sW;
    bias += (size_t)z * sB;
    C    += (size_t)z * sC;

    int bm = blockIdx.y << 7;
    int bn = blockIdx.x << 7;
    int tid = threadIdx.x;
    int tm = (tid >> 4) << 3;     // 0..120
    int tn = (tid & 15) << 3;     // 0..120

    int ar = tid >> 2, ac = (tid & 3) << 2;   // A: 128 rows x 16 cols (2 passes of 64 rows)
    int wr = tid >> 5, wc = (tid & 31) << 2;  // W: 16 rows x 128 cols (2 passes of 8 rows)

    ull acc[8][4] = {};

    for (int k0 = 0; k0 < K; k0 += BK) {
        float4 a0 = *(const float4*)(A + (size_t)(bm + ar) * K + k0 + ac);
        float4 a1 = *(const float4*)(A + (size_t)(bm + ar + 64) * K + k0 + ac);
        As[ac + 0][ar] = a0.x; As[ac + 1][ar] = a0.y;
        As[ac + 2][ar] = a0.z; As[ac + 3][ar] = a0.w;
        As[ac + 0][ar + 64] = a1.x; As[ac + 1][ar + 64] = a1.y;
        As[ac + 2][ar + 64] = a1.z; As[ac + 3][ar + 64] = a1.w;
        *(float4*)&Ws[wr][wc]     = *(const float4*)(W + (size_t)(k0 + wr) * N + bn + wc);
        *(float4*)&Ws[wr + 8][wc] = *(const float4*)(W + (size_t)(k0 + wr + 8) * N + bn + wc);
        __syncthreads();

        #pragma unroll
        for (int kk = 0; kk < BK; kk++) {
            float4 av0 = *(const float4*)&As[kk][tm];
            float4 av1 = *(const float4*)&As[kk][tm + 4];
            float4 bv0 = *(const float4*)&Ws[kk][tn];
            float4 bv1 = *(const float4*)&Ws[kk][tn + 4];
            ull a2[8];
            a2[0] = pk2(av0.x, av0.x); a2[1] = pk2(av0.y, av0.y);
            a2[2] = pk2(av0.z, av0.z); a2[3] = pk2(av0.w, av0.w);
            a2[4] = pk2(av1.x, av1.x); a2[5] = pk2(av1.y, av1.y);
            a2[6] = pk2(av1.z, av1.z); a2[7] = pk2(av1.w, av1.w);
            ull b2[4];
            b2[0] = pk2(bv0.x, bv0.y); b2[1] = pk2(bv0.z, bv0.w);
            b2[2] = pk2(bv1.x, bv1.y); b2[3] = pk2(bv1.z, bv1.w);
            #pragma unroll
            for (int i = 0; i < 8; i++)
                #pragma unroll
                for (int j = 0; j < 4; j++)
                    fma2(acc[i][j], a2[i], b2[j]);
        }
        __syncthreads();
    }

    float bv[8];
    #pragma unroll
    for (int j = 0; j < 8; j++) bv[j] = bias[bn + tn + j];

    #pragma unroll
    for (int i = 0; i < 8; i++) {
        float o[8];
        #pragma unroll
        for (int j = 0; j < 4; j++) {
            float lo, hi;
            upk2(acc[i][j], lo, hi);
            o[2 * j]     = fmaxf(lo + bv[2 * j], 0.f);
            o[2 * j + 1] = fmaxf(hi + bv[2 * j + 1], 0.f);
        }
        float* Cr = C + (size_t)(bm + tm + i) * N + bn + tn;
        *(float4*)Cr       = make_float4(o[0], o[1], o[2], o[3]);
        *(float4*)(Cr + 4) = make_float4(o[4], o[5], o[6], o[7]);
    }
}

// ============================================================
// gates[b,t,:] = softmax(x[b] @ gW[t] + gb[t])  — one warp per (b,t)
// ============================================================
__global__ void gates_kernel(const float* __restrict__ x, const float* __restrict__ gW,
                             const float* __restrict__ gb, float* __restrict__ gates)
{
    int gw = (blockIdx.x * blockDim.x + threadIdx.x) >> 5;
    int lane = threadIdx.x & 31;
    if (gw >= NB * 2) return;
    int b = gw >> 1, t = gw & 1;
    const float* xr = x + (size_t)b * DD;
    float acc[8] = {0, 0, 0, 0, 0, 0, 0, 0};
    for (int d = lane; d < DD; d += 32) {
        float xv = xr[d];
        const float* g = gW + ((size_t)t * DD + d) * NE;
        float4 w0 = *(const float4*)g;
        float4 w1 = *(const float4*)(g + 4);
        acc[0] += xv * w0.x; acc[1] += xv * w0.y; acc[2] += xv * w0.z; acc[3] += xv * w0.w;
        acc[4] += xv * w1.x; acc[5] += xv * w1.y; acc[6] += xv * w1.z; acc[7] += xv * w1.w;
    }
    #pragma unroll
    for (int e = 0; e < 8; e++)
        #pragma unroll
        for (int o = 16; o; o >>= 1) acc[e] += __shfl_xor_sync(0xffffffffu, acc[e], o);
    float m = -1e30f;
    #pragma unroll
    for (int e = 0; e < 8; e++) { acc[e] += gb[t * 8 + e]; m = fmaxf(m, acc[e]); }
    float s = 0.f;
    #pragma unroll
    for (int e = 0; e < 8; e++) { acc[e] = expf(acc[e] - m); s += acc[e]; }
    float inv = 1.f / s;
    if (lane < 8) gates[((size_t)b * 2 + t) * 8 + lane] = acc[lane] * inv;
}

// ============================================================
// out[t][b][h] = sum_e g[b,t,e] * fea[e][b][h]
// ============================================================
__global__ void combine_kernel(const float* __restrict__ fea, const float* __restrict__ gates,
                               int gstride, float* __restrict__ outp, size_t tstride)
{
    int b = blockIdx.x, t = blockIdx.y;
    __shared__ float g[8];
    if (threadIdx.x < 8) g[threadIdx.x] = gates[(size_t)b * gstride + t * 8 + threadIdx.x];
    __syncthreads();
    float* orow = outp + (size_t)t * tstride + (size_t)b * NH2;
    const float* f = fea + (size_t)b * NH2;
    for (int h = threadIdx.x; h < NH2; h += blockDim.x) {
        float s = 0.f;
        #pragma unroll
        for (int e = 0; e < 8; e++) s += g[e] * f[(size_t)e * NB * NH2 + h];
        orow[h] = s;
    }
}

// ============================================================
// pctr/pcvr = sigmoid(th2[b,t] . pW[t] + pb[t]) — warp per (b,t)
// ============================================================
__global__ void preds_kernel(const float* __restrict__ outr, const float* __restrict__ pW,
                             const float* __restrict__ pb, float* __restrict__ out)
{
    int gw = (blockIdx.x * blockDim.x + threadIdx.x) >> 5;
    int lane = threadIdx.x & 31;
    if (gw >= NB * 2) return;
    int b = gw >> 1, t = gw & 1;
    const float* th2 = outr + O6 + (size_t)t * NB * TT2 + (size_t)b * TT2;
    const float* w = pW + t * TT2;
    float s = 0.f;
    for (int m = lane; m < TT2; m += 32) s += th2[m] * w[m];
    #pragma unroll
    for (int o = 16; o; o >>= 1) s += __shfl_xor_sync(0xffffffffu, s, o);
    if (lane == 0) {
        s += pb[t];
        out[(size_t)t * NB + b] = 1.f / (1.f + expf(-s));
    }
}

// ============================================================
// ait[b, d*5+p] = x[b,d] * (pctr[b]*embW[p] + embB[p])
// ============================================================
__global__ void pe_ait_kernel(const float* __restrict__ x, const float* __restrict__ out,
                              const float* __restrict__ embW, const float* __restrict__ embB,
                              float* __restrict__ ait)
{
    int b = blockIdx.x;
    float pc = out[b];  // pctr at offset O0
    float pe[PEN];
    #pragma unroll
    for (int p = 0; p < PEN; p++) pe[p] = pc * embW[p] + embB[p];
    const float* xr = x + (size_t)b * DD;
    float* ar = ait + (size_t)b * KAIT;
    for (int idx = threadIdx.x; idx < KAIT; idx += blockDim.x) {
        int d = idx / PEN, p = idx - PEN * d;
        ar[idx] = xr[d] * pe[p];
    }
}

// ============================================================
// cgate[b] = softmax(ait[b] @ cgW + cgb) — one warp per b
// ============================================================
__global__ void cgate_kernel(const float* __restrict__ ait, const float* __restrict__ cgW,
                             const float* __restrict__ cgb, float* __restrict__ cg)
{
    int gw = (blockIdx.x * blockDim.x + threadIdx.x) >> 5;
    int lane = threadIdx.x & 31;
    if (gw >= NB) return;
    const float* ar = ait + (size_t)gw * KAIT;
    float acc[8] = {0, 0, 0, 0, 0, 0, 0, 0};
    for (int k = lane; k < KAIT; k += 32) {
        float a = ar[k];
        float4 w0 = *(const float4*)(cgW + (size_t)k * 8);
        float4 w1 = *(const float4*)(cgW + (size_t)k * 8 + 4);
        acc[0] += a * w0.x; acc[1] += a * w0.y; acc[2] += a * w0.z; acc[3] += a * w0.w;
        acc[4] += a * w1.x; acc[5] += a * w1.y; acc[6] += a * w1.z; acc[7] += a * w1.w;
    }
    #pragma unroll
    for (int e = 0; e < 8; e++)
        #pragma unroll
        for (int o = 16; o; o >>= 1) acc[e] += __shfl_xor_sync(0xffffffffu, acc[e], o);
    float m = -1e30f;
    #pragma unroll
    for (int e = 0; e < 8; e++) { acc[e] += cgb[e]; m = fmaxf(m, acc[e]); }
    float s = 0.f;
    #pragma unroll
    for (int e = 0; e < 8; e++) { acc[e] = expf(acc[e] - m); s += acc[e]; }
    float inv = 1.f / s;
    if (lane < 8) cg[(size_t)gw * 8 + lane] = acc[lane] * inv;
}

// ============================================================
// pconversion = sigmoid(ch2[b] . cpW + cpb) — warp per b
// ============================================================
__global__ void pconv_kernel(const float* __restrict__ outr, const float* __restrict__ cpW,
                             const float* __restrict__ cpb, float* __restrict__ out)
{
    int gw = (blockIdx.x * blockDim.x + threadIdx.x) >> 5;
    int lane = threadIdx.x & 31;
    if (gw >= NB) return;
    const float* ch2 = outr + O8 + (size_t)gw * TT2;
    float s = 0.f;
    for (int m = lane; m < TT2; m += 32) s += ch2[m] * cpW[m];
    #pragma unroll
    for (int o = 16; o; o >>= 1) s += __shfl_xor_sync(0xffffffffu, s, o);
    if (lane == 0) out[O2 + gw] = 1.f / (1.f + expf(-(s + cpb[0])));
}

// ============================================================
extern "C" void kernel_launch(void* const* d_in, const int* in_sizes, int n_in,
                              void* d_out, int out_size)
{
    const float* x    = (const float*)d_in[0];
    const float* eW1  = (const float*)d_in[1];
    const float* eb1  = (const float*)d_in[2];
    const float* eW2  = (const float*)d_in[3];
    const float* eb2  = (const float*)d_in[4];
    const float* gW   = (const float*)d_in[5];
    const float* gb   = (const float*)d_in[6];
    const float* tW1  = (const float*)d_in[7];
    const float* tb1  = (const float*)d_in[8];
    const float* tW2  = (const float*)d_in[9];
    const float* tb2  = (const float*)d_in[10];
    const float* pW   = (const float*)d_in[11];
    const float* pb   = (const float*)d_in[12];
    const float* embW = (const float*)d_in[13];
    const float* embB = (const float*)d_in[14];
    const float* ceW1 = (const float*)d_in[15];
    const float* ceb1 = (const float*)d_in[16];
    const float* ceW2 = (const float*)d_in[17];
    const float* ceb2 = (const float*)d_in[18];
    const float* cgW  = (const float*)d_in[19];
    const float* cgb  = (const float*)d_in[20];
    const float* ctW1 = (const float*)d_in[21];
    const float* ctb1 = (const float*)d_in[22];
    const float* ctW2 = (const float*)d_in[23];
    const float* ctb2 = (const float*)d_in[24];
    const float* cpW  = (const float*)d_in[25];
    const float* cpb  = (const float*)d_in[26];
    float* out = (float*)d_out;

    float *pH, *pFEA, *pAIT, *pTH1, *pCH1, *pG, *pCG;
    cudaGetSymbolAddress((void**)&pH,   g_H);
    cudaGetSymbolAddress((void**)&pFEA, g_FEA);
    cudaGetSymbolAddress((void**)&pAIT, g_AIT);
    cudaGetSymbolAddress((void**)&pTH1, g_TH1);
    cudaGetSymbolAddress((void**)&pCH1, g_CH1);
    cudaGetSymbolAddress((void**)&pG,   g_GATES);
    cudaGetSymbolAddress((void**)&pCG,  g_CGATE);

    dim3 blk(256);

    // Phase 1: experts
    gemm_bias_relu<<<dim3(NH1 / 128, NB / 128, NE), blk>>>(
        x, eW1, eb1, pH, NB, NH1, DD,
        0, (size_t)DD * NH1, NH1, (size_t)NB * NH1);
    gemm_bias_relu<<<dim3(NH2 / 128, NB / 128, NE), blk>>>(
        pH, eW2, eb2, pFEA, NB, NH2, NH1,
        (size_t)NB * NH1, (size_t)NH1 * NH2, NH2, (size_t)NB * NH2);

    // gates + task_fea (written straight into output o3/o4)
    gates_kernel<<<NB * 2 / 8, 256>>>(x, gW, gb, pG);
    combine_kernel<<<dim3(NB, 2), 256>>>(pFEA, pG, 16, out + O3, (size_t)NB * NH2);

    // towers -> th2 (o6/o7) -> pctr/pcvr (o0/o1)
    gemm_bias_relu<<<dim3(TT1 / 128, NB / 128, 2), blk>>>(
        out + O3, tW1, tb1, pTH1, NB, TT1, NH2,
        (size_t)NB * NH2, (size_t)NH2 * TT1, TT1, (size_t)NB * TT1);
    gemm_bias_relu<<<dim3(TT2 / 128, NB / 128, 2), blk>>>(
        pTH1, tW2, tb2, out + O6, NB, TT2, TT1,
        (size_t)NB * TT1, (size_t)TT1 * TT2, TT2, (size_t)NB * TT2);
    preds_kernel<<<NB * 2 / 8, 256>>>(out, pW, pb, out);

    // Phase 2: cascade
    pe_ait_kernel<<<NB, 256>>>(x, out, embW, embB, pAIT);
    gemm_bias_relu<<<dim3(NH1 / 128, NB / 128, NE), blk>>>(
        pAIT, ceW1, ceb1, pH, NB, NH1, KAIT,
        0, (size_t)KAIT * NH1, NH1, (size_t)NB * NH1);
    gemm_bias_relu<<<dim3(NH2 / 128, NB / 128, NE), blk>>>(
        pH, ceW2, ceb2, pFEA, NB, NH2, NH1,
        (size_t)NB * NH1, (size_t)NH1 * NH2, NH2, (size_t)NB * NH2);
    cgate_kernel<<<NB / 8, 256>>>(pAIT, cgW, cgb, pCG);
    combine_kernel<<<dim3(NB, 1), 256>>>(pFEA, pCG, 8, out + O5, 0);

    // cascade towers -> ch2 (o8) -> pconversion (o2)
    gemm_bias_relu<<<dim3(TT1 / 128, NB / 128, 1), blk>>>(
        out + O5, ctW1, ctb1, pCH1, NB, TT1, NH2, 0, 0, 0, 0);
    gemm_bias_relu<<<dim3(TT2 / 128, NB / 128, 1), blk>>>(
        pCH1, ctW2, ctb2, out + O8, NB, TT2, TT1, 0, 0, 0, 0);
    pconv_kernel<<<NB / 8, 256>>>(out, cpW, cpb, out);
}

// round 3
// speedup vs baseline: 3.5185x; 3.5185x over previous
#include <cuda_runtime.h>
#include <cuda_fp16.h>
#include <math.h>

typedef unsigned long long ull;
typedef unsigned int u32;

#define NB   16384
#define DD   512
#define NE   8
#define NH1  1024
#define NH2  512
#define TT1  256
#define TT2  128
#define PEN  5
#define KAIT 2560   // D*PE

// ---- output layout ----
#define O0 ((size_t)0)
#define O1 ((size_t)NB)
#define O2 ((size_t)2*NB)
#define O3 ((size_t)3*NB)
#define O4 (O3 + (size_t)NB*512)
#define O5 (O4 + (size_t)NB*512)
#define O6 (O5 + (size_t)NB*512)
#define O7 (O6 + (size_t)NB*128)
#define O8 (O7 + (size_t)NB*128)

// ---- scratch ----
__device__ __half g_xh [(size_t)NB*DD];
__device__ __half g_xl [(size_t)NB*DD];
__device__ __half g_Hh [(size_t)NE*NB*NH1];
__device__ __half g_Hl [(size_t)NE*NB*NH1];
__device__ __half g_Ah [(size_t)NB*KAIT];
__device__ __half g_Al [(size_t)NB*KAIT];
__device__ __half g_W1h[(size_t)NE*NH1*DD];
__device__ __half g_W2h[(size_t)NE*NH2*NH1];
__device__ __half g_CW1h[(size_t)NE*NH1*KAIT];
__device__ __half g_CW2h[(size_t)NE*NH2*NH1];
__device__ float g_FEA [(size_t)NE*NB*NH2];
__device__ float g_TH1 [(size_t)2*NB*TT1];
__device__ float g_CH1 [(size_t)NB*TT1];
__device__ float g_GATES[(size_t)NB*2*8];
__device__ float g_CGATE[(size_t)NB*8];

// ================= helpers =================
__device__ __forceinline__ u32 smem_u32(const void* p) {
    u32 a;
    asm("{ .reg .u64 t; cvta.to.shared.u64 t, %1; cvt.u32.u64 %0, t; }" : "=r"(a) : "l"(p));
    return a;
}
__device__ __forceinline__ void cpa16(u32 dst, const void* src) {
    asm volatile("cp.async.cg.shared.global [%0], [%1], 16;" :: "r"(dst), "l"(src) : "memory");
}
#define CPA_COMMIT() asm volatile("cp.async.commit_group;" ::: "memory")
#define CPA_WAIT2()  asm volatile("cp.async.wait_group 2;" ::: "memory")

__device__ __forceinline__ void mma16816(float* c, const u32* a, const u32* b) {
    asm volatile(
        "mma.sync.aligned.m16n8k16.row.col.f32.f16.f16.f32 "
        "{%0,%1,%2,%3}, {%4,%5,%6,%7}, {%8,%9}, {%0,%1,%2,%3};"
        : "+f"(c[0]), "+f"(c[1]), "+f"(c[2]), "+f"(c[3])
        : "r"(a[0]), "r"(a[1]), "r"(a[2]), "r"(a[3]), "r"(b[0]), "r"(b[1]));
}

// swizzled smem offset for tile row (64B/row, 4x16B chunks)
__device__ __forceinline__ u32 swz(int row, int ch) {
    return (u32)(row * 64 + ((ch ^ ((row >> 1) & 3)) << 4));
}

// A-fragment ldmatrix (16x16 block at row0, k-slice s within 32-wide tile)
__device__ __forceinline__ void ldA(u32 tb, int row0, int s, u32* a) {
    int lane = threadIdx.x & 31;
    int g = lane >> 3, li = lane & 7;
    int row = row0 + ((g & 1) << 3) + li;
    int ch = 2 * s + (g >> 1);
    u32 addr = tb + swz(row, ch);
    asm volatile("ldmatrix.sync.aligned.m8n8.x4.shared.b16 {%0,%1,%2,%3}, [%4];"
        : "=r"(a[0]), "=r"(a[1]), "=r"(a[2]), "=r"(a[3]) : "r"(addr));
}
// B-fragment ldmatrix: covers n16 (two n8 blocks) x k16; B stored [N][K]
__device__ __forceinline__ void ldB(u32 tb, int n0, int s, u32* r) {
    int lane = threadIdx.x & 31;
    int g = lane >> 3, li = lane & 7;
    int row = n0 + ((g >> 1) << 3) + li;
    int ch = 2 * s + (g & 1);
    u32 addr = tb + swz(row, ch);
    asm volatile("ldmatrix.sync.aligned.m8n8.x4.shared.b16 {%0,%1,%2,%3}, [%4];"
        : "=r"(r[0]), "=r"(r[1]), "=r"(r[2]), "=r"(r[3]) : "r"(addr));
}

// ============================================================
// HMMA GEMM: C[z] = relu(A[z] @ B[z]^T + bias[z])
// A = Ah + Al (fp16 hi/lo) [M,K] row-major; B = Bh fp16 [N,K] row-major.
// Tile 128x128, k-chunks of 32, 4-stage cp.async pipeline.
// mode 0: fp32 C; mode 1: fp16 hi/lo C (for next GEMM's A).
// ============================================================
#define STAGE_BYTES 24576
__global__ void __launch_bounds__(256, 1) hmma_gemm(
    const __half* __restrict__ Ah, const __half* __restrict__ Al,
    const __half* __restrict__ Bh, const float* __restrict__ bias,
    float* __restrict__ Cf, __half* __restrict__ Ch, __half* __restrict__ Cl,
    int N, int K, size_t sA, size_t sB, size_t sBias, size_t sC, int mode)
{
    extern __shared__ char dsm[];
    const int tid = threadIdx.x;
    const int wid = tid >> 5;
    const int lane = tid & 31;
    const int z = blockIdx.z;
    const int bm = blockIdx.y << 7;
    const int bn = blockIdx.x << 7;

    Ah += (size_t)z * sA;  Al += (size_t)z * sA;
    Bh += (size_t)z * sB;  bias += (size_t)z * sBias;

    const u32 sbase = smem_u32(dsm);

    // 6 cp.async slots per thread: 1536 x 16B per stage (Ah 512, Al 512, Bh 512)
    u32 soff[6];
    const __half* gsrc[6];
    #pragma unroll
    for (int j = 0; j < 6; j++) {
        int sid = tid + (j << 8);
        int buf = sid >> 9;            // 0:Ah 1:Al 2:Bh
        int rem = sid & 511;
        int r = rem >> 2;
        int ch = rem & 3;
        soff[j] = (u32)(buf * 8192) + swz(r, ch);
        const __half* base = (buf == 0) ? Ah : (buf == 1) ? Al : Bh;
        int grow = (buf < 2 ? bm : bn) + r;
        gsrc[j] = base + (size_t)grow * K + ch * 8;
    }

    const int nch = K >> 5;

    #pragma unroll
    for (int p = 0; p < 3; p++) {
        u32 sb = sbase + (u32)p * STAGE_BYTES;
        #pragma unroll
        for (int j = 0; j < 6; j++) cpa16(sb + soff[j], gsrc[j] + p * 32);
        CPA_COMMIT();
    }

    const int wm = (wid & 3) << 5;   // warp m-offset in tile (0..96)
    const int wn = (wid >> 2) << 6;  // warp n-offset in tile (0 or 64)

    float acc[2][8][4];
    #pragma unroll
    for (int i = 0; i < 2; i++)
        #pragma unroll
        for (int j = 0; j < 8; j++)
            #pragma unroll
            for (int q = 0; q < 4; q++) acc[i][j][q] = 0.f;

    for (int i = 0; i < nch; i++) {
        CPA_WAIT2();
        __syncthreads();
        int pf = i + 3;
        if (pf < nch) {
            u32 sb = sbase + (u32)(pf & 3) * STAGE_BYTES;
            #pragma unroll
            for (int j = 0; j < 6; j++) cpa16(sb + soff[j], gsrc[j] + pf * 32);
        }
        CPA_COMMIT();

        u32 stb = sbase + (u32)(i & 3) * STAGE_BYTES;
        #pragma unroll
        for (int s = 0; s < 2; s++) {
            u32 ah[2][4], al[2][4], b[8][2];
            ldA(stb,        wm,      s, ah[0]);
            ldA(stb,        wm + 16, s, ah[1]);
            ldA(stb + 8192, wm,      s, al[0]);
            ldA(stb + 8192, wm + 16, s, al[1]);
            #pragma unroll
            for (int j4 = 0; j4 < 4; j4++) {
                u32 r[4];
                ldB(stb + 16384, wn + j4 * 16, s, r);
                b[2 * j4][0] = r[0]; b[2 * j4][1] = r[1];
                b[2 * j4 + 1][0] = r[2]; b[2 * j4 + 1][1] = r[3];
            }
            #pragma unroll
            for (int i2 = 0; i2 < 2; i2++)
                #pragma unroll
                for (int j8 = 0; j8 < 8; j8++) mma16816(acc[i2][j8], ah[i2], b[j8]);
            #pragma unroll
            for (int i2 = 0; i2 < 2; i2++)
                #pragma unroll
                for (int j8 = 0; j8 < 8; j8++) mma16816(acc[i2][j8], al[i2], b[j8]);
        }
    }

    // epilogue
    const int r0b = bm + wm + (lane >> 2);
    const int c0b = bn + wn + ((lane & 3) << 1);
    #pragma unroll
    for (int i2 = 0; i2 < 2; i2++) {
        #pragma unroll
        for (int j8 = 0; j8 < 8; j8++) {
            int col = c0b + j8 * 8;
            float b0 = bias[col], b1 = bias[col + 1];
            #pragma unroll
            for (int h = 0; h < 2; h++) {
                int row = r0b + i2 * 16 + h * 8;
                float v0 = fmaxf(acc[i2][j8][2 * h]     + b0, 0.f);
                float v1 = fmaxf(acc[i2][j8][2 * h + 1] + b1, 0.f);
                if (mode == 0) {
                    float2 v = make_float2(v0, v1);
                    *(float2*)(Cf + (size_t)z * sC + (size_t)row * N + col) = v;
                } else {
                    __half h0 = __float2half_rn(v0);
                    __half h1 = __float2half_rn(v1);
                    __half2 hp; hp.x = h0; hp.y = h1;
                    __half2 lp;
                    lp.x = __float2half_rn(v0 - __half2float(h0));
                    lp.y = __float2half_rn(v1 - __half2float(h1));
                    *(__half2*)(Ch + (size_t)z * sC + (size_t)row * N + col) = hp;
                    *(__half2*)(Cl + (size_t)z * sC + (size_t)row * N + col) = lp;
                }
            }
        }
    }
}

// ============================================================
// weight transpose + fp16 split: W[z][K][N] f32 -> T[z][N][K] fp16 (hi only)
// ============================================================
__global__ void transpose_h(const float* __restrict__ W, __half* __restrict__ Th,
                            int Kd, int Nd)
{
    __shared__ float t[32][33];
    int z = blockIdx.z;
    const float* Wz = W + (size_t)z * Kd * Nd;
    int n0 = blockIdx.x << 5, k0 = blockIdx.y << 5;
    for (int r = threadIdx.y; r < 32; r += 8)
        t[r][threadIdx.x] = Wz[(size_t)(k0 + r) * Nd + n0 + threadIdx.x];
    __syncthreads();
    size_t ob = (size_t)z * Nd * Kd;
    for (int r = threadIdx.y; r < 32; r += 8) {
        float v = t[threadIdx.x][r];
        Th[ob + (size_t)(n0 + r) * Kd + k0 + threadIdx.x] = __float2half_rn(v);
    }
}

// elementwise fp32 -> fp16 hi/lo
__global__ void convert_split(const float* __restrict__ src,
                              __half* __restrict__ hi, __half* __restrict__ lo, size_t n)
{
    size_t i = ((size_t)blockIdx.x * blockDim.x + threadIdx.x) * 4;
    if (i >= n) return;
    float4 v = *(const float4*)(src + i);
    __half h0 = __float2half_rn(v.x), h1 = __float2half_rn(v.y);
    __half h2 = __float2half_rn(v.z), h3 = __float2half_rn(v.w);
    __half2 a, b, c, d;
    a.x = h0; a.y = h1; b.x = h2; b.y = h3;
    c.x = __float2half_rn(v.x - __half2float(h0));
    c.y = __float2half_rn(v.y - __half2float(h1));
    d.x = __float2half_rn(v.z - __half2float(h2));
    d.y = __float2half_rn(v.w - __half2float(h3));
    *(__half2*)(hi + i) = a; *(__half2*)(hi + i + 2) = b;
    *(__half2*)(lo + i) = c; *(__half2*)(lo + i + 2) = d;
}

// ================= fp32 path (towers & small ops) =================
__device__ __forceinline__ ull pk2(float lo, float hi) {
    ull r; asm("mov.b64 %0, {%1, %2};" : "=l"(r) : "f"(lo), "f"(hi)); return r;
}
__device__ __forceinline__ void fma2(ull& d, ull a, ull b) {
    asm("fma.rn.f32x2 %0, %1, %2, %0;" : "+l"(d) : "l"(a), "l"(b));
}
__device__ __forceinline__ void upk2(ull v, float& lo, float& hi) {
    u32 a, b; asm("mov.b64 {%0, %1}, %2;" : "=r"(a), "=r"(b) : "l"(v));
    lo = __uint_as_float(a); hi = __uint_as_float(b);
}

__global__ void __launch_bounds__(256, 2) gemm_bias_relu(
    const float* __restrict__ A, const float* __restrict__ W,
    const float* __restrict__ bias, float* __restrict__ C,
    int M, int N, int K, size_t sA, size_t sW, size_t sB, size_t sC)
{
    const int BK = 16;
    __shared__ float As[BK][128];
    __shared__ float Ws[BK][128];
    int z = blockIdx.z;
    A += (size_t)z * sA; W += (size_t)z * sW; bias += (size_t)z * sB; C += (size_t)z * sC;
    int bm = blockIdx.y << 7, bn = blockIdx.x << 7;
    int tid = threadIdx.x;
    int tm = (tid >> 4) << 3, tn = (tid & 15) << 3;
    int ar = tid >> 2, ac = (tid & 3) << 2;
    int wr = tid >> 5, wc = (tid & 31) << 2;
    ull acc[8][4] = {};
    for (int k0 = 0; k0 < K; k0 += BK) {
        float4 a0 = *(const float4*)(A + (size_t)(bm + ar) * K + k0 + ac);
        float4 a1 = *(const float4*)(A + (size_t)(bm + ar + 64) * K + k0 + ac);
        As[ac + 0][ar] = a0.x; As[ac + 1][ar] = a0.y; As[ac + 2][ar] = a0.z; As[ac + 3][ar] = a0.w;
        As[ac + 0][ar + 64] = a1.x; As[ac + 1][ar + 64] = a1.y;
        As[ac + 2][ar + 64] = a1.z; As[ac + 3][ar + 64] = a1.w;
        *(float4*)&Ws[wr][wc]     = *(const float4*)(W + (size_t)(k0 + wr) * N + bn + wc);
        *(float4*)&Ws[wr + 8][wc] = *(const float4*)(W + (size_t)(k0 + wr + 8) * N + bn + wc);
        __syncthreads();
        #pragma unroll
        for (int kk = 0; kk < BK; kk++) {
            float4 av0 = *(const float4*)&As[kk][tm];
            float4 av1 = *(const float4*)&As[kk][tm + 4];
            float4 bv0 = *(const float4*)&Ws[kk][tn];
            float4 bv1 = *(const float4*)&Ws[kk][tn + 4];
            ull a2[8];
            a2[0] = pk2(av0.x, av0.x); a2[1] = pk2(av0.y, av0.y);
            a2[2] = pk2(av0.z, av0.z); a2[3] = pk2(av0.w, av0.w);
            a2[4] = pk2(av1.x, av1.x); a2[5] = pk2(av1.y, av1.y);
            a2[6] = pk2(av1.z, av1.z); a2[7] = pk2(av1.w, av1.w);
            ull b2[4];
            b2[0] = pk2(bv0.x, bv0.y); b2[1] = pk2(bv0.z, bv0.w);
            b2[2] = pk2(bv1.x, bv1.y); b2[3] = pk2(bv1.z, bv1.w);
            #pragma unroll
            for (int i = 0; i < 8; i++)
                #pragma unroll
                for (int j = 0; j < 4; j++)
                    fma2(acc[i][j], a2[i], b2[j]);
        }
        __syncthreads();
    }
    float bv[8];
    #pragma unroll
    for (int j = 0; j < 8; j++) bv[j] = bias[bn + tn + j];
    #pragma unroll
    for (int i = 0; i < 8; i++) {
        float o[8];
        #pragma unroll
        for (int j = 0; j < 4; j++) {
            float lo, hi; upk2(acc[i][j], lo, hi);
            o[2 * j]     = fmaxf(lo + bv[2 * j], 0.f);
            o[2 * j + 1] = fmaxf(hi + bv[2 * j + 1], 0.f);
        }
        float* Cr = C + (size_t)(bm + tm + i) * N + bn + tn;
        *(float4*)Cr = make_float4(o[0], o[1], o[2], o[3]);
        *(float4*)(Cr + 4) = make_float4(o[4], o[5], o[6], o[7]);
    }
}

__global__ void gates_kernel(const float* __restrict__ x, const float* __restrict__ gW,
                             const float* __restrict__ gb, float* __restrict__ gates)
{
    int gw = (blockIdx.x * blockDim.x + threadIdx.x) >> 5;
    int lane = threadIdx.x & 31;
    if (gw >= NB * 2) return;
    int b = gw >> 1, t = gw & 1;
    const float* xr = x + (size_t)b * DD;
    float acc[8] = {};
    for (int d = lane; d < DD; d += 32) {
        float xv = xr[d];
        const float* g = gW + ((size_t)t * DD + d) * NE;
        float4 w0 = *(const float4*)g;
        float4 w1 = *(const float4*)(g + 4);
        acc[0] += xv * w0.x; acc[1] += xv * w0.y; acc[2] += xv * w0.z; acc[3] += xv * w0.w;
        acc[4] += xv * w1.x; acc[5] += xv * w1.y; acc[6] += xv * w1.z; acc[7] += xv * w1.w;
    }
    #pragma unroll
    for (int e = 0; e < 8; e++)
        #pragma unroll
        for (int o = 16; o; o >>= 1) acc[e] += __shfl_xor_sync(0xffffffffu, acc[e], o);
    float m = -1e30f;
    #pragma unroll
    for (int e = 0; e < 8; e++) { acc[e] += gb[t * 8 + e]; m = fmaxf(m, acc[e]); }
    float s = 0.f;
    #pragma unroll
    for (int e = 0; e < 8; e++) { acc[e] = expf(acc[e] - m); s += acc[e]; }
    float inv = 1.f / s;
    if (lane < 8) gates[((size_t)b * 2 + t) * 8 + lane] = acc[lane] * inv;
}

__global__ void combine_kernel(const float* __restrict__ fea, const float* __restrict__ gates,
                               int gstride, float* __restrict__ outp, size_t tstride)
{
    int b = blockIdx.x, t = blockIdx.y;
    __shared__ float g[8];
    if (threadIdx.x < 8) g[threadIdx.x] = gates[(size_t)b * gstride + t * 8 + threadIdx.x];
    __syncthreads();
    float* orow = outp + (size_t)t * tstride + (size_t)b * NH2;
    const float* f = fea + (size_t)b * NH2;
    for (int h = threadIdx.x; h < NH2; h += blockDim.x) {
        float s = 0.f;
        #pragma unroll
        for (int e = 0; e < 8; e++) s += g[e] * f[(size_t)e * NB * NH2 + h];
        orow[h] = s;
    }
}

__global__ void preds_kernel(const float* __restrict__ outr, const float* __restrict__ pW,
                             const float* __restrict__ pb, float* __restrict__ out)
{
    int gw = (blockIdx.x * blockDim.x + threadIdx.x) >> 5;
    int lane = threadIdx.x & 31;
    if (gw >= NB * 2) return;
    int b = gw >> 1, t = gw & 1;
    const float* th2 = outr + O6 + (size_t)t * NB * TT2 + (size_t)b * TT2;
    const float* w = pW + t * TT2;
    float s = 0.f;
    for (int m = lane; m < TT2; m += 32) s += th2[m] * w[m];
    #pragma unroll
    for (int o = 16; o; o >>= 1) s += __shfl_xor_sync(0xffffffffu, s, o);
    if (lane == 0) {
        s += pb[t];
        out[(size_t)t * NB + b] = 1.f / (1.f + expf(-s));
    }
}

// ait hi/lo: ait[b, d*5+p] = x[b,d] * (pctr[b]*embW[p] + embB[p])
__global__ void pe_ait_kernel(const float* __restrict__ x, const float* __restrict__ out,
                              const float* __restrict__ embW, const float* __restrict__ embB,
                              __half* __restrict__ ah, __half* __restrict__ al)
{
    int b = blockIdx.x;
    float pc = out[b];
    float pe[PEN];
    #pragma unroll
    for (int p = 0; p < PEN; p++) pe[p] = pc * embW[p] + embB[p];
    const float* xr = x + (size_t)b * DD;
    size_t ob = (size_t)b * KAIT;
    for (int idx = threadIdx.x; idx < KAIT; idx += blockDim.x) {
        int d = idx / PEN, p = idx - PEN * d;
        float v = xr[d] * pe[p];
        __half h = __float2half_rn(v);
        ah[ob + idx] = h;
        al[ob + idx] = __float2half_rn(v - __half2float(h));
    }
}

__global__ void cgate_kernel(const __half* __restrict__ ah, const __half* __restrict__ al,
                             const float* __restrict__ cgW, const float* __restrict__ cgb,
                             float* __restrict__ cg)
{
    int gw = (blockIdx.x * blockDim.x + threadIdx.x) >> 5;
    int lane = threadIdx.x & 31;
    if (gw >= NB) return;
    const __half* arh = ah + (size_t)gw * KAIT;
    const __half* arl = al + (size_t)gw * KAIT;
    float acc[8] = {};
    for (int k = lane; k < KAIT; k += 32) {
        float a = __half2float(arh[k]) + __half2float(arl[k]);
        float4 w0 = *(const float4*)(cgW + (size_t)k * 8);
        float4 w1 = *(const float4*)(cgW + (size_t)k * 8 + 4);
        acc[0] += a * w0.x; acc[1] += a * w0.y; acc[2] += a * w0.z; acc[3] += a * w0.w;
        acc[4] += a * w1.x; acc[5] += a * w1.y; acc[6] += a * w1.z; acc[7] += a * w1.w;
    }
    #pragma unroll
    for (int e = 0; e < 8; e++)
        #pragma unroll
        for (int o = 16; o; o >>= 1) acc[e] += __shfl_xor_sync(0xffffffffu, acc[e], o);
    float m = -1e30f;
    #pragma unroll
    for (int e = 0; e < 8; e++) { acc[e] += cgb[e]; m = fmaxf(m, acc[e]); }
    float s = 0.f;
    #pragma unroll
    for (int e = 0; e < 8; e++) { acc[e] = expf(acc[e] - m); s += acc[e]; }
    float inv = 1.f / s;
    if (lane < 8) cg[(size_t)gw * 8 + lane] = acc[lane] * inv;
}

__global__ void pconv_kernel(const float* __restrict__ outr, const float* __restrict__ cpW,
                             const float* __restrict__ cpb, float* __restrict__ out)
{
    int gw = (blockIdx.x * blockDim.x + threadIdx.x) >> 5;
    int lane = threadIdx.x & 31;
    if (gw >= NB) return;
    const float* ch2 = outr + O8 + (size_t)gw * TT2;
    float s = 0.f;
    for (int m = lane; m < TT2; m += 32) s += ch2[m] * cpW[m];
    #pragma unroll
    for (int o = 16; o; o >>= 1) s += __shfl_xor_sync(0xffffffffu, s, o);
    if (lane == 0) out[O2 + gw] = 1.f / (1.f + expf(-(s + cpb[0])));
}

// ============================================================
extern "C" void kernel_launch(void* const* d_in, const int* in_sizes, int n_in,
                              void* d_out, int out_size)
{
    const float* x    = (const float*)d_in[0];
    const float* eW1  = (const float*)d_in[1];
    const float* eb1  = (const float*)d_in[2];
    const float* eW2  = (const float*)d_in[3];
    const float* eb2  = (const float*)d_in[4];
    const float* gW   = (const float*)d_in[5];
    const float* gb   = (const float*)d_in[6];
    const float* tW1  = (const float*)d_in[7];
    const float* tb1  = (const float*)d_in[8];
    const float* tW2  = (const float*)d_in[9];
    const float* tb2  = (const float*)d_in[10];
    const float* pW   = (const float*)d_in[11];
    const float* pb   = (const float*)d_in[12];
    const float* embW = (const float*)d_in[13];
    const float* embB = (const float*)d_in[14];
    const float* ceW1 = (const float*)d_in[15];
    const float* ceb1 = (const float*)d_in[16];
    const float* ceW2 = (const float*)d_in[17];
    const float* ceb2 = (const float*)d_in[18];
    const float* cgW  = (const float*)d_in[19];
    const float* cgb  = (const float*)d_in[20];
    const float* ctW1 = (const float*)d_in[21];
    const float* ctb1 = (const float*)d_in[22];
    const float* ctW2 = (const float*)d_in[23];
    const float* ctb2 = (const float*)d_in[24];
    const float* cpW  = (const float*)d_in[25];
    const float* cpb  = (const float*)d_in[26];
    float* out = (float*)d_out;

    __half *xh, *xl, *Hh, *Hl, *Ah, *Al, *W1h, *W2h, *CW1h, *CW2h;
    float *pFEA, *pTH1, *pCH1, *pG, *pCG;
    cudaGetSymbolAddress((void**)&xh, g_xh);   cudaGetSymbolAddress((void**)&xl, g_xl);
    cudaGetSymbolAddress((void**)&Hh, g_Hh);   cudaGetSymbolAddress((void**)&Hl, g_Hl);
    cudaGetSymbolAddress((void**)&Ah, g_Ah);   cudaGetSymbolAddress((void**)&Al, g_Al);
    cudaGetSymbolAddress((void**)&W1h, g_W1h); cudaGetSymbolAddress((void**)&W2h, g_W2h);
    cudaGetSymbolAddress((void**)&CW1h, g_CW1h); cudaGetSymbolAddress((void**)&CW2h, g_CW2h);
    cudaGetSymbolAddress((void**)&pFEA, g_FEA);
    cudaGetSymbolAddress((void**)&pTH1, g_TH1);
    cudaGetSymbolAddress((void**)&pCH1, g_CH1);
    cudaGetSymbolAddress((void**)&pG, g_GATES);
    cudaGetSymbolAddress((void**)&pCG, g_CGATE);

    cudaFuncSetAttribute(hmma_gemm, cudaFuncAttributeMaxDynamicSharedMemorySize, 4 * STAGE_BYTES);
    const int HSMEM = 4 * STAGE_BYTES;
    dim3 blk(256);

    // weight prep (fp16 hi, [N,K] K-major) + x split
    transpose_h<<<dim3(NH1 / 32, DD / 32, NE), dim3(32, 8)>>>(eW1, W1h, DD, NH1);
    transpose_h<<<dim3(NH2 / 32, NH1 / 32, NE), dim3(32, 8)>>>(eW2, W2h, NH1, NH2);
    transpose_h<<<dim3(NH1 / 32, KAIT / 32, NE), dim3(32, 8)>>>(ceW1, CW1h, KAIT, NH1);
    transpose_h<<<dim3(NH2 / 32, NH1 / 32, NE), dim3(32, 8)>>>(ceW2, CW2h, NH1, NH2);
    convert_split<<<(NB * DD / 4 + 255) / 256, 256>>>(x, xh, xl, (size_t)NB * DD);

    // Phase 1: experts (HMMA)
    hmma_gemm<<<dim3(NH1 / 128, NB / 128, NE), blk, HSMEM>>>(
        xh, xl, W1h, eb1, nullptr, Hh, Hl,
        NH1, DD, 0, (size_t)NH1 * DD, NH1, (size_t)NB * NH1, 1);
    hmma_gemm<<<dim3(NH2 / 128, NB / 128, NE), blk, HSMEM>>>(
        Hh, Hl, W2h, eb2, pFEA, nullptr, nullptr,
        NH2, NH1, (size_t)NB * NH1, (size_t)NH2 * NH1, NH2, (size_t)NB * NH2, 0);

    gates_kernel<<<NB * 2 / 8, 256>>>(x, gW, gb, pG);
    combine_kernel<<<dim3(NB, 2), 256>>>(pFEA, pG, 16, out + O3, (size_t)NB * NH2);

    gemm_bias_relu<<<dim3(TT1 / 128, NB / 128, 2), blk>>>(
        out + O3, tW1, tb1, pTH1, NB, TT1, NH2,
        (size_t)NB * NH2, (size_t)NH2 * TT1, TT1, (size_t)NB * TT1);
    gemm_bias_relu<<<dim3(TT2 / 128, NB / 128, 2), blk>>>(
        pTH1, tW2, tb2, out + O6, NB, TT2, TT1,
        (size_t)NB * TT1, (size_t)TT1 * TT2, TT2, (size_t)NB * TT2);
    preds_kernel<<<NB * 2 / 8, 256>>>(out, pW, pb, out);

    // Phase 2: cascade
    pe_ait_kernel<<<NB, 256>>>(x, out, embW, embB, Ah, Al);
    hmma_gemm<<<dim3(NH1 / 128, NB / 128, NE), blk, HSMEM>>>(
        Ah, Al, CW1h, ceb1, nullptr, Hh, Hl,
        NH1, KAIT, 0, (size_t)NH1 * KAIT, NH1, (size_t)NB * NH1, 1);
    hmma_gemm<<<dim3(NH2 / 128, NB / 128, NE), blk, HSMEM>>>(
        Hh, Hl, CW2h, ceb2, pFEA, nullptr, nullptr,
        NH2, NH1, (size_t)NB * NH1, (size_t)NH2 * NH1, NH2, (size_t)NB * NH2, 0);
    cgate_kernel<<<NB / 8, 256>>>(Ah, Al, cgW, cgb, pCG);
    combine_kernel<<<dim3(NB, 1), 256>>>(pFEA, pCG, 8, out + O5, 0);

    gemm_bias_relu<<<dim3(TT1 / 128, NB / 128, 1), blk>>>(
        out + O5, ctW1, ctb1, pCH1, NB, TT1, NH2, 0, 0, 0, 0);
    gemm_bias_relu<<<dim3(TT2 / 128, NB / 128, 1), blk>>>(
        pCH1, ctW2, ctb2, out + O8, NB, TT2, TT1, 0, 0, 0, 0);
    pconv_kernel<<<NB / 8, 256>>>(out, cpW, cpb, out);
}

// round 4
// speedup vs baseline: 3.7696x; 1.0714x over previous
#include <cuda_runtime.h>
#include <cuda_fp16.h>
#include <math.h>

typedef unsigned long long ull;
typedef unsigned int u32;

#define NB   16384
#define DD   512
#define NE   8
#define NH1  1024
#define NH2  512
#define TT1  256
#define TT2  128
#define PEN  5
#define KAIT 2560   // D*PE

// ---- output layout ----
#define O0 ((size_t)0)
#define O1 ((size_t)NB)
#define O2 ((size_t)2*NB)
#define O3 ((size_t)3*NB)
#define O4 (O3 + (size_t)NB*512)
#define O5 (O4 + (size_t)NB*512)
#define O6 (O5 + (size_t)NB*512)
#define O7 (O6 + (size_t)NB*128)
#define O8 (O7 + (size_t)NB*128)

// ---- scratch ----
__device__ __half g_xh [(size_t)NB*DD];
__device__ __half g_xl [(size_t)NB*DD];
__device__ __half g_Hh [(size_t)NE*NB*NH1];
__device__ __half g_W1h[(size_t)NE*NH1*DD];
__device__ __half g_W2h[(size_t)NE*NH2*NH1];
__device__ __half g_CW1h[(size_t)NE*NH1*KAIT];
__device__ __half g_CW2h[(size_t)NE*NH2*NH1];
__device__ __half g_tW1h[(size_t)2*TT1*NH2];
__device__ __half g_tW2h[(size_t)2*TT2*TT1];
__device__ __half g_cW1h[(size_t)TT1*NH2];
__device__ __half g_cW2h[(size_t)TT2*TT1];
__device__ __half g_tfh[(size_t)2*NB*NH2];
__device__ __half g_tfl[(size_t)2*NB*NH2];
__device__ __half g_th1h[(size_t)2*NB*TT1];
__device__ __half g_th1l[(size_t)2*NB*TT1];
__device__ __half g_cth[(size_t)NB*NH2];
__device__ __half g_ctl[(size_t)NB*NH2];
__device__ __half g_ch1h[(size_t)NB*TT1];
__device__ __half g_ch1l[(size_t)NB*TT1];
__device__ float g_FEA [(size_t)NE*NB*NH2];
__device__ float g_GATES[(size_t)NB*2*8];
__device__ float g_CGATE[(size_t)NB*8];
__device__ float g_PEF [(size_t)NB*PEN];

// ================= helpers =================
__device__ __forceinline__ u32 smem_u32(const void* p) {
    u32 a;
    asm("{ .reg .u64 t; cvta.to.shared.u64 t, %1; cvt.u32.u64 %0, t; }" : "=r"(a) : "l"(p));
    return a;
}
__device__ __forceinline__ void cpa16(u32 dst, const void* src) {
    asm volatile("cp.async.cg.shared.global [%0], [%1], 16;" :: "r"(dst), "l"(src) : "memory");
}
#define CPA_COMMIT() asm volatile("cp.async.commit_group;" ::: "memory")
#define CPA_WAIT2()  asm volatile("cp.async.wait_group 2;" ::: "memory")

__device__ __forceinline__ void mma16816(float* c, const u32* a, const u32* b) {
    asm volatile(
        "mma.sync.aligned.m16n8k16.row.col.f32.f16.f16.f32 "
        "{%0,%1,%2,%3}, {%4,%5,%6,%7}, {%8,%9}, {%0,%1,%2,%3};"
        : "+f"(c[0]), "+f"(c[1]), "+f"(c[2]), "+f"(c[3])
        : "r"(a[0]), "r"(a[1]), "r"(a[2]), "r"(a[3]), "r"(b[0]), "r"(b[1]));
}

// swizzled smem offset (64B rows, 4x16B chunks)
__device__ __forceinline__ u32 swz(int row, int ch) {
    return (u32)(row * 64 + ((ch ^ ((row >> 1) & 3)) << 4));
}

__device__ __forceinline__ void ldA(u32 tb, int row0, int s, u32* a) {
    int lane = threadIdx.x & 31;
    int g = lane >> 3, li = lane & 7;
    int row = row0 + ((g & 1) << 3) + li;
    int ch = 2 * s + (g >> 1);
    u32 addr = tb + swz(row, ch);
    asm volatile("ldmatrix.sync.aligned.m8n8.x4.shared.b16 {%0,%1,%2,%3}, [%4];"
        : "=r"(a[0]), "=r"(a[1]), "=r"(a[2]), "=r"(a[3]) : "r"(addr));
}
__device__ __forceinline__ void ldB(u32 tb, int n0, int s, u32* r) {
    int lane = threadIdx.x & 31;
    int g = lane >> 3, li = lane & 7;
    int row = n0 + ((g >> 1) << 3) + li;
    int ch = 2 * s + (g & 1);
    u32 addr = tb + swz(row, ch);
    asm volatile("ldmatrix.sync.aligned.m8n8.x4.shared.b16 {%0,%1,%2,%3}, [%4];"
        : "=r"(r[0]), "=r"(r[1]), "=r"(r[2]), "=r"(r[3]) : "r"(addr));
}
__device__ __forceinline__ void split_hl(float v, __half& h, __half& l) {
    h = __float2half_rn(v);
    l = __float2half_rn(v - __half2float(h));
}

// ============================================================
// HMMA GEMM template.
//   C[z] = relu(A[z] @ B[z]^T + bias[z])
// A [M, aK] fp16 (hi + optional lo); B [N, K] fp16 (pre-transposed W).
// A's k-column for chunk c = (c & acolmask)*32  (A streamed cyclically when aK<K).
// PESCALE: K split into segments of 512 (16 chunks); segment p's partial sum
//   is scaled by per-row pe[row][p] (fp32) into a master accumulator.
// mode: 0 = fp32 C, 1 = fp16 hi/lo C, 2 = fp16 hi-only C.
// ============================================================
template<int TWOPASS, int PESCALE>
__global__ void __launch_bounds__(256, 1) hmma_t(
    const __half* __restrict__ Ah, const __half* __restrict__ Al,
    const __half* __restrict__ Bh, const float* __restrict__ bias,
    float* __restrict__ Cf, __half* __restrict__ Ch, __half* __restrict__ Cl,
    const float* __restrict__ pef,
    int N, int K, int acolmask, int aK,
    size_t sA, size_t sB, size_t sBias, size_t sC, int mode)
{
    extern __shared__ char dsm[];
    const int STAGE = TWOPASS ? 24576 : 16384;
    const int NSLOT = TWOPASS ? 6 : 4;
    const int tid = threadIdx.x;
    const int wid = tid >> 5;
    const int lane = tid & 31;
    const int z = blockIdx.z;
    const int bm = blockIdx.y << 7;
    const int bn = blockIdx.x << 7;

    Ah += (size_t)z * sA;
    if (TWOPASS) Al += (size_t)z * sA;
    Bh += (size_t)z * sB;  bias += (size_t)z * sBias;

    const u32 sbase = smem_u32(dsm);

    u32 soff[NSLOT];
    const __half* gsrc[NSLOT];
    u32 amask[NSLOT];
    #pragma unroll
    for (int j = 0; j < NSLOT; j++) {
        int sid = tid + (j << 8);
        int buf = sid >> 9;
        int rem = sid & 511;
        int r = rem >> 2;
        int ch = rem & 3;
        soff[j] = (u32)(buf * 8192) + swz(r, ch);
        bool isA = TWOPASS ? (buf < 2) : (buf == 0);
        const __half* base = isA ? ((TWOPASS && buf == 1) ? Al : Ah) : Bh;
        int grow = (isA ? bm : bn) + r;
        gsrc[j] = base + (size_t)grow * (isA ? aK : K) + ch * 8;
        amask[j] = isA ? (u32)acolmask : 0xFFFFFFFFu;
    }

    const int nch = K >> 5;

    #pragma unroll
    for (int p = 0; p < 3; p++) {
        u32 sb = sbase + (u32)p * STAGE;
        #pragma unroll
        for (int j = 0; j < NSLOT; j++) cpa16(sb + soff[j], gsrc[j] + (((u32)p & amask[j]) << 5));
        CPA_COMMIT();
    }

    const int wm = (wid & 3) << 5;
    const int wn = (wid >> 2) << 6;
    const u32 Boff = TWOPASS ? 16384u : 8192u;

    float acc[2][8][4];
    float macc[2][8][4];
    #pragma unroll
    for (int i = 0; i < 2; i++)
        #pragma unroll
        for (int j = 0; j < 8; j++)
            #pragma unroll
            for (int q = 0; q < 4; q++) { acc[i][j][q] = 0.f; if (PESCALE) macc[i][j][q] = 0.f; }

    // per-row pe values: pfa[p][i2*2+parity]
    float pfa[PESCALE ? 5 : 1][4];
    float curpe[4] = {0.f, 0.f, 0.f, 0.f};
    if (PESCALE) {
        #pragma unroll
        for (int p = 0; p < 5; p++)
            #pragma unroll
            for (int t = 0; t < 4; t++) {
                int row = bm + wm + (t >> 1) * 16 + (lane >> 2) + (t & 1) * 8;
                pfa[p][t] = pef[(size_t)row * PEN + p];
            }
    }

    for (int i = 0; i < nch; i++) {
        if (PESCALE && (i & 15) == 0) {
            int p = i >> 4;
            #pragma unroll
            for (int t = 0; t < 4; t++) {
                float v = pfa[0][t];
                #pragma unroll
                for (int pp = 1; pp < 5; pp++) if (p == pp) v = pfa[pp][t];
                curpe[t] = v;
            }
        }
        CPA_WAIT2();
        __syncthreads();
        int pf = i + 3;
        if (pf < nch) {
            u32 sb = sbase + (u32)(pf & 3) * STAGE;
            #pragma unroll
            for (int j = 0; j < NSLOT; j++) cpa16(sb + soff[j], gsrc[j] + (((u32)pf & amask[j]) << 5));
        }
        CPA_COMMIT();

        u32 stb = sbase + (u32)(i & 3) * STAGE;
        #pragma unroll
        for (int s = 0; s < 2; s++) {
            u32 ah[2][4], b[8][2];
            ldA(stb, wm,      s, ah[0]);
            ldA(stb, wm + 16, s, ah[1]);
            #pragma unroll
            for (int j4 = 0; j4 < 4; j4++) {
                u32 r[4];
                ldB(stb + Boff, wn + j4 * 16, s, r);
                b[2 * j4][0] = r[0]; b[2 * j4][1] = r[1];
                b[2 * j4 + 1][0] = r[2]; b[2 * j4 + 1][1] = r[3];
            }
            #pragma unroll
            for (int i2 = 0; i2 < 2; i2++)
                #pragma unroll
                for (int j8 = 0; j8 < 8; j8++) mma16816(acc[i2][j8], ah[i2], b[j8]);
            if (TWOPASS) {
                u32 al[2][4];
                ldA(stb + 8192, wm,      s, al[0]);
                ldA(stb + 8192, wm + 16, s, al[1]);
                #pragma unroll
                for (int i2 = 0; i2 < 2; i2++)
                    #pragma unroll
                    for (int j8 = 0; j8 < 8; j8++) mma16816(acc[i2][j8], al[i2], b[j8]);
            }
        }

        if (PESCALE && (i & 15) == 15) {
            #pragma unroll
            for (int i2 = 0; i2 < 2; i2++)
                #pragma unroll
                for (int j8 = 0; j8 < 8; j8++)
                    #pragma unroll
                    for (int q = 0; q < 4; q++) {
                        macc[i2][j8][q] += curpe[i2 * 2 + (q >> 1)] * acc[i2][j8][q];
                        acc[i2][j8][q] = 0.f;
                    }
        }
    }

    float (*eacc)[8][4] = PESCALE ? macc : acc;

    // epilogue
    const int r0b = bm + wm + (lane >> 2);
    const int c0b = bn + wn + ((lane & 3) << 1);
    #pragma unroll
    for (int i2 = 0; i2 < 2; i2++) {
        #pragma unroll
        for (int j8 = 0; j8 < 8; j8++) {
            int col = c0b + j8 * 8;
            float b0 = bias[col], b1 = bias[col + 1];
            #pragma unroll
            for (int h = 0; h < 2; h++) {
                int row = r0b + i2 * 16 + h * 8;
                float v0 = fmaxf(eacc[i2][j8][2 * h]     + b0, 0.f);
                float v1 = fmaxf(eacc[i2][j8][2 * h + 1] + b1, 0.f);
                if (mode == 0) {
                    *(float2*)(Cf + (size_t)z * sC + (size_t)row * N + col) = make_float2(v0, v1);
                } else {
                    __half h0, l0, h1, l1;
                    split_hl(v0, h0, l0);
                    split_hl(v1, h1, l1);
                    __half2 hp; hp.x = h0; hp.y = h1;
                    *(__half2*)(Ch + (size_t)z * sC + (size_t)row * N + col) = hp;
                    if (mode == 1) {
                        __half2 lp; lp.x = l0; lp.y = l1;
                        *(__half2*)(Cl + (size_t)z * sC + (size_t)row * N + col) = lp;
                    }
                }
            }
        }
    }
}

// ============================================================
// weight transpose: W[z][K][N] f32 -> T[z][N][K] fp16
// ============================================================
__global__ void transpose_h(const float* __restrict__ W, __half* __restrict__ Th,
                            int Kd, int Nd)
{
    __shared__ float t[32][33];
    int z = blockIdx.z;
    const float* Wz = W + (size_t)z * Kd * Nd;
    int n0 = blockIdx.x << 5, k0 = blockIdx.y << 5;
    for (int r = threadIdx.y; r < 32; r += 8)
        t[r][threadIdx.x] = Wz[(size_t)(k0 + r) * Nd + n0 + threadIdx.x];
    __syncthreads();
    size_t ob = (size_t)z * Nd * Kd;
    for (int r = threadIdx.y; r < 32; r += 8)
        Th[ob + (size_t)(n0 + r) * Kd + k0 + threadIdx.x] = __float2half_rn(t[threadIdx.x][r]);
}

// CE1 weight: ceW1[z][d*5+p][n] f32 -> T[z][n][p*512+d] fp16 (p-major K)
__global__ void transpose_cw1(const float* __restrict__ W, __half* __restrict__ Th)
{
    __shared__ float t[32][33];
    int z = blockIdx.z;
    int n0 = blockIdx.x << 5;
    int p = blockIdx.y >> 4;
    int d0 = (blockIdx.y & 15) << 5;
    const float* Wz = W + (size_t)z * KAIT * NH1;
    for (int r = threadIdx.y; r < 32; r += 8)
        t[r][threadIdx.x] = Wz[(size_t)((d0 + r) * 5 + p) * NH1 + n0 + threadIdx.x];
    __syncthreads();
    size_t ob = (size_t)z * NH1 * KAIT;
    for (int r = threadIdx.y; r < 32; r += 8)
        Th[ob + (size_t)(n0 + r) * KAIT + p * 512 + d0 + threadIdx.x] =
            __float2half_rn(t[threadIdx.x][r]);
}

// elementwise fp32 -> fp16 hi/lo
__global__ void convert_split(const float* __restrict__ src,
                              __half* __restrict__ hi, __half* __restrict__ lo, size_t n)
{
    size_t i = ((size_t)blockIdx.x * blockDim.x + threadIdx.x) * 4;
    if (i >= n) return;
    float4 v = *(const float4*)(src + i);
    __half h0, l0, h1, l1, h2, l2, h3, l3;
    split_hl(v.x, h0, l0); split_hl(v.y, h1, l1);
    split_hl(v.z, h2, l2); split_hl(v.w, h3, l3);
    __half2 a, b, c, d;
    a.x = h0; a.y = h1; b.x = h2; b.y = h3;
    c.x = l0; c.y = l1; d.x = l2; d.y = l3;
    *(__half2*)(hi + i) = a; *(__half2*)(hi + i + 2) = b;
    *(__half2*)(lo + i) = c; *(__half2*)(lo + i + 2) = d;
}

// ================= small fp32 kernels =================
__global__ void gates_kernel(const float* __restrict__ x, const float* __restrict__ gW,
                             const float* __restrict__ gb, float* __restrict__ gates)
{
    int gw = (blockIdx.x * blockDim.x + threadIdx.x) >> 5;
    int lane = threadIdx.x & 31;
    if (gw >= NB * 2) return;
    int b = gw >> 1, t = gw & 1;
    const float* xr = x + (size_t)b * DD;
    float acc[8] = {};
    for (int d = lane; d < DD; d += 32) {
        float xv = xr[d];
        const float* g = gW + ((size_t)t * DD + d) * NE;
        float4 w0 = *(const float4*)g;
        float4 w1 = *(const float4*)(g + 4);
        acc[0] += xv * w0.x; acc[1] += xv * w0.y; acc[2] += xv * w0.z; acc[3] += xv * w0.w;
        acc[4] += xv * w1.x; acc[5] += xv * w1.y; acc[6] += xv * w1.z; acc[7] += xv * w1.w;
    }
    #pragma unroll
    for (int e = 0; e < 8; e++)
        #pragma unroll
        for (int o = 16; o; o >>= 1) acc[e] += __shfl_xor_sync(0xffffffffu, acc[e], o);
    float m = -1e30f;
    #pragma unroll
    for (int e = 0; e < 8; e++) { acc[e] += gb[t * 8 + e]; m = fmaxf(m, acc[e]); }
    float s = 0.f;
    #pragma unroll
    for (int e = 0; e < 8; e++) { acc[e] = expf(acc[e] - m); s += acc[e]; }
    float inv = 1.f / s;
    if (lane < 8) gates[((size_t)b * 2 + t) * 8 + lane] = acc[lane] * inv;
}

// fused combine for both tasks + fp16 split of task_fea (tower input)
__global__ void combine12(const float* __restrict__ fea, const float* __restrict__ gates,
                          float* __restrict__ o3, float* __restrict__ o4,
                          __half* __restrict__ tfh, __half* __restrict__ tfl)
{
    int b = blockIdx.x;
    __shared__ float g[16];
    if (threadIdx.x < 16) g[threadIdx.x] = gates[(size_t)b * 16 + threadIdx.x];
    __syncthreads();
    const float* f = fea + (size_t)b * NH2;
    for (int h = threadIdx.x; h < NH2; h += blockDim.x) {
        float s0 = 0.f, s1 = 0.f;
        #pragma unroll
        for (int e = 0; e < 8; e++) {
            float v = f[(size_t)e * NB * NH2 + h];
            s0 += g[e] * v;
            s1 += g[8 + e] * v;
        }
        o3[(size_t)b * NH2 + h] = s0;
        o4[(size_t)b * NH2 + h] = s1;
        __half hh, ll;
        split_hl(s0, hh, ll);
        tfh[(size_t)b * NH2 + h] = hh;
        tfl[(size_t)b * NH2 + h] = ll;
        split_hl(s1, hh, ll);
        tfh[(size_t)(NB + b) * NH2 + h] = hh;
        tfl[(size_t)(NB + b) * NH2 + h] = ll;
    }
}

// phase-2 combine: ctask -> O5 + fp16 split for cascade tower
__global__ void combine1c(const float* __restrict__ fea, const float* __restrict__ cg,
                          float* __restrict__ o5, __half* __restrict__ cth,
                          __half* __restrict__ ctl)
{
    int b = blockIdx.x;
    __shared__ float g[8];
    if (threadIdx.x < 8) g[threadIdx.x] = cg[(size_t)b * 8 + threadIdx.x];
    __syncthreads();
    const float* f = fea + (size_t)b * NH2;
    for (int h = threadIdx.x; h < NH2; h += blockDim.x) {
        float s = 0.f;
        #pragma unroll
        for (int e = 0; e < 8; e++) s += g[e] * f[(size_t)e * NB * NH2 + h];
        o5[(size_t)b * NH2 + h] = s;
        __half hh, ll;
        split_hl(s, hh, ll);
        cth[(size_t)b * NH2 + h] = hh;
        ctl[(size_t)b * NH2 + h] = ll;
    }
}

__global__ void preds_kernel(const float* __restrict__ outr, const float* __restrict__ pW,
                             const float* __restrict__ pb, float* __restrict__ out)
{
    int gw = (blockIdx.x * blockDim.x + threadIdx.x) >> 5;
    int lane = threadIdx.x & 31;
    if (gw >= NB * 2) return;
    int b = gw >> 1, t = gw & 1;
    const float* th2 = outr + O6 + (size_t)t * NB * TT2 + (size_t)b * TT2;
    const float* w = pW + t * TT2;
    float s = 0.f;
    for (int m = lane; m < TT2; m += 32) s += th2[m] * w[m];
    #pragma unroll
    for (int o = 16; o; o >>= 1) s += __shfl_xor_sync(0xffffffffu, s, o);
    if (lane == 0) {
        s += pb[t];
        out[(size_t)t * NB + b] = 1.f / (1.f + expf(-s));
    }
}

// pe[b,p] = pctr[b]*embW[p] + embB[p]  (fp32)
__global__ void pe_kernel(const float* __restrict__ out, const float* __restrict__ embW,
                          const float* __restrict__ embB, float* __restrict__ pef)
{
    int i = blockIdx.x * blockDim.x + threadIdx.x;
    if (i >= NB * PEN) return;
    int b = i / PEN, p = i - PEN * b;
    pef[i] = out[b] * embW[p] + embB[p];
}

// cgate from x (fp32) and pe (fp32): a_k = x[b, k/5] * pe[b, k%5]
__global__ void cgate_kernel(const float* __restrict__ x, const float* __restrict__ pef,
                             const float* __restrict__ cgW, const float* __restrict__ cgb,
                             float* __restrict__ cg)
{
    int gw = (blockIdx.x * blockDim.x + threadIdx.x) >> 5;
    int lane = threadIdx.x & 31;
    if (gw >= NB) return;
    const float* xr = x + (size_t)gw * DD;
    float pe[PEN];
    #pragma unroll
    for (int p = 0; p < PEN; p++) pe[p] = pef[(size_t)gw * PEN + p];
    float acc[8] = {};
    for (int k = lane; k < KAIT; k += 32) {
        int d = k / PEN, p = k - PEN * d;
        float a = xr[d] * pe[p];
        float4 w0 = *(const float4*)(cgW + (size_t)k * 8);
        float4 w1 = *(const float4*)(cgW + (size_t)k * 8 + 4);
        acc[0] += a * w0.x; acc[1] += a * w0.y; acc[2] += a * w0.z; acc[3] += a * w0.w;
        acc[4] += a * w1.x; acc[5] += a * w1.y; acc[6] += a * w1.z; acc[7] += a * w1.w;
    }
    #pragma unroll
    for (int e = 0; e < 8; e++)
        #pragma unroll
        for (int o = 16; o; o >>= 1) acc[e] += __shfl_xor_sync(0xffffffffu, acc[e], o);
    float m = -1e30f;
    #pragma unroll
    for (int e = 0; e < 8; e++) { acc[e] += cgb[e]; m = fmaxf(m, acc[e]); }
    float s = 0.f;
    #pragma unroll
    for (int e = 0; e < 8; e++) { acc[e] = expf(acc[e] - m); s += acc[e]; }
    float inv = 1.f / s;
    if (lane < 8) cg[(size_t)gw * 8 + lane] = acc[lane] * inv;
}

__global__ void pconv_kernel(const float* __restrict__ outr, const float* __restrict__ cpW,
                             const float* __restrict__ cpb, float* __restrict__ out)
{
    int gw = (blockIdx.x * blockDim.x + threadIdx.x) >> 5;
    int lane = threadIdx.x & 31;
    if (gw >= NB) return;
    const float* ch2 = outr + O8 + (size_t)gw * TT2;
    float s = 0.f;
    for (int m = lane; m < TT2; m += 32) s += ch2[m] * cpW[m];
    #pragma unroll
    for (int o = 16; o; o >>= 1) s += __shfl_xor_sync(0xffffffffu, s, o);
    if (lane == 0) out[O2 + gw] = 1.f / (1.f + expf(-(s + cpb[0])));
}

// ============================================================
extern "C" void kernel_launch(void* const* d_in, const int* in_sizes, int n_in,
                              void* d_out, int out_size)
{
    const float* x    = (const float*)d_in[0];
    const float* eW1  = (const float*)d_in[1];
    const float* eb1  = (const float*)d_in[2];
    const float* eW2  = (const float*)d_in[3];
    const float* eb2  = (const float*)d_in[4];
    const float* gW   = (const float*)d_in[5];
    const float* gb   = (const float*)d_in[6];
    const float* tW1  = (const float*)d_in[7];
    const float* tb1  = (const float*)d_in[8];
    const float* tW2  = (const float*)d_in[9];
    const float* tb2  = (const float*)d_in[10];
    const float* pW   = (const float*)d_in[11];
    const float* pb   = (const float*)d_in[12];
    const float* embW = (const float*)d_in[13];
    const float* embB = (const float*)d_in[14];
    const float* ceW1 = (const float*)d_in[15];
    const float* ceb1 = (const float*)d_in[16];
    const float* ceW2 = (const float*)d_in[17];
    const float* ceb2 = (const float*)d_in[18];
    const float* cgW  = (const float*)d_in[19];
    const float* cgb  = (const float*)d_in[20];
    const float* ctW1 = (const float*)d_in[21];
    const float* ctb1 = (const float*)d_in[22];
    const float* ctW2 = (const float*)d_in[23];
    const float* ctb2 = (const float*)d_in[24];
    const float* cpW  = (const float*)d_in[25];
    const float* cpb  = (const float*)d_in[26];
    float* out = (float*)d_out;

    __half *xh, *xl, *Hh, *W1h, *W2h, *CW1h, *CW2h, *tW1h, *tW2h, *cW1h, *cW2h;
    __half *tfh, *tfl, *th1h, *th1l, *cth, *ctl, *ch1h, *ch1l;
    float *pFEA, *pG, *pCG, *pPEF;
    cudaGetSymbolAddress((void**)&xh, g_xh);   cudaGetSymbolAddress((void**)&xl, g_xl);
    cudaGetSymbolAddress((void**)&Hh, g_Hh);
    cudaGetSymbolAddress((void**)&W1h, g_W1h); cudaGetSymbolAddress((void**)&W2h, g_W2h);
    cudaGetSymbolAddress((void**)&CW1h, g_CW1h); cudaGetSymbolAddress((void**)&CW2h, g_CW2h);
    cudaGetSymbolAddress((void**)&tW1h, g_tW1h); cudaGetSymbolAddress((void**)&tW2h, g_tW2h);
    cudaGetSymbolAddress((void**)&cW1h, g_cW1h); cudaGetSymbolAddress((void**)&cW2h, g_cW2h);
    cudaGetSymbolAddress((void**)&tfh, g_tfh); cudaGetSymbolAddress((void**)&tfl, g_tfl);
    cudaGetSymbolAddress((void**)&th1h, g_th1h); cudaGetSymbolAddress((void**)&th1l, g_th1l);
    cudaGetSymbolAddress((void**)&cth, g_cth); cudaGetSymbolAddress((void**)&ctl, g_ctl);
    cudaGetSymbolAddress((void**)&ch1h, g_ch1h); cudaGetSymbolAddress((void**)&ch1l, g_ch1l);
    cudaGetSymbolAddress((void**)&pFEA, g_FEA);
    cudaGetSymbolAddress((void**)&pG, g_GATES);
    cudaGetSymbolAddress((void**)&pCG, g_CGATE);
    cudaGetSymbolAddress((void**)&pPEF, g_PEF);

    const int SM2 = 4 * 24576;   // twopass stages
    const int SM1 = 4 * 16384;   // onepass stages
    cudaFuncSetAttribute(hmma_t<1, 0>, cudaFuncAttributeMaxDynamicSharedMemorySize, SM2);
    cudaFuncSetAttribute(hmma_t<1, 1>, cudaFuncAttributeMaxDynamicSharedMemorySize, SM2);
    cudaFuncSetAttribute(hmma_t<0, 0>, cudaFuncAttributeMaxDynamicSharedMemorySize, SM1);
    dim3 blk(256);
    dim3 tb(32, 8);

    // ---- weight prep ----
    transpose_h<<<dim3(NH1 / 32, DD / 32, NE), tb>>>(eW1, W1h, DD, NH1);
    transpose_h<<<dim3(NH2 / 32, NH1 / 32, NE), tb>>>(eW2, W2h, NH1, NH2);
    transpose_cw1<<<dim3(NH1 / 32, 80, NE), tb>>>(ceW1, CW1h);
    transpose_h<<<dim3(NH2 / 32, NH1 / 32, NE), tb>>>(ceW2, CW2h, NH1, NH2);
    transpose_h<<<dim3(TT1 / 32, NH2 / 32, 2), tb>>>(tW1, tW1h, NH2, TT1);
    transpose_h<<<dim3(TT2 / 32, TT1 / 32, 2), tb>>>(tW2, tW2h, TT1, TT2);
    transpose_h<<<dim3(TT1 / 32, NH2 / 32, 1), tb>>>(ctW1, cW1h, NH2, TT1);
    transpose_h<<<dim3(TT2 / 32, TT1 / 32, 1), tb>>>(ctW2, cW2h, TT1, TT2);
    convert_split<<<NB * DD / 4 / 256, 256>>>(x, xh, xl, (size_t)NB * DD);

    // ---- phase 1: experts ----
    hmma_t<1, 0><<<dim3(NH1 / 128, NB / 128, NE), blk, SM2>>>(
        xh, xl, W1h, eb1, nullptr, Hh, nullptr, nullptr,
        NH1, DD, 15, DD, 0, (size_t)NH1 * DD, NH1, (size_t)NB * NH1, 2);
    hmma_t<0, 0><<<dim3(NH2 / 128, NB / 128, NE), blk, SM1>>>(
        Hh, nullptr, W2h, eb2, pFEA, nullptr, nullptr, nullptr,
        NH2, NH1, 31, NH1, (size_t)NB * NH1, (size_t)NH2 * NH1, NH2, (size_t)NB * NH2, 0);

    gates_kernel<<<NB * 2 / 8, 256>>>(x, gW, gb, pG);
    combine12<<<NB, 256>>>(pFEA, pG, out + O3, out + O4, tfh, tfl);

    // towers (HMMA, 2-pass)
    hmma_t<1, 0><<<dim3(TT1 / 128, NB / 128, 2), blk, SM2>>>(
        tfh, tfl, tW1h, tb1, nullptr, th1h, th1l, nullptr,
        TT1, NH2, 15, NH2, (size_t)NB * NH2, (size_t)TT1 * NH2, TT1, (size_t)NB * TT1, 1);
    hmma_t<1, 0><<<dim3(1, NB / 128, 2), blk, SM2>>>(
        th1h, th1l, tW2h, tb2, out + O6, nullptr, nullptr, nullptr,
        TT2, TT1, 7, TT1, (size_t)NB * TT1, (size_t)TT2 * TT1, TT2, (size_t)NB * TT2, 0);
    preds_kernel<<<NB * 2 / 8, 256>>>(out, pW, pb, out);

    // ---- phase 2: cascade ----
    pe_kernel<<<(NB * PEN + 255) / 256, 256>>>(out, embW, embB, pPEF);
    hmma_t<1, 1><<<dim3(NH1 / 128, NB / 128, NE), blk, SM2>>>(
        xh, xl, CW1h, ceb1, nullptr, Hh, nullptr, pPEF,
        NH1, KAIT, 15, DD, 0, (size_t)NH1 * KAIT, NH1, (size_t)NB * NH1, 2);
    hmma_t<0, 0><<<dim3(NH2 / 128, NB / 128, NE), blk, SM1>>>(
        Hh, nullptr, CW2h, ceb2, pFEA, nullptr, nullptr, nullptr,
        NH2, NH1, 31, NH1, (size_t)NB * NH1, (size_t)NH2 * NH1, NH2, (size_t)NB * NH2, 0);
    cgate_kernel<<<NB / 8, 256>>>(x, pPEF, cgW, cgb, pCG);
    combine1c<<<NB, 256>>>(pFEA, pCG, out + O5, cth, ctl);

    hmma_t<1, 0><<<dim3(TT1 / 128, NB / 128, 1), blk, SM2>>>(
        cth, ctl, cW1h, ctb1, nullptr, ch1h, ch1l, nullptr,
        TT1, NH2, 15, NH2, 0, 0, 0, (size_t)NB * TT1, 1);
    hmma_t<1, 0><<<dim3(1, NB / 128, 1), blk, SM2>>>(
        ch1h, ch1l, cW2h, ctb2, out + O8, nullptr, nullptr, nullptr,
        TT2, TT1, 7, TT1, 0, 0, 0, 0, 0);
    pconv_kernel<<<NB / 8, 256>>>(out, cpW, cpb, out);
}

// round 5
// speedup vs baseline: 6.2979x; 1.6707x over previous
#include <cuda_runtime.h>
#include <cuda_fp16.h>
#include <math.h>

typedef unsigned long long ull;
typedef unsigned int u32;

#define NB   16384
#define DD   512
#define NE   8
#define NH1  1024
#define NH2  512
#define TT1  256
#define TT2  128
#define PEN  5
#define KAIT 2560   // D*PE

// ---- output layout ----
#define O0 ((size_t)0)
#define O1 ((size_t)NB)
#define O2 ((size_t)2*NB)
#define O3 ((size_t)3*NB)
#define O4 (O3 + (size_t)NB*512)
#define O5 (O4 + (size_t)NB*512)
#define O6 (O5 + (size_t)NB*512)
#define O7 (O6 + (size_t)NB*128)
#define O8 (O7 + (size_t)NB*128)

// ---- scratch ----
__device__ __half g_xh [(size_t)NB*DD];
__device__ __half g_xl [(size_t)NB*DD];
__device__ __half g_cxh[(size_t)NB*1024];   // [x | pctr*x] hi
__device__ __half g_cxl[(size_t)NB*1024];   // [x | pctr*x] lo
__device__ __half g_Hh [(size_t)NE*NB*NH1];
__device__ __half g_W1h[(size_t)NE*NH1*DD];
__device__ __half g_W2h[(size_t)NE*NH2*NH1];
__device__ __half g_CUh[(size_t)NE*NH1*1024];  // [U0;U1] per expert, [N][1024]
__device__ __half g_CW2h[(size_t)NE*NH2*NH1];
__device__ __half g_tW1h[(size_t)2*TT1*NH2];
__device__ __half g_tW2h[(size_t)2*TT2*TT1];
__device__ __half g_cW1h[(size_t)TT1*NH2];
__device__ __half g_cW2h[(size_t)TT2*TT1];
__device__ __half g_tfh[(size_t)2*NB*NH2];
__device__ __half g_tfl[(size_t)2*NB*NH2];
__device__ __half g_th1h[(size_t)2*NB*TT1];
__device__ __half g_th1l[(size_t)2*NB*TT1];
__device__ __half g_cth[(size_t)NB*NH2];
__device__ __half g_ctl[(size_t)NB*NH2];
__device__ __half g_ch1h[(size_t)NB*TT1];
__device__ __half g_ch1l[(size_t)NB*TT1];
__device__ float g_FEA [(size_t)NE*NB*NH2];
__device__ float g_GATES[(size_t)NB*2*8];
__device__ float g_CGATE[(size_t)NB*8];
__device__ float g_UG  [(size_t)2*DD*8];    // cgate u0/u1

// ================= helpers =================
__device__ __forceinline__ u32 smem_u32(const void* p) {
    u32 a;
    asm("{ .reg .u64 t; cvta.to.shared.u64 t, %1; cvt.u32.u64 %0, t; }" : "=r"(a) : "l"(p));
    return a;
}
__device__ __forceinline__ void cpa16(u32 dst, const void* src) {
    asm volatile("cp.async.cg.shared.global [%0], [%1], 16;" :: "r"(dst), "l"(src) : "memory");
}
#define CPA_COMMIT() asm volatile("cp.async.commit_group;" ::: "memory")
#define CPA_WAIT2()  asm volatile("cp.async.wait_group 2;" ::: "memory")

__device__ __forceinline__ void mma16816(float* c, const u32* a, const u32* b) {
    asm volatile(
        "mma.sync.aligned.m16n8k16.row.col.f32.f16.f16.f32 "
        "{%0,%1,%2,%3}, {%4,%5,%6,%7}, {%8,%9}, {%0,%1,%2,%3};"
        : "+f"(c[0]), "+f"(c[1]), "+f"(c[2]), "+f"(c[3])
        : "r"(a[0]), "r"(a[1]), "r"(a[2]), "r"(a[3]), "r"(b[0]), "r"(b[1]));
}

// swizzled smem offset (64B rows, 4x16B chunks)
__device__ __forceinline__ u32 swz(int row, int ch) {
    return (u32)(row * 64 + ((ch ^ ((row >> 1) & 3)) << 4));
}

__device__ __forceinline__ void ldA(u32 tb, int row0, int s, u32* a) {
    int lane = threadIdx.x & 31;
    int g = lane >> 3, li = lane & 7;
    int row = row0 + ((g & 1) << 3) + li;
    int ch = 2 * s + (g >> 1);
    u32 addr = tb + swz(row, ch);
    asm volatile("ldmatrix.sync.aligned.m8n8.x4.shared.b16 {%0,%1,%2,%3}, [%4];"
        : "=r"(a[0]), "=r"(a[1]), "=r"(a[2]), "=r"(a[3]) : "r"(addr));
}
__device__ __forceinline__ void ldB(u32 tb, int n0, int s, u32* r) {
    int lane = threadIdx.x & 31;
    int g = lane >> 3, li = lane & 7;
    int row = n0 + ((g >> 1) << 3) + li;
    int ch = 2 * s + (g & 1);
    u32 addr = tb + swz(row, ch);
    asm volatile("ldmatrix.sync.aligned.m8n8.x4.shared.b16 {%0,%1,%2,%3}, [%4];"
        : "=r"(r[0]), "=r"(r[1]), "=r"(r[2]), "=r"(r[3]) : "r"(addr));
}
__device__ __forceinline__ void split_hl(float v, __half& h, __half& l) {
    h = __float2half_rn(v);
    l = __float2half_rn(v - __half2float(h));
}

// ============================================================
// HMMA GEMM template.
//   C[z] = relu(A[z] @ B[z]^T + bias[z])
// A [M, aK] fp16 (hi + optional lo); B [N, K] fp16 (pre-transposed).
// A k-column for chunk c = (c & acolmask)*32.
// mode: 0 = fp32 C, 1 = fp16 hi/lo C, 2 = fp16 hi-only C.
// ============================================================
template<int TWOPASS>
__global__ void __launch_bounds__(256, 1) hmma_t(
    const __half* __restrict__ Ah, const __half* __restrict__ Al,
    const __half* __restrict__ Bh, const float* __restrict__ bias,
    float* __restrict__ Cf, __half* __restrict__ Ch, __half* __restrict__ Cl,
    int N, int K, int acolmask, int aK,
    size_t sA, size_t sB, size_t sBias, size_t sC, int mode)
{
    extern __shared__ char dsm[];
    const int STAGE = TWOPASS ? 24576 : 16384;
    const int NSLOT = TWOPASS ? 6 : 4;
    const int tid = threadIdx.x;
    const int wid = tid >> 5;
    const int lane = tid & 31;
    const int z = blockIdx.z;
    const int bm = blockIdx.y << 7;
    const int bn = blockIdx.x << 7;

    Ah += (size_t)z * sA;
    if (TWOPASS) Al += (size_t)z * sA;
    Bh += (size_t)z * sB;  bias += (size_t)z * sBias;

    const u32 sbase = smem_u32(dsm);

    u32 soff[NSLOT];
    const __half* gsrc[NSLOT];
    u32 amask[NSLOT];
    #pragma unroll
    for (int j = 0; j < NSLOT; j++) {
        int sid = tid + (j << 8);
        int buf = sid >> 9;
        int rem = sid & 511;
        int r = rem >> 2;
        int ch = rem & 3;
        soff[j] = (u32)(buf * 8192) + swz(r, ch);
        bool isA = TWOPASS ? (buf < 2) : (buf == 0);
        const __half* base = isA ? ((TWOPASS && buf == 1) ? Al : Ah) : Bh;
        int grow = (isA ? bm : bn) + r;
        gsrc[j] = base + (size_t)grow * (isA ? aK : K) + ch * 8;
        amask[j] = isA ? (u32)acolmask : 0xFFFFFFFFu;
    }

    const int nch = K >> 5;

    #pragma unroll
    for (int p = 0; p < 3; p++) {
        u32 sb = sbase + (u32)p * STAGE;
        #pragma unroll
        for (int j = 0; j < NSLOT; j++) cpa16(sb + soff[j], gsrc[j] + (((u32)p & amask[j]) << 5));
        CPA_COMMIT();
    }

    const int wm = (wid & 3) << 5;
    const int wn = (wid >> 2) << 6;
    const u32 Boff = TWOPASS ? 16384u : 8192u;

    float acc[2][8][4];
    #pragma unroll
    for (int i = 0; i < 2; i++)
        #pragma unroll
        for (int j = 0; j < 8; j++)
            #pragma unroll
            for (int q = 0; q < 4; q++) acc[i][j][q] = 0.f;

    for (int i = 0; i < nch; i++) {
        CPA_WAIT2();
        __syncthreads();
        int pf = i + 3;
        if (pf < nch) {
            u32 sb = sbase + (u32)(pf & 3) * STAGE;
            #pragma unroll
            for (int j = 0; j < NSLOT; j++) cpa16(sb + soff[j], gsrc[j] + (((u32)pf & amask[j]) << 5));
        }
        CPA_COMMIT();

        u32 stb = sbase + (u32)(i & 3) * STAGE;
        #pragma unroll
        for (int s = 0; s < 2; s++) {
            u32 ah[2][4], b[8][2];
            ldA(stb, wm,      s, ah[0]);
            ldA(stb, wm + 16, s, ah[1]);
            #pragma unroll
            for (int j4 = 0; j4 < 4; j4++) {
                u32 r[4];
                ldB(stb + Boff, wn + j4 * 16, s, r);
                b[2 * j4][0] = r[0]; b[2 * j4][1] = r[1];
                b[2 * j4 + 1][0] = r[2]; b[2 * j4 + 1][1] = r[3];
            }
            #pragma unroll
            for (int i2 = 0; i2 < 2; i2++)
                #pragma unroll
                for (int j8 = 0; j8 < 8; j8++) mma16816(acc[i2][j8], ah[i2], b[j8]);
            if (TWOPASS) {
                u32 al[2][4];
                ldA(stb + 8192, wm,      s, al[0]);
                ldA(stb + 8192, wm + 16, s, al[1]);
                #pragma unroll
                for (int i2 = 0; i2 < 2; i2++)
                    #pragma unroll
                    for (int j8 = 0; j8 < 8; j8++) mma16816(acc[i2][j8], al[i2], b[j8]);
            }
        }
    }

    // epilogue
    const int r0b = bm + wm + (lane >> 2);
    const int c0b = bn + wn + ((lane & 3) << 1);
    #pragma unroll
    for (int i2 = 0; i2 < 2; i2++) {
        #pragma unroll
        for (int j8 = 0; j8 < 8; j8++) {
            int col = c0b + j8 * 8;
            float b0 = bias[col], b1 = bias[col + 1];
            #pragma unroll
            for (int h = 0; h < 2; h++) {
                int row = r0b + i2 * 16 + h * 8;
                float v0 = fmaxf(acc[i2][j8][2 * h]     + b0, 0.f);
                float v1 = fmaxf(acc[i2][j8][2 * h + 1] + b1, 0.f);
                if (mode == 0) {
                    *(float2*)(Cf + (size_t)z * sC + (size_t)row * N + col) = make_float2(v0, v1);
                } else {
                    __half h0, l0, h1, l1;
                    split_hl(v0, h0, l0);
                    split_hl(v1, h1, l1);
                    __half2 hp; hp.x = h0; hp.y = h1;
                    *(__half2*)(Ch + (size_t)z * sC + (size_t)row * N + col) = hp;
                    if (mode == 1) {
                        __half2 lp; lp.x = l0; lp.y = l1;
                        *(__half2*)(Cl + (size_t)z * sC + (size_t)row * N + col) = lp;
                    }
                }
            }
        }
    }
}

// ============================================================
// weight transpose: W[z][K][N] f32 -> T[z][N][K] fp16
// ============================================================
__global__ void transpose_h(const float* __restrict__ W, __half* __restrict__ Th,
                            int Kd, int Nd)
{
    __shared__ float t[32][33];
    int z = blockIdx.z;
    const float* Wz = W + (size_t)z * Kd * Nd;
    int n0 = blockIdx.x << 5, k0 = blockIdx.y << 5;
    for (int r = threadIdx.y; r < 32; r += 8)
        t[r][threadIdx.x] = Wz[(size_t)(k0 + r) * Nd + n0 + threadIdx.x];
    __syncthreads();
    size_t ob = (size_t)z * Nd * Kd;
    for (int r = threadIdx.y; r < 32; r += 8)
        Th[ob + (size_t)(n0 + r) * Kd + k0 + threadIdx.x] = __float2half_rn(t[threadIdx.x][r]);
}

// CE1 collapse: ceW1[z][d*5+p][n] f32 -> CU[z][n][d] = sum_p embB_p*W,
//                                        CU[z][n][512+d] = sum_p embW_p*W
__global__ void prep_cu(const float* __restrict__ W, const float* __restrict__ embW,
                        const float* __restrict__ embB, __half* __restrict__ CU)
{
    __shared__ float t0[32][33], t1[32][33];
    int z = blockIdx.z;
    int n0 = blockIdx.x << 5, d0 = blockIdx.y << 5;
    const float* Wz = W + (size_t)z * KAIT * NH1;
    float ew[PEN], eb[PEN];
    #pragma unroll
    for (int p = 0; p < PEN; p++) { ew[p] = embW[p]; eb[p] = embB[p]; }
    for (int r = threadIdx.y; r < 32; r += 8) {
        float s0 = 0.f, s1 = 0.f;
        #pragma unroll
        for (int p = 0; p < PEN; p++) {
            float w = Wz[(size_t)((d0 + r) * PEN + p) * NH1 + n0 + threadIdx.x];
            s0 += eb[p] * w;
            s1 += ew[p] * w;
        }
        t0[r][threadIdx.x] = s0;
        t1[r][threadIdx.x] = s1;
    }
    __syncthreads();
    size_t ob = (size_t)z * NH1 * 1024;
    for (int r = threadIdx.y; r < 32; r += 8) {
        CU[ob + (size_t)(n0 + r) * 1024 + d0 + threadIdx.x] =
            __float2half_rn(t0[threadIdx.x][r]);
        CU[ob + (size_t)(n0 + r) * 1024 + 512 + d0 + threadIdx.x] =
            __float2half_rn(t1[threadIdx.x][r]);
    }
}

// cgate collapse: u0[d][e] = sum_p embB_p*cgW[d*5+p][e]; u1 likewise with embW
__global__ void prep_ug(const float* __restrict__ cgW, const float* __restrict__ embW,
                        const float* __restrict__ embB, float* __restrict__ u)
{
    int i = blockIdx.x * blockDim.x + threadIdx.x;
    if (i >= DD * 8) return;
    int d = i >> 3, e = i & 7;
    float s0 = 0.f, s1 = 0.f;
    #pragma unroll
    for (int p = 0; p < PEN; p++) {
        float w = cgW[(size_t)(d * PEN + p) * 8 + e];
        s0 += embB[p] * w;
        s1 += embW[p] * w;
    }
    u[i] = s0;
    u[DD * 8 + i] = s1;
}

// elementwise fp32 -> fp16 hi/lo
__global__ void convert_split(const float* __restrict__ src,
                              __half* __restrict__ hi, __half* __restrict__ lo, size_t n)
{
    size_t i = ((size_t)blockIdx.x * blockDim.x + threadIdx.x) * 4;
    if (i >= n) return;
    float4 v = *(const float4*)(src + i);
    __half h0, l0, h1, l1, h2, l2, h3, l3;
    split_hl(v.x, h0, l0); split_hl(v.y, h1, l1);
    split_hl(v.z, h2, l2); split_hl(v.w, h3, l3);
    __half2 a, b, c, d;
    a.x = h0; a.y = h1; b.x = h2; b.y = h3;
    c.x = l0; c.y = l1; d.x = l2; d.y = l3;
    *(__half2*)(hi + i) = a; *(__half2*)(hi + i + 2) = b;
    *(__half2*)(lo + i) = c; *(__half2*)(lo + i + 2) = d;
}

// cx[b] = [x[b] | pctr[b]*x[b]] fp16 hi/lo (CE1 A operand)
__global__ void cx_kernel(const float* __restrict__ x, const float* __restrict__ out,
                          __half* __restrict__ cxh, __half* __restrict__ cxl)
{
    int b = blockIdx.x;
    float pc = out[b];
    const float* xr = x + (size_t)b * DD;
    size_t ob = (size_t)b * 1024;
    for (int d = threadIdx.x; d < DD; d += blockDim.x) {
        float v = xr[d];
        __half h, l;
        split_hl(v, h, l);
        cxh[ob + d] = h; cxl[ob + d] = l;
        float v2 = pc * v;
        split_hl(v2, h, l);
        cxh[ob + 512 + d] = h; cxl[ob + 512 + d] = l;
    }
}

// ================= small fp32 kernels =================
__global__ void gates_kernel(const float* __restrict__ x, const float* __restrict__ gW,
                             const float* __restrict__ gb, float* __restrict__ gates)
{
    int gw = (blockIdx.x * blockDim.x + threadIdx.x) >> 5;
    int lane = threadIdx.x & 31;
    if (gw >= NB * 2) return;
    int b = gw >> 1, t = gw & 1;
    const float* xr = x + (size_t)b * DD;
    float acc[8] = {};
    for (int d = lane; d < DD; d += 32) {
        float xv = xr[d];
        const float* g = gW + ((size_t)t * DD + d) * NE;
        float4 w0 = *(const float4*)g;
        float4 w1 = *(const float4*)(g + 4);
        acc[0] += xv * w0.x; acc[1] += xv * w0.y; acc[2] += xv * w0.z; acc[3] += xv * w0.w;
        acc[4] += xv * w1.x; acc[5] += xv * w1.y; acc[6] += xv * w1.z; acc[7] += xv * w1.w;
    }
    #pragma unroll
    for (int e = 0; e < 8; e++)
        #pragma unroll
        for (int o = 16; o; o >>= 1) acc[e] += __shfl_xor_sync(0xffffffffu, acc[e], o);
    float m = -1e30f;
    #pragma unroll
    for (int e = 0; e < 8; e++) { acc[e] += gb[t * 8 + e]; m = fmaxf(m, acc[e]); }
    float s = 0.f;
    #pragma unroll
    for (int e = 0; e < 8; e++) { acc[e] = expf(acc[e] - m); s += acc[e]; }
    float inv = 1.f / s;
    if (lane < 8) gates[((size_t)b * 2 + t) * 8 + lane] = acc[lane] * inv;
}

// fused combine for both tasks + fp16 split of task_fea (tower input)
__global__ void combine12(const float* __restrict__ fea, const float* __restrict__ gates,
                          float* __restrict__ o3, float* __restrict__ o4,
                          __half* __restrict__ tfh, __half* __restrict__ tfl)
{
    int b = blockIdx.x;
    __shared__ float g[16];
    if (threadIdx.x < 16) g[threadIdx.x] = gates[(size_t)b * 16 + threadIdx.x];
    __syncthreads();
    const float* f = fea + (size_t)b * NH2;
    for (int h = threadIdx.x; h < NH2; h += blockDim.x) {
        float s0 = 0.f, s1 = 0.f;
        #pragma unroll
        for (int e = 0; e < 8; e++) {
            float v = f[(size_t)e * NB * NH2 + h];
            s0 += g[e] * v;
            s1 += g[8 + e] * v;
        }
        o3[(size_t)b * NH2 + h] = s0;
        o4[(size_t)b * NH2 + h] = s1;
        __half hh, ll;
        split_hl(s0, hh, ll);
        tfh[(size_t)b * NH2 + h] = hh;
        tfl[(size_t)b * NH2 + h] = ll;
        split_hl(s1, hh, ll);
        tfh[(size_t)(NB + b) * NH2 + h] = hh;
        tfl[(size_t)(NB + b) * NH2 + h] = ll;
    }
}

// phase-2 combine: ctask -> O5 + fp16 split for cascade tower
__global__ void combine1c(const float* __restrict__ fea, const float* __restrict__ cg,
                          float* __restrict__ o5, __half* __restrict__ cth,
                          __half* __restrict__ ctl)
{
    int b = blockIdx.x;
    __shared__ float g[8];
    if (threadIdx.x < 8) g[threadIdx.x] = cg[(size_t)b * 8 + threadIdx.x];
    __syncthreads();
    const float* f = fea + (size_t)b * NH2;
    for (int h = threadIdx.x; h < NH2; h += blockDim.x) {
        float s = 0.f;
        #pragma unroll
        for (int e = 0; e < 8; e++) s += g[e] * f[(size_t)e * NB * NH2 + h];
        o5[(size_t)b * NH2 + h] = s;
        __half hh, ll;
        split_hl(s, hh, ll);
        cth[(size_t)b * NH2 + h] = hh;
        ctl[(size_t)b * NH2 + h] = ll;
    }
}

__global__ void preds_kernel(const float* __restrict__ outr, const float* __restrict__ pW,
                             const float* __restrict__ pb, float* __restrict__ out)
{
    int gw = (blockIdx.x * blockDim.x + threadIdx.x) >> 5;
    int lane = threadIdx.x & 31;
    if (gw >= NB * 2) return;
    int b = gw >> 1, t = gw & 1;
    const float* th2 = outr + O6 + (size_t)t * NB * TT2 + (size_t)b * TT2;
    const float* w = pW + t * TT2;
    float s = 0.f;
    for (int m = lane; m < TT2; m += 32) s += th2[m] * w[m];
    #pragma unroll
    for (int o = 16; o; o >>= 1) s += __shfl_xor_sync(0xffffffffu, s, o);
    if (lane == 0) {
        s += pb[t];
        out[(size_t)t * NB + b] = 1.f / (1.f + expf(-s));
    }
}

// cgate via collapsed u: logits_e = x.u0[:,e] + pctr*(x.u1[:,e]) + cgb
__global__ void cgate_kernel(const float* __restrict__ x, const float* __restrict__ out,
                             const float* __restrict__ u, const float* __restrict__ cgb,
                             float* __restrict__ cg)
{
    int gw = (blockIdx.x * blockDim.x + threadIdx.x) >> 5;
    int lane = threadIdx.x & 31;
    if (gw >= NB) return;
    const float* xr = x + (size_t)gw * DD;
    float a0[8] = {}, a1[8] = {};
    for (int d = lane; d < DD; d += 32) {
        float xv = xr[d];
        const float* u0 = u + (size_t)d * 8;
        const float* u1 = u + (size_t)(DD + d) * 8;
        float4 w0 = *(const float4*)u0;
        float4 w1 = *(const float4*)(u0 + 4);
        a0[0] += xv * w0.x; a0[1] += xv * w0.y; a0[2] += xv * w0.z; a0[3] += xv * w0.w;
        a0[4] += xv * w1.x; a0[5] += xv * w1.y; a0[6] += xv * w1.z; a0[7] += xv * w1.w;
        float4 v0 = *(const float4*)u1;
        float4 v1 = *(const float4*)(u1 + 4);
        a1[0] += xv * v0.x; a1[1] += xv * v0.y; a1[2] += xv * v0.z; a1[3] += xv * v0.w;
        a1[4] += xv * v1.x; a1[5] += xv * v1.y; a1[6] += xv * v1.z; a1[7] += xv * v1.w;
    }
    #pragma unroll
    for (int e = 0; e < 8; e++) {
        #pragma unroll
        for (int o = 16; o; o >>= 1) {
            a0[e] += __shfl_xor_sync(0xffffffffu, a0[e], o);
            a1[e] += __shfl_xor_sync(0xffffffffu, a1[e], o);
        }
    }
    float pc = out[gw];
    float m = -1e30f;
    float acc[8];
    #pragma unroll
    for (int e = 0; e < 8; e++) {
        acc[e] = a0[e] + pc * a1[e] + cgb[e];
        m = fmaxf(m, acc[e]);
    }
    float s = 0.f;
    #pragma unroll
    for (int e = 0; e < 8; e++) { acc[e] = expf(acc[e] - m); s += acc[e]; }
    float inv = 1.f / s;
    if (lane < 8) cg[(size_t)gw * 8 + lane] = acc[lane] * inv;
}

__global__ void pconv_kernel(const float* __restrict__ outr, const float* __restrict__ cpW,
                             const float* __restrict__ cpb, float* __restrict__ out)
{
    int gw = (blockIdx.x * blockDim.x + threadIdx.x) >> 5;
    int lane = threadIdx.x & 31;
    if (gw >= NB) return;
    const float* ch2 = outr + O8 + (size_t)gw * TT2;
    float s = 0.f;
    for (int m = lane; m < TT2; m += 32) s += ch2[m] * cpW[m];
    #pragma unroll
    for (int o = 16; o; o >>= 1) s += __shfl_xor_sync(0xffffffffu, s, o);
    if (lane == 0) out[O2 + gw] = 1.f / (1.f + expf(-(s + cpb[0])));
}

// ============================================================
extern "C" void kernel_launch(void* const* d_in, const int* in_sizes, int n_in,
                              void* d_out, int out_size)
{
    const float* x    = (const float*)d_in[0];
    const float* eW1  = (const float*)d_in[1];
    const float* eb1  = (const float*)d_in[2];
    const float* eW2  = (const float*)d_in[3];
    const float* eb2  = (const float*)d_in[4];
    const float* gW   = (const float*)d_in[5];
    const float* gb   = (const float*)d_in[6];
    const float* tW1  = (const float*)d_in[7];
    const float* tb1  = (const float*)d_in[8];
    const float* tW2  = (const float*)d_in[9];
    const float* tb2  = (const float*)d_in[10];
    const float* pW   = (const float*)d_in[11];
    const float* pb   = (const float*)d_in[12];
    const float* embW = (const float*)d_in[13];
    const float* embB = (const float*)d_in[14];
    const float* ceW1 = (const float*)d_in[15];
    const float* ceb1 = (const float*)d_in[16];
    const float* ceW2 = (const float*)d_in[17];
    const float* ceb2 = (const float*)d_in[18];
    const float* cgW  = (const float*)d_in[19];
    const float* cgb  = (const float*)d_in[20];
    const float* ctW1 = (const float*)d_in[21];
    const float* ctb1 = (const float*)d_in[22];
    const float* ctW2 = (const float*)d_in[23];
    const float* ctb2 = (const float*)d_in[24];
    const float* cpW  = (const float*)d_in[25];
    const float* cpb  = (const float*)d_in[26];
    float* out = (float*)d_out;

    __half *xh, *xl, *cxh, *cxl, *Hh, *W1h, *W2h, *CUh, *CW2h, *tW1h, *tW2h, *cW1h, *cW2h;
    __half *tfh, *tfl, *th1h, *th1l, *cth, *ctl, *ch1h, *ch1l;
    float *pFEA, *pG, *pCG, *pUG;
    cudaGetSymbolAddress((void**)&xh, g_xh);   cudaGetSymbolAddress((void**)&xl, g_xl);
    cudaGetSymbolAddress((void**)&cxh, g_cxh); cudaGetSymbolAddress((void**)&cxl, g_cxl);
    cudaGetSymbolAddress((void**)&Hh, g_Hh);
    cudaGetSymbolAddress((void**)&W1h, g_W1h); cudaGetSymbolAddress((void**)&W2h, g_W2h);
    cudaGetSymbolAddress((void**)&CUh, g_CUh); cudaGetSymbolAddress((void**)&CW2h, g_CW2h);
    cudaGetSymbolAddress((void**)&tW1h, g_tW1h); cudaGetSymbolAddress((void**)&tW2h, g_tW2h);
    cudaGetSymbolAddress((void**)&cW1h, g_cW1h); cudaGetSymbolAddress((void**)&cW2h, g_cW2h);
    cudaGetSymbolAddress((void**)&tfh, g_tfh); cudaGetSymbolAddress((void**)&tfl, g_tfl);
    cudaGetSymbolAddress((void**)&th1h, g_th1h); cudaGetSymbolAddress((void**)&th1l, g_th1l);
    cudaGetSymbolAddress((void**)&cth, g_cth); cudaGetSymbolAddress((void**)&ctl, g_ctl);
    cudaGetSymbolAddress((void**)&ch1h, g_ch1h); cudaGetSymbolAddress((void**)&ch1l, g_ch1l);
    cudaGetSymbolAddress((void**)&pFEA, g_FEA);
    cudaGetSymbolAddress((void**)&pG, g_GATES);
    cudaGetSymbolAddress((void**)&pCG, g_CGATE);
    cudaGetSymbolAddress((void**)&pUG, g_UG);

    const int SM2 = 4 * 24576;
    const int SM1 = 4 * 16384;
    cudaFuncSetAttribute(hmma_t<1>, cudaFuncAttributeMaxDynamicSharedMemorySize, SM2);
    cudaFuncSetAttribute(hmma_t<0>, cudaFuncAttributeMaxDynamicSharedMemorySize, SM1);
    dim3 blk(256);
    dim3 tb(32, 8);

    // ---- weight prep ----
    transpose_h<<<dim3(NH1 / 32, DD / 32, NE), tb>>>(eW1, W1h, DD, NH1);
    transpose_h<<<dim3(NH2 / 32, NH1 / 32, NE), tb>>>(eW2, W2h, NH1, NH2);
    prep_cu<<<dim3(NH1 / 32, DD / 32, NE), tb>>>(ceW1, embW, embB, CUh);
    transpose_h<<<dim3(NH2 / 32, NH1 / 32, NE), tb>>>(ceW2, CW2h, NH1, NH2);
    transpose_h<<<dim3(TT1 / 32, NH2 / 32, 2), tb>>>(tW1, tW1h, NH2, TT1);
    transpose_h<<<dim3(TT2 / 32, TT1 / 32, 2), tb>>>(tW2, tW2h, TT1, TT2);
    transpose_h<<<dim3(TT1 / 32, NH2 / 32, 1), tb>>>(ctW1, cW1h, NH2, TT1);
    transpose_h<<<dim3(TT2 / 32, TT1 / 32, 1), tb>>>(ctW2, cW2h, TT1, TT2);
    prep_ug<<<(DD * 8 + 255) / 256, 256>>>(cgW, embW, embB, pUG);
    convert_split<<<NB * DD / 4 / 256, 256>>>(x, xh, xl, (size_t)NB * DD);

    // ---- phase 1: experts ----
    hmma_t<1><<<dim3(NH1 / 128, NB / 128, NE), blk, SM2>>>(
        xh, xl, W1h, eb1, nullptr, Hh, nullptr,
        NH1, DD, 15, DD, 0, (size_t)NH1 * DD, NH1, (size_t)NB * NH1, 2);
    hmma_t<0><<<dim3(NH2 / 128, NB / 128, NE), blk, SM1>>>(
        Hh, nullptr, W2h, eb2, pFEA, nullptr, nullptr,
        NH2, NH1, 31, NH1, (size_t)NB * NH1, (size_t)NH2 * NH1, NH2, (size_t)NB * NH2, 0);

    gates_kernel<<<NB * 2 / 8, 256>>>(x, gW, gb, pG);
    combine12<<<NB, 256>>>(pFEA, pG, out + O3, out + O4, tfh, tfl);

    // towers
    hmma_t<1><<<dim3(TT1 / 128, NB / 128, 2), blk, SM2>>>(
        tfh, tfl, tW1h, tb1, nullptr, th1h, th1l,
        TT1, NH2, 15, NH2, (size_t)NB * NH2, (size_t)TT1 * NH2, TT1, (size_t)NB * TT1, 1);
    hmma_t<1><<<dim3(1, NB / 128, 2), blk, SM2>>>(
        th1h, th1l, tW2h, tb2, out + O6, nullptr, nullptr,
        TT2, TT1, 7, TT1, (size_t)NB * TT1, (size_t)TT2 * TT1, TT2, (size_t)NB * TT2, 0);
    preds_kernel<<<NB * 2 / 8, 256>>>(out, pW, pb, out);

    // ---- phase 2: cascade (CE1 collapsed via affine-in-pctr identity) ----
    cx_kernel<<<NB, 256>>>(x, out, cxh, cxl);
    hmma_t<1><<<dim3(NH1 / 128, NB / 128, NE), blk, SM2>>>(
        cxh, cxl, CUh, ceb1, nullptr, Hh, nullptr,
        NH1, 1024, 31, 1024, 0, (size_t)NH1 * 1024, NH1, (size_t)NB * NH1, 2);
    hmma_t<0><<<dim3(NH2 / 128, NB / 128, NE), blk, SM1>>>(
        Hh, nullptr, CW2h, ceb2, pFEA, nullptr, nullptr,
        NH2, NH1, 31, NH1, (size_t)NB * NH1, (size_t)NH2 * NH1, NH2, (size_t)NB * NH2, 0);
    cgate_kernel<<<NB / 8, 256>>>(x, out, pUG, cgb, pCG);
    combine1c<<<NB, 256>>>(pFEA, pCG, out + O5, cth, ctl);

    hmma_t<1><<<dim3(TT1 / 128, NB / 128, 1), blk, SM2>>>(
        cth, ctl, cW1h, ctb1, nullptr, ch1h, ch1l,
        TT1, NH2, 15, NH2, 0, 0, 0, (size_t)NB * TT1, 1);
    hmma_t<1><<<dim3(1, NB / 128, 1), blk, SM2>>>(
        ch1h, ch1l, cW2h, ctb2, out + O8, nullptr, nullptr,
        TT2, TT1, 7, TT1, 0, 0, 0, 0, 0);
    pconv_kernel<<<NB / 8, 256>>>(out, cpW, cpb, out);
}

// round 6
// speedup vs baseline: 7.5995x; 1.2067x over previous
#include <cuda_runtime.h>
#include <cuda_fp16.h>
#include <math.h>

typedef unsigned long long ull;
typedef unsigned int u32;

#define NB   16384
#define DD   512
#define NE   8
#define NH1  1024
#define NH2  512
#define TT1  256
#define TT2  128
#define PEN  5
#define KAIT 2560   // D*PE

// ---- output layout ----
#define O0 ((size_t)0)
#define O1 ((size_t)NB)
#define O2 ((size_t)2*NB)
#define O3 ((size_t)3*NB)
#define O4 (O3 + (size_t)NB*512)
#define O5 (O4 + (size_t)NB*512)
#define O6 (O5 + (size_t)NB*512)
#define O7 (O6 + (size_t)NB*128)
#define O8 (O7 + (size_t)NB*128)

// ---- scratch ----
__device__ __half g_xh [(size_t)NB*DD];
__device__ __half g_xl [(size_t)NB*DD];
__device__ __half g_cxh[(size_t)NB*1024];   // [x | pctr*x] hi only
__device__ __half g_Hh [(size_t)NE*NB*NH1];
__device__ __half g_W1h[(size_t)NE*NH1*DD];
__device__ __half g_W2h[(size_t)NE*NH2*NH1];
__device__ __half g_CUh[(size_t)NE*NH1*1024];  // [U0;U1] per expert, [N][1024]
__device__ __half g_CW2h[(size_t)NE*NH2*NH1];
__device__ __half g_tW1h[(size_t)2*TT1*NH2];
__device__ __half g_tW2h[(size_t)2*TT2*TT1];
__device__ __half g_cW1h[(size_t)TT1*NH2];
__device__ __half g_cW2h[(size_t)TT2*TT1];
__device__ __half g_tfh[(size_t)2*NB*NH2];
__device__ __half g_tfl[(size_t)2*NB*NH2];
__device__ __half g_th1h[(size_t)2*NB*TT1];
__device__ __half g_th1l[(size_t)2*NB*TT1];
__device__ __half g_cth[(size_t)NB*NH2];
__device__ __half g_ctl[(size_t)NB*NH2];
__device__ __half g_ch1h[(size_t)NB*TT1];
__device__ __half g_ch1l[(size_t)NB*TT1];
__device__ float g_FEA [(size_t)NE*NB*NH2];
__device__ float g_GATES[(size_t)NB*2*8];
__device__ float g_CGATE[(size_t)NB*8];
__device__ float g_UG  [(size_t)2*DD*8];    // cgate u0/u1

// ================= helpers =================
__device__ __forceinline__ u32 smem_u32(const void* p) {
    u32 a;
    asm("{ .reg .u64 t; cvta.to.shared.u64 t, %1; cvt.u32.u64 %0, t; }" : "=r"(a) : "l"(p));
    return a;
}
__device__ __forceinline__ void cpa16(u32 dst, const void* src) {
    asm volatile("cp.async.cg.shared.global [%0], [%1], 16;" :: "r"(dst), "l"(src) : "memory");
}
#define CPA_COMMIT() asm volatile("cp.async.commit_group;" ::: "memory")
#define CPA_WAIT2()  asm volatile("cp.async.wait_group 2;" ::: "memory")

__device__ __forceinline__ void mma16816(float* c, const u32* a, const u32* b) {
    asm volatile(
        "mma.sync.aligned.m16n8k16.row.col.f32.f16.f16.f32 "
        "{%0,%1,%2,%3}, {%4,%5,%6,%7}, {%8,%9}, {%0,%1,%2,%3};"
        : "+f"(c[0]), "+f"(c[1]), "+f"(c[2]), "+f"(c[3])
        : "r"(a[0]), "r"(a[1]), "r"(a[2]), "r"(a[3]), "r"(b[0]), "r"(b[1]));
}

// swizzled smem offset (64B rows, 4x16B chunks)
__device__ __forceinline__ u32 swz(int row, int ch) {
    return (u32)(row * 64 + ((ch ^ ((row >> 1) & 3)) << 4));
}

__device__ __forceinline__ void ldA(u32 tb, int row0, int s, u32* a) {
    int lane = threadIdx.x & 31;
    int g = lane >> 3, li = lane & 7;
    int row = row0 + ((g & 1) << 3) + li;
    int ch = 2 * s + (g >> 1);
    u32 addr = tb + swz(row, ch);
    asm volatile("ldmatrix.sync.aligned.m8n8.x4.shared.b16 {%0,%1,%2,%3}, [%4];"
        : "=r"(a[0]), "=r"(a[1]), "=r"(a[2]), "=r"(a[3]) : "r"(addr));
}
__device__ __forceinline__ void ldB(u32 tb, int n0, int s, u32* r) {
    int lane = threadIdx.x & 31;
    int g = lane >> 3, li = lane & 7;
    int row = n0 + ((g >> 1) << 3) + li;
    int ch = 2 * s + (g & 1);
    u32 addr = tb + swz(row, ch);
    asm volatile("ldmatrix.sync.aligned.m8n8.x4.shared.b16 {%0,%1,%2,%3}, [%4];"
        : "=r"(r[0]), "=r"(r[1]), "=r"(r[2]), "=r"(r[3]) : "r"(addr));
}
__device__ __forceinline__ void split_hl(float v, __half& h, __half& l) {
    h = __float2half_rn(v);
    l = __float2half_rn(v - __half2float(h));
}

// ============================================================
// HMMA GEMM template, k=64 chunks (two 32-k sub-tiles per stage).
//   C[z] = relu(A[z] @ B[z]^T + bias[z])
// A [M, aK] fp16 (hi + optional lo); B [N, K] fp16 (pre-transposed).
// A k-col for 32-chunk c32 = (c32 & acolmask)*32.  K % 64 == 0.
// mode: 0 = fp32 C, 1 = fp16 hi/lo C, 2 = fp16 hi-only C.
// ============================================================
template<int TWOPASS>
__global__ void __launch_bounds__(256, 1) hmma_t(
    const __half* __restrict__ Ah, const __half* __restrict__ Al,
    const __half* __restrict__ Bh, const float* __restrict__ bias,
    float* __restrict__ Cf, __half* __restrict__ Ch, __half* __restrict__ Cl,
    int N, int K, int acolmask, int aK,
    size_t sA, size_t sB, size_t sBias, size_t sC, int mode)
{
    extern __shared__ char dsm[];
    const int SUB   = TWOPASS ? 24576 : 16384;
    const int STAGE = 2 * SUB;
    const int NSLOT = TWOPASS ? 6 : 4;
    const int tid = threadIdx.x;
    const int wid = tid >> 5;
    const int lane = tid & 31;
    const int z = blockIdx.z;
    const int bm = blockIdx.y << 7;
    const int bn = blockIdx.x << 7;

    Ah += (size_t)z * sA;
    if (TWOPASS) Al += (size_t)z * sA;
    Bh += (size_t)z * sB;  bias += (size_t)z * sBias;

    const u32 sbase = smem_u32(dsm);

    u32 soff[NSLOT];
    const __half* gsrc[NSLOT];
    u32 amask[NSLOT];
    #pragma unroll
    for (int j = 0; j < NSLOT; j++) {
        int sid = tid + (j << 8);
        int buf = sid >> 9;
        int rem = sid & 511;
        int r = rem >> 2;
        int ch = rem & 3;
        soff[j] = (u32)(buf * 8192) + swz(r, ch);
        bool isA = TWOPASS ? (buf < 2) : (buf == 0);
        const __half* base = isA ? ((TWOPASS && buf == 1) ? Al : Ah) : Bh;
        int grow = (isA ? bm : bn) + r;
        gsrc[j] = base + (size_t)grow * (isA ? aK : K) + ch * 8;
        amask[j] = isA ? (u32)acolmask : 0xFFFFFFFFu;
    }

    const int nch = K >> 6;   // 64-k chunks

    #pragma unroll
    for (int p = 0; p < 3; p++) {
        if (p < nch) {
            u32 sb = sbase + (u32)p * STAGE;
            #pragma unroll
            for (int sc = 0; sc < 2; sc++)
                #pragma unroll
                for (int j = 0; j < NSLOT; j++)
                    cpa16(sb + (u32)sc * SUB + soff[j],
                          gsrc[j] + (((u32)(2 * p + sc) & amask[j]) << 5));
        }
        CPA_COMMIT();
    }

    const int wm = (wid & 3) << 5;
    const int wn = (wid >> 2) << 6;
    const u32 Boff = TWOPASS ? 16384u : 8192u;

    float acc[2][8][4];
    #pragma unroll
    for (int i = 0; i < 2; i++)
        #pragma unroll
        for (int j = 0; j < 8; j++)
            #pragma unroll
            for (int q = 0; q < 4; q++) acc[i][j][q] = 0.f;

    for (int i = 0; i < nch; i++) {
        CPA_WAIT2();
        __syncthreads();
        int pf = i + 3;
        if (pf < nch) {
            u32 sb = sbase + (u32)(pf & 3) * STAGE;
            #pragma unroll
            for (int sc = 0; sc < 2; sc++)
                #pragma unroll
                for (int j = 0; j < NSLOT; j++)
                    cpa16(sb + (u32)sc * SUB + soff[j],
                          gsrc[j] + (((u32)(2 * pf + sc) & amask[j]) << 5));
        }
        CPA_COMMIT();

        #pragma unroll
        for (int sc = 0; sc < 2; sc++) {
            u32 stb = sbase + (u32)(i & 3) * STAGE + (u32)sc * SUB;
            #pragma unroll
            for (int s = 0; s < 2; s++) {
                u32 ah[2][4], b[8][2];
                ldA(stb, wm,      s, ah[0]);
                ldA(stb, wm + 16, s, ah[1]);
                #pragma unroll
                for (int j4 = 0; j4 < 4; j4++) {
                    u32 r[4];
                    ldB(stb + Boff, wn + j4 * 16, s, r);
                    b[2 * j4][0] = r[0]; b[2 * j4][1] = r[1];
                    b[2 * j4 + 1][0] = r[2]; b[2 * j4 + 1][1] = r[3];
                }
                #pragma unroll
                for (int i2 = 0; i2 < 2; i2++)
                    #pragma unroll
                    for (int j8 = 0; j8 < 8; j8++) mma16816(acc[i2][j8], ah[i2], b[j8]);
                if (TWOPASS) {
                    u32 al[2][4];
                    ldA(stb + 8192, wm,      s, al[0]);
                    ldA(stb + 8192, wm + 16, s, al[1]);
                    #pragma unroll
                    for (int i2 = 0; i2 < 2; i2++)
                        #pragma unroll
                        for (int j8 = 0; j8 < 8; j8++) mma16816(acc[i2][j8], al[i2], b[j8]);
                }
            }
        }
    }

    // epilogue
    const int r0b = bm + wm + (lane >> 2);
    const int c0b = bn + wn + ((lane & 3) << 1);
    #pragma unroll
    for (int i2 = 0; i2 < 2; i2++) {
        #pragma unroll
        for (int j8 = 0; j8 < 8; j8++) {
            int col = c0b + j8 * 8;
            float b0 = bias[col], b1 = bias[col + 1];
            #pragma unroll
            for (int h = 0; h < 2; h++) {
                int row = r0b + i2 * 16 + h * 8;
                float v0 = fmaxf(acc[i2][j8][2 * h]     + b0, 0.f);
                float v1 = fmaxf(acc[i2][j8][2 * h + 1] + b1, 0.f);
                if (mode == 0) {
                    *(float2*)(Cf + (size_t)z * sC + (size_t)row * N + col) = make_float2(v0, v1);
                } else {
                    __half h0, l0, h1, l1;
                    split_hl(v0, h0, l0);
                    split_hl(v1, h1, l1);
                    __half2 hp; hp.x = h0; hp.y = h1;
                    *(__half2*)(Ch + (size_t)z * sC + (size_t)row * N + col) = hp;
                    if (mode == 1) {
                        __half2 lp; lp.x = l0; lp.y = l1;
                        *(__half2*)(Cl + (size_t)z * sC + (size_t)row * N + col) = lp;
                    }
                }
            }
        }
    }
}

// ============================================================
// weight transpose: W[z][K][N] f32 -> T[z][N][K] fp16
// ============================================================
__global__ void transpose_h(const float* __restrict__ W, __half* __restrict__ Th,
                            int Kd, int Nd)
{
    __shared__ float t[32][33];
    int z = blockIdx.z;
    const float* Wz = W + (size_t)z * Kd * Nd;
    int n0 = blockIdx.x << 5, k0 = blockIdx.y << 5;
    for (int r = threadIdx.y; r < 32; r += 8)
        t[r][threadIdx.x] = Wz[(size_t)(k0 + r) * Nd + n0 + threadIdx.x];
    __syncthreads();
    size_t ob = (size_t)z * Nd * Kd;
    for (int r = threadIdx.y; r < 32; r += 8)
        Th[ob + (size_t)(n0 + r) * Kd + k0 + threadIdx.x] = __float2half_rn(t[threadIdx.x][r]);
}

// CE1 collapse: ceW1[z][d*5+p][n] f32 -> CU[z][n][d] = sum_p embB_p*W,
//                                        CU[z][n][512+d] = sum_p embW_p*W
__global__ void prep_cu(const float* __restrict__ W, const float* __restrict__ embW,
                        const float* __restrict__ embB, __half* __restrict__ CU)
{
    __shared__ float t0[32][33], t1[32][33];
    int z = blockIdx.z;
    int n0 = blockIdx.x << 5, d0 = blockIdx.y << 5;
    const float* Wz = W + (size_t)z * KAIT * NH1;
    float ew[PEN], eb[PEN];
    #pragma unroll
    for (int p = 0; p < PEN; p++) { ew[p] = embW[p]; eb[p] = embB[p]; }
    for (int r = threadIdx.y; r < 32; r += 8) {
        float s0 = 0.f, s1 = 0.f;
        #pragma unroll
        for (int p = 0; p < PEN; p++) {
            float w = Wz[(size_t)((d0 + r) * PEN + p) * NH1 + n0 + threadIdx.x];
            s0 += eb[p] * w;
            s1 += ew[p] * w;
        }
        t0[r][threadIdx.x] = s0;
        t1[r][threadIdx.x] = s1;
    }
    __syncthreads();
    size_t ob = (size_t)z * NH1 * 1024;
    for (int r = threadIdx.y; r < 32; r += 8) {
        CU[ob + (size_t)(n0 + r) * 1024 + d0 + threadIdx.x] =
            __float2half_rn(t0[threadIdx.x][r]);
        CU[ob + (size_t)(n0 + r) * 1024 + 512 + d0 + threadIdx.x] =
            __float2half_rn(t1[threadIdx.x][r]);
    }
}

// cgate collapse: u0[d][e] = sum_p embB_p*cgW[d*5+p][e]; u1 likewise with embW
__global__ void prep_ug(const float* __restrict__ cgW, const float* __restrict__ embW,
                        const float* __restrict__ embB, float* __restrict__ u)
{
    int i = blockIdx.x * blockDim.x + threadIdx.x;
    if (i >= DD * 8) return;
    int d = i >> 3, e = i & 7;
    float s0 = 0.f, s1 = 0.f;
    #pragma unroll
    for (int p = 0; p < PEN; p++) {
        float w = cgW[(size_t)(d * PEN + p) * 8 + e];
        s0 += embB[p] * w;
        s1 += embW[p] * w;
    }
    u[i] = s0;
    u[DD * 8 + i] = s1;
}

// elementwise fp32 -> fp16 hi/lo
__global__ void convert_split(const float* __restrict__ src,
                              __half* __restrict__ hi, __half* __restrict__ lo, size_t n)
{
    size_t i = ((size_t)blockIdx.x * blockDim.x + threadIdx.x) * 4;
    if (i >= n) return;
    float4 v = *(const float4*)(src + i);
    __half h0, l0, h1, l1, h2, l2, h3, l3;
    split_hl(v.x, h0, l0); split_hl(v.y, h1, l1);
    split_hl(v.z, h2, l2); split_hl(v.w, h3, l3);
    __half2 a, b, c, d;
    a.x = h0; a.y = h1; b.x = h2; b.y = h3;
    c.x = l0; c.y = l1; d.x = l2; d.y = l3;
    *(__half2*)(hi + i) = a; *(__half2*)(hi + i + 2) = b;
    *(__half2*)(lo + i) = c; *(__half2*)(lo + i + 2) = d;
}

// cx[b] = [x[b] | pctr[b]*x[b]] fp16 hi only (CE1 A operand)
__global__ void cx_kernel(const float* __restrict__ x, const float* __restrict__ out,
                          __half* __restrict__ cxh)
{
    int b = blockIdx.x;
    float pc = out[b];
    const float* xr = x + (size_t)b * DD;
    size_t ob = (size_t)b * 1024;
    for (int d = threadIdx.x; d < DD; d += blockDim.x) {
        float v = xr[d];
        cxh[ob + d] = __float2half_rn(v);
        cxh[ob + 512 + d] = __float2half_rn(pc * v);
    }
}

// ================= small fp32 kernels =================
__global__ void gates_kernel(const float* __restrict__ x, const float* __restrict__ gW,
                             const float* __restrict__ gb, float* __restrict__ gates)
{
    int gw = (blockIdx.x * blockDim.x + threadIdx.x) >> 5;
    int lane = threadIdx.x & 31;
    if (gw >= NB * 2) return;
    int b = gw >> 1, t = gw & 1;
    const float* xr = x + (size_t)b * DD;
    float acc[8] = {};
    for (int d = lane; d < DD; d += 32) {
        float xv = xr[d];
        const float* g = gW + ((size_t)t * DD + d) * NE;
        float4 w0 = *(const float4*)g;
        float4 w1 = *(const float4*)(g + 4);
        acc[0] += xv * w0.x; acc[1] += xv * w0.y; acc[2] += xv * w0.z; acc[3] += xv * w0.w;
        acc[4] += xv * w1.x; acc[5] += xv * w1.y; acc[6] += xv * w1.z; acc[7] += xv * w1.w;
    }
    #pragma unroll
    for (int e = 0; e < 8; e++)
        #pragma unroll
        for (int o = 16; o; o >>= 1) acc[e] += __shfl_xor_sync(0xffffffffu, acc[e], o);
    float m = -1e30f;
    #pragma unroll
    for (int e = 0; e < 8; e++) { acc[e] += gb[t * 8 + e]; m = fmaxf(m, acc[e]); }
    float s = 0.f;
    #pragma unroll
    for (int e = 0; e < 8; e++) { acc[e] = expf(acc[e] - m); s += acc[e]; }
    float inv = 1.f / s;
    if (lane < 8) gates[((size_t)b * 2 + t) * 8 + lane] = acc[lane] * inv;
}

// fused combine for both tasks + fp16 split of task_fea (tower input)
__global__ void combine12(const float* __restrict__ fea, const float* __restrict__ gates,
                          float* __restrict__ o3, float* __restrict__ o4,
                          __half* __restrict__ tfh, __half* __restrict__ tfl)
{
    int b = blockIdx.x;
    __shared__ float g[16];
    if (threadIdx.x < 16) g[threadIdx.x] = gates[(size_t)b * 16 + threadIdx.x];
    __syncthreads();
    const float* f = fea + (size_t)b * NH2;
    for (int h = threadIdx.x; h < NH2; h += blockDim.x) {
        float s0 = 0.f, s1 = 0.f;
        #pragma unroll
        for (int e = 0; e < 8; e++) {
            float v = f[(size_t)e * NB * NH2 + h];
            s0 += g[e] * v;
            s1 += g[8 + e] * v;
        }
        o3[(size_t)b * NH2 + h] = s0;
        o4[(size_t)b * NH2 + h] = s1;
        __half hh, ll;
        split_hl(s0, hh, ll);
        tfh[(size_t)b * NH2 + h] = hh;
        tfl[(size_t)b * NH2 + h] = ll;
        split_hl(s1, hh, ll);
        tfh[(size_t)(NB + b) * NH2 + h] = hh;
        tfl[(size_t)(NB + b) * NH2 + h] = ll;
    }
}

// phase-2 combine: ctask -> O5 + fp16 split for cascade tower
__global__ void combine1c(const float* __restrict__ fea, const float* __restrict__ cg,
                          float* __restrict__ o5, __half* __restrict__ cth,
                          __half* __restrict__ ctl)
{
    int b = blockIdx.x;
    __shared__ float g[8];
    if (threadIdx.x < 8) g[threadIdx.x] = cg[(size_t)b * 8 + threadIdx.x];
    __syncthreads();
    const float* f = fea + (size_t)b * NH2;
    for (int h = threadIdx.x; h < NH2; h += blockDim.x) {
        float s = 0.f;
        #pragma unroll
        for (int e = 0; e < 8; e++) s += g[e] * f[(size_t)e * NB * NH2 + h];
        o5[(size_t)b * NH2 + h] = s;
        __half hh, ll;
        split_hl(s, hh, ll);
        cth[(size_t)b * NH2 + h] = hh;
        ctl[(size_t)b * NH2 + h] = ll;
    }
}

__global__ void preds_kernel(const float* __restrict__ outr, const float* __restrict__ pW,
                             const float* __restrict__ pb, float* __restrict__ out)
{
    int gw = (blockIdx.x * blockDim.x + threadIdx.x) >> 5;
    int lane = threadIdx.x & 31;
    if (gw >= NB * 2) return;
    int b = gw >> 1, t = gw & 1;
    const float* th2 = outr + O6 + (size_t)t * NB * TT2 + (size_t)b * TT2;
    const float* w = pW + t * TT2;
    float s = 0.f;
    for (int m = lane; m < TT2; m += 32) s += th2[m] * w[m];
    #pragma unroll
    for (int o = 16; o; o >>= 1) s += __shfl_xor_sync(0xffffffffu, s, o);
    if (lane == 0) {
        s += pb[t];
        out[(size_t)t * NB + b] = 1.f / (1.f + expf(-s));
    }
}

// cgate via collapsed u: logits_e = x.u0[:,e] + pctr*(x.u1[:,e]) + cgb
__global__ void cgate_kernel(const float* __restrict__ x, const float* __restrict__ out,
                             const float* __restrict__ u, const float* __restrict__ cgb,
                             float* __restrict__ cg)
{
    int gw = (blockIdx.x * blockDim.x + threadIdx.x) >> 5;
    int lane = threadIdx.x & 31;
    if (gw >= NB) return;
    const float* xr = x + (size_t)gw * DD;
    float a0[8] = {}, a1[8] = {};
    for (int d = lane; d < DD; d += 32) {
        float xv = xr[d];
        const float* u0 = u + (size_t)d * 8;
        const float* u1 = u + (size_t)(DD + d) * 8;
        float4 w0 = *(const float4*)u0;
        float4 w1 = *(const float4*)(u0 + 4);
        a0[0] += xv * w0.x; a0[1] += xv * w0.y; a0[2] += xv * w0.z; a0[3] += xv * w0.w;
        a0[4] += xv * w1.x; a0[5] += xv * w1.y; a0[6] += xv * w1.z; a0[7] += xv * w1.w;
        float4 v0 = *(const float4*)u1;
        float4 v1 = *(const float4*)(u1 + 4);
        a1[0] += xv * v0.x; a1[1] += xv * v0.y; a1[2] += xv * v0.z; a1[3] += xv * v0.w;
        a1[4] += xv * v1.x; a1[5] += xv * v1.y; a1[6] += xv * v1.z; a1[7] += xv * v1.w;
    }
    #pragma unroll
    for (int e = 0; e < 8; e++) {
        #pragma unroll
        for (int o = 16; o; o >>= 1) {
            a0[e] += __shfl_xor_sync(0xffffffffu, a0[e], o);
            a1[e] += __shfl_xor_sync(0xffffffffu, a1[e], o);
        }
    }
    float pc = out[gw];
    float m = -1e30f;
    float acc[8];
    #pragma unroll
    for (int e = 0; e < 8; e++) {
        acc[e] = a0[e] + pc * a1[e] + cgb[e];
        m = fmaxf(m, acc[e]);
    }
    float s = 0.f;
    #pragma unroll
    for (int e = 0; e < 8; e++) { acc[e] = expf(acc[e] - m); s += acc[e]; }
    float inv = 1.f / s;
    if (lane < 8) cg[(size_t)gw * 8 + lane] = acc[lane] * inv;
}

__global__ void pconv_kernel(const float* __restrict__ outr, const float* __restrict__ cpW,
                             const float* __restrict__ cpb, float* __restrict__ out)
{
    int gw = (blockIdx.x * blockDim.x + threadIdx.x) >> 5;
    int lane = threadIdx.x & 31;
    if (gw >= NB) return;
    const float* ch2 = outr + O8 + (size_t)gw * TT2;
    float s = 0.f;
    for (int m = lane; m < TT2; m += 32) s += ch2[m] * cpW[m];
    #pragma unroll
    for (int o = 16; o; o >>= 1) s += __shfl_xor_sync(0xffffffffu, s, o);
    if (lane == 0) out[O2 + gw] = 1.f / (1.f + expf(-(s + cpb[0])));
}

// ============================================================
extern "C" void kernel_launch(void* const* d_in, const int* in_sizes, int n_in,
                              void* d_out, int out_size)
{
    const float* x    = (const float*)d_in[0];
    const float* eW1  = (const float*)d_in[1];
    const float* eb1  = (const float*)d_in[2];
    const float* eW2  = (const float*)d_in[3];
    const float* eb2  = (const float*)d_in[4];
    const float* gW   = (const float*)d_in[5];
    const float* gb   = (const float*)d_in[6];
    const float* tW1  = (const float*)d_in[7];
    const float* tb1  = (const float*)d_in[8];
    const float* tW2  = (const float*)d_in[9];
    const float* tb2  = (const float*)d_in[10];
    const float* pW   = (const float*)d_in[11];
    const float* pb   = (const float*)d_in[12];
    const float* embW = (const float*)d_in[13];
    const float* embB = (const float*)d_in[14];
    const float* ceW1 = (const float*)d_in[15];
    const float* ceb1 = (const float*)d_in[16];
    const float* ceW2 = (const float*)d_in[17];
    const float* ceb2 = (const float*)d_in[18];
    const float* cgW  = (const float*)d_in[19];
    const float* cgb  = (const float*)d_in[20];
    const float* ctW1 = (const float*)d_in[21];
    const float* ctb1 = (const float*)d_in[22];
    const float* ctW2 = (const float*)d_in[23];
    const float* ctb2 = (const float*)d_in[24];
    const float* cpW  = (const float*)d_in[25];
    const float* cpb  = (const float*)d_in[26];
    float* out = (float*)d_out;

    __half *xh, *xl, *cxh, *Hh, *W1h, *W2h, *CUh, *CW2h, *tW1h, *tW2h, *cW1h, *cW2h;
    __half *tfh, *tfl, *th1h, *th1l, *cth, *ctl, *ch1h, *ch1l;
    float *pFEA, *pG, *pCG, *pUG;
    cudaGetSymbolAddress((void**)&xh, g_xh);   cudaGetSymbolAddress((void**)&xl, g_xl);
    cudaGetSymbolAddress((void**)&cxh, g_cxh);
    cudaGetSymbolAddress((void**)&Hh, g_Hh);
    cudaGetSymbolAddress((void**)&W1h, g_W1h); cudaGetSymbolAddress((void**)&W2h, g_W2h);
    cudaGetSymbolAddress((void**)&CUh, g_CUh); cudaGetSymbolAddress((void**)&CW2h, g_CW2h);
    cudaGetSymbolAddress((void**)&tW1h, g_tW1h); cudaGetSymbolAddress((void**)&tW2h, g_tW2h);
    cudaGetSymbolAddress((void**)&cW1h, g_cW1h); cudaGetSymbolAddress((void**)&cW2h, g_cW2h);
    cudaGetSymbolAddress((void**)&tfh, g_tfh); cudaGetSymbolAddress((void**)&tfl, g_tfl);
    cudaGetSymbolAddress((void**)&th1h, g_th1h); cudaGetSymbolAddress((void**)&th1l, g_th1l);
    cudaGetSymbolAddress((void**)&cth, g_cth); cudaGetSymbolAddress((void**)&ctl, g_ctl);
    cudaGetSymbolAddress((void**)&ch1h, g_ch1h); cudaGetSymbolAddress((void**)&ch1l, g_ch1l);
    cudaGetSymbolAddress((void**)&pFEA, g_FEA);
    cudaGetSymbolAddress((void**)&pG, g_GATES);
    cudaGetSymbolAddress((void**)&pCG, g_CGATE);
    cudaGetSymbolAddress((void**)&pUG, g_UG);

    const int SM2 = 4 * 2 * 24576;   // 196608
    const int SM1 = 4 * 2 * 16384;   // 131072
    cudaFuncSetAttribute(hmma_t<1>, cudaFuncAttributeMaxDynamicSharedMemorySize, SM2);
    cudaFuncSetAttribute(hmma_t<0>, cudaFuncAttributeMaxDynamicSharedMemorySize, SM1);
    dim3 blk(256);
    dim3 tb(32, 8);

    // ---- weight prep ----
    transpose_h<<<dim3(NH1 / 32, DD / 32, NE), tb>>>(eW1, W1h, DD, NH1);
    transpose_h<<<dim3(NH2 / 32, NH1 / 32, NE), tb>>>(eW2, W2h, NH1, NH2);
    prep_cu<<<dim3(NH1 / 32, DD / 32, NE), tb>>>(ceW1, embW, embB, CUh);
    transpose_h<<<dim3(NH2 / 32, NH1 / 32, NE), tb>>>(ceW2, CW2h, NH1, NH2);
    transpose_h<<<dim3(TT1 / 32, NH2 / 32, 2), tb>>>(tW1, tW1h, NH2, TT1);
    transpose_h<<<dim3(TT2 / 32, TT1 / 32, 2), tb>>>(tW2, tW2h, TT1, TT2);
    transpose_h<<<dim3(TT1 / 32, NH2 / 32, 1), tb>>>(ctW1, cW1h, NH2, TT1);
    transpose_h<<<dim3(TT2 / 32, TT1 / 32, 1), tb>>>(ctW2, cW2h, TT1, TT2);
    prep_ug<<<(DD * 8 + 255) / 256, 256>>>(cgW, embW, embB, pUG);
    convert_split<<<NB * DD / 4 / 256, 256>>>(x, xh, xl, (size_t)NB * DD);

    // ---- phase 1: experts ----
    hmma_t<1><<<dim3(NH1 / 128, NB / 128, NE), blk, SM2>>>(
        xh, xl, W1h, eb1, nullptr, Hh, nullptr,
        NH1, DD, 15, DD, 0, (size_t)NH1 * DD, NH1, (size_t)NB * NH1, 2);
    hmma_t<0><<<dim3(NH2 / 128, NB / 128, NE), blk, SM1>>>(
        Hh, nullptr, W2h, eb2, pFEA, nullptr, nullptr,
        NH2, NH1, 31, NH1, (size_t)NB * NH1, (size_t)NH2 * NH1, NH2, (size_t)NB * NH2, 0);

    gates_kernel<<<NB * 2 / 8, 256>>>(x, gW, gb, pG);
    combine12<<<NB, 256>>>(pFEA, pG, out + O3, out + O4, tfh, tfl);

    // towers
    hmma_t<1><<<dim3(TT1 / 128, NB / 128, 2), blk, SM2>>>(
        tfh, tfl, tW1h, tb1, nullptr, th1h, th1l,
        TT1, NH2, 15, NH2, (size_t)NB * NH2, (size_t)TT1 * NH2, TT1, (size_t)NB * TT1, 1);
    hmma_t<1><<<dim3(1, NB / 128, 2), blk, SM2>>>(
        th1h, th1l, tW2h, tb2, out + O6, nullptr, nullptr,
        TT2, TT1, 7, TT1, (size_t)NB * TT1, (size_t)TT2 * TT1, TT2, (size_t)NB * TT2, 0);
    preds_kernel<<<NB * 2 / 8, 256>>>(out, pW, pb, out);

    // ---- phase 2: cascade (CE1 collapsed, one-pass) ----
    cx_kernel<<<NB, 256>>>(x, out, cxh);
    hmma_t<0><<<dim3(NH1 / 128, NB / 128, NE), blk, SM1>>>(
        cxh, nullptr, CUh, ceb1, nullptr, Hh, nullptr,
        NH1, 1024, 31, 1024, 0, (size_t)NH1 * 1024, NH1, (size_t)NB * NH1, 2);
    hmma_t<0><<<dim3(NH2 / 128, NB / 128, NE), blk, SM1>>>(
        Hh, nullptr, CW2h, ceb2, pFEA, nullptr, nullptr,
        NH2, NH1, 31, NH1, (size_t)NB * NH1, (size_t)NH2 * NH1, NH2, (size_t)NB * NH2, 0);
    cgate_kernel<<<NB / 8, 256>>>(x, out, pUG, cgb, pCG);
    combine1c<<<NB, 256>>>(pFEA, pCG, out + O5, cth, ctl);

    hmma_t<1><<<dim3(TT1 / 128, NB / 128, 1), blk, SM2>>>(
        cth, ctl, cW1h, ctb1, nullptr, ch1h, ch1l,
        TT1, NH2, 15, NH2, 0, 0, 0, (size_t)NB * TT1, 1);
    hmma_t<1><<<dim3(1, NB / 128, 1), blk, SM2>>>(
        ch1h, ch1l, cW2h, ctb2, out + O8, nullptr, nullptr,
        TT2, TT1, 7, TT1, 0, 0, 0, 0, 0);
    pconv_kernel<<<NB / 8, 256>>>(out, cpW, cpb, out);
}

// round 7
// speedup vs baseline: 8.3880x; 1.1038x over previous
#include <cuda_runtime.h>
#include <cuda_fp16.h>
#include <math.h>

typedef unsigned long long ull;
typedef unsigned int u32;

#define NB   16384
#define DD   512
#define NE   8
#define NH1  1024
#define NH2  512
#define TT1  256
#define TT2  128
#define PEN  5
#define KAIT 2560   // D*PE

// ---- output layout ----
#define O0 ((size_t)0)
#define O1 ((size_t)NB)
#define O2 ((size_t)2*NB)
#define O3 ((size_t)3*NB)
#define O4 (O3 + (size_t)NB*512)
#define O5 (O4 + (size_t)NB*512)
#define O6 (O5 + (size_t)NB*512)
#define O7 (O6 + (size_t)NB*128)
#define O8 (O7 + (size_t)NB*128)

// ---- scratch ----
__device__ __half g_xh [(size_t)NB*DD];
__device__ __half g_cxh[(size_t)NB*1024];   // [x | pctr*x] hi only
__device__ __half g_Hh [(size_t)NE*NB*NH1];
__device__ __half g_W1h[(size_t)NE*NH1*DD];
__device__ __half g_W2h[(size_t)NE*NH2*NH1];
__device__ __half g_CUh[(size_t)NE*NH1*1024];  // [U0;U1] per expert, [N][1024]
__device__ __half g_CW2h[(size_t)NE*NH2*NH1];
__device__ __half g_tW1h[(size_t)2*TT1*NH2];
__device__ __half g_tW2h[(size_t)2*TT2*TT1];
__device__ __half g_cW1h[(size_t)TT1*NH2];
__device__ __half g_cW2h[(size_t)TT2*TT1];
__device__ __half g_tfh[(size_t)2*NB*NH2];
__device__ __half g_tfl[(size_t)2*NB*NH2];
__device__ __half g_th1h[(size_t)2*NB*TT1];
__device__ __half g_th1l[(size_t)2*NB*TT1];
__device__ __half g_cth[(size_t)NB*NH2];
__device__ __half g_ctl[(size_t)NB*NH2];
__device__ __half g_ch1h[(size_t)NB*TT1];
__device__ __half g_ch1l[(size_t)NB*TT1];
__device__ float g_FEA [(size_t)NE*NB*NH2];
__device__ float g_GATES[(size_t)NB*2*8];
__device__ float g_CGATE[(size_t)NB*8];
__device__ float g_UG  [(size_t)2*DD*8];    // cgate u0/u1

// ================= helpers =================
__device__ __forceinline__ u32 smem_u32(const void* p) {
    u32 a;
    asm("{ .reg .u64 t; cvta.to.shared.u64 t, %1; cvt.u32.u64 %0, t; }" : "=r"(a) : "l"(p));
    return a;
}
__device__ __forceinline__ void cpa16(u32 dst, const void* src) {
    asm volatile("cp.async.cg.shared.global [%0], [%1], 16;" :: "r"(dst), "l"(src) : "memory");
}
#define CPA_COMMIT() asm volatile("cp.async.commit_group;" ::: "memory")
#define CPA_WAIT2()  asm volatile("cp.async.wait_group 2;" ::: "memory")

__device__ __forceinline__ void mma16816(float* c, const u32* a, const u32* b) {
    asm volatile(
        "mma.sync.aligned.m16n8k16.row.col.f32.f16.f16.f32 "
        "{%0,%1,%2,%3}, {%4,%5,%6,%7}, {%8,%9}, {%0,%1,%2,%3};"
        : "+f"(c[0]), "+f"(c[1]), "+f"(c[2]), "+f"(c[3])
        : "r"(a[0]), "r"(a[1]), "r"(a[2]), "r"(a[3]), "r"(b[0]), "r"(b[1]));
}

// swizzled smem offset (64B rows, 4x16B chunks)
__device__ __forceinline__ u32 swz(int row, int ch) {
    return (u32)(row * 64 + ((ch ^ ((row >> 1) & 3)) << 4));
}

__device__ __forceinline__ void ldA(u32 tb, int row0, int s, u32* a) {
    int lane = threadIdx.x & 31;
    int g = lane >> 3, li = lane & 7;
    int row = row0 + ((g & 1) << 3) + li;
    int ch = 2 * s + (g >> 1);
    u32 addr = tb + swz(row, ch);
    asm volatile("ldmatrix.sync.aligned.m8n8.x4.shared.b16 {%0,%1,%2,%3}, [%4];"
        : "=r"(a[0]), "=r"(a[1]), "=r"(a[2]), "=r"(a[3]) : "r"(addr));
}
__device__ __forceinline__ void ldB(u32 tb, int n0, int s, u32* r) {
    int lane = threadIdx.x & 31;
    int g = lane >> 3, li = lane & 7;
    int row = n0 + ((g >> 1) << 3) + li;
    int ch = 2 * s + (g & 1);
    u32 addr = tb + swz(row, ch);
    asm volatile("ldmatrix.sync.aligned.m8n8.x4.shared.b16 {%0,%1,%2,%3}, [%4];"
        : "=r"(r[0]), "=r"(r[1]), "=r"(r[2]), "=r"(r[3]) : "r"(addr));
}
__device__ __forceinline__ void split_hl(float v, __half& h, __half& l) {
    h = __float2half_rn(v);
    l = __float2half_rn(v - __half2float(h));
}

// ============================================================
// HMMA GEMM template, k=64 chunks (two 32-k sub-tiles per stage).
//   C[z] = relu(A[z] @ B[z]^T + bias[z])
// A [M, aK] fp16 (hi + optional lo); B [N, K] fp16 (pre-transposed).
// A k-col for 32-chunk c32 = (c32 & acolmask)*32.  K % 64 == 0.
// mode: 0 = fp32 C, 1 = fp16 hi/lo C, 2 = fp16 hi-only C.
// ============================================================
template<int TWOPASS>
__global__ void __launch_bounds__(256, 1) hmma_t(
    const __half* __restrict__ Ah, const __half* __restrict__ Al,
    const __half* __restrict__ Bh, const float* __restrict__ bias,
    float* __restrict__ Cf, __half* __restrict__ Ch, __half* __restrict__ Cl,
    int N, int K, int acolmask, int aK,
    size_t sA, size_t sB, size_t sBias, size_t sC, int mode)
{
    extern __shared__ char dsm[];
    const int SUB   = TWOPASS ? 24576 : 16384;
    const int STAGE = 2 * SUB;
    const int NSLOT = TWOPASS ? 6 : 4;
    const int tid = threadIdx.x;
    const int wid = tid >> 5;
    const int lane = tid & 31;
    const int z = blockIdx.z;
    const int bm = blockIdx.y << 7;
    const int bn = blockIdx.x << 7;

    Ah += (size_t)z * sA;
    if (TWOPASS) Al += (size_t)z * sA;
    Bh += (size_t)z * sB;  bias += (size_t)z * sBias;

    const u32 sbase = smem_u32(dsm);

    u32 soff[NSLOT];
    const __half* gsrc[NSLOT];
    u32 amask[NSLOT];
    #pragma unroll
    for (int j = 0; j < NSLOT; j++) {
        int sid = tid + (j << 8);
        int buf = sid >> 9;
        int rem = sid & 511;
        int r = rem >> 2;
        int ch = rem & 3;
        soff[j] = (u32)(buf * 8192) + swz(r, ch);
        bool isA = TWOPASS ? (buf < 2) : (buf == 0);
        const __half* base = isA ? ((TWOPASS && buf == 1) ? Al : Ah) : Bh;
        int grow = (isA ? bm : bn) + r;
        gsrc[j] = base + (size_t)grow * (isA ? aK : K) + ch * 8;
        amask[j] = isA ? (u32)acolmask : 0xFFFFFFFFu;
    }

    const int nch = K >> 6;   // 64-k chunks

    #pragma unroll
    for (int p = 0; p < 3; p++) {
        if (p < nch) {
            u32 sb = sbase + (u32)p * STAGE;
            #pragma unroll
            for (int sc = 0; sc < 2; sc++)
                #pragma unroll
                for (int j = 0; j < NSLOT; j++)
                    cpa16(sb + (u32)sc * SUB + soff[j],
                          gsrc[j] + (((u32)(2 * p + sc) & amask[j]) << 5));
        }
        CPA_COMMIT();
    }

    const int wm = (wid & 3) << 5;
    const int wn = (wid >> 2) << 6;
    const u32 Boff = TWOPASS ? 16384u : 8192u;

    float acc[2][8][4];
    #pragma unroll
    for (int i = 0; i < 2; i++)
        #pragma unroll
        for (int j = 0; j < 8; j++)
            #pragma unroll
            for (int q = 0; q < 4; q++) acc[i][j][q] = 0.f;

    for (int i = 0; i < nch; i++) {
        CPA_WAIT2();
        __syncthreads();
        int pf = i + 3;
        if (pf < nch) {
            u32 sb = sbase + (u32)(pf & 3) * STAGE;
            #pragma unroll
            for (int sc = 0; sc < 2; sc++)
                #pragma unroll
                for (int j = 0; j < NSLOT; j++)
                    cpa16(sb + (u32)sc * SUB + soff[j],
                          gsrc[j] + (((u32)(2 * pf + sc) & amask[j]) << 5));
        }
        CPA_COMMIT();

        #pragma unroll
        for (int sc = 0; sc < 2; sc++) {
            u32 stb = sbase + (u32)(i & 3) * STAGE + (u32)sc * SUB;
            #pragma unroll
            for (int s = 0; s < 2; s++) {
                u32 ah[2][4], b[8][2];
                ldA(stb, wm,      s, ah[0]);
                ldA(stb, wm + 16, s, ah[1]);
                #pragma unroll
                for (int j4 = 0; j4 < 4; j4++) {
                    u32 r[4];
                    ldB(stb + Boff, wn + j4 * 16, s, r);
                    b[2 * j4][0] = r[0]; b[2 * j4][1] = r[1];
                    b[2 * j4 + 1][0] = r[2]; b[2 * j4 + 1][1] = r[3];
                }
                #pragma unroll
                for (int i2 = 0; i2 < 2; i2++)
                    #pragma unroll
                    for (int j8 = 0; j8 < 8; j8++) mma16816(acc[i2][j8], ah[i2], b[j8]);
                if (TWOPASS) {
                    u32 al[2][4];
                    ldA(stb + 8192, wm,      s, al[0]);
                    ldA(stb + 8192, wm + 16, s, al[1]);
                    #pragma unroll
                    for (int i2 = 0; i2 < 2; i2++)
                        #pragma unroll
                        for (int j8 = 0; j8 < 8; j8++) mma16816(acc[i2][j8], al[i2], b[j8]);
                }
            }
        }
    }

    // epilogue
    const int r0b = bm + wm + (lane >> 2);
    const int c0b = bn + wn + ((lane & 3) << 1);
    #pragma unroll
    for (int i2 = 0; i2 < 2; i2++) {
        #pragma unroll
        for (int j8 = 0; j8 < 8; j8++) {
            int col = c0b + j8 * 8;
            float b0 = bias[col], b1 = bias[col + 1];
            #pragma unroll
            for (int h = 0; h < 2; h++) {
                int row = r0b + i2 * 16 + h * 8;
                float v0 = fmaxf(acc[i2][j8][2 * h]     + b0, 0.f);
                float v1 = fmaxf(acc[i2][j8][2 * h + 1] + b1, 0.f);
                if (mode == 0) {
                    *(float2*)(Cf + (size_t)z * sC + (size_t)row * N + col) = make_float2(v0, v1);
                } else {
                    __half h0, l0, h1, l1;
                    split_hl(v0, h0, l0);
                    split_hl(v1, h1, l1);
                    __half2 hp; hp.x = h0; hp.y = h1;
                    *(__half2*)(Ch + (size_t)z * sC + (size_t)row * N + col) = hp;
                    if (mode == 1) {
                        __half2 lp; lp.x = l0; lp.y = l1;
                        *(__half2*)(Cl + (size_t)z * sC + (size_t)row * N + col) = lp;
                    }
                }
            }
        }
    }
}

// ============================================================
// weight transpose: W[z][K][N] f32 -> T[z][N][K] fp16
// ============================================================
__global__ void transpose_h(const float* __restrict__ W, __half* __restrict__ Th,
                            int Kd, int Nd)
{
    __shared__ float t[32][33];
    int z = blockIdx.z;
    const float* Wz = W + (size_t)z * Kd * Nd;
    int n0 = blockIdx.x << 5, k0 = blockIdx.y << 5;
    for (int r = threadIdx.y; r < 32; r += 8)
        t[r][threadIdx.x] = Wz[(size_t)(k0 + r) * Nd + n0 + threadIdx.x];
    __syncthreads();
    size_t ob = (size_t)z * Nd * Kd;
    for (int r = threadIdx.y; r < 32; r += 8)
        Th[ob + (size_t)(n0 + r) * Kd + k0 + threadIdx.x] = __float2half_rn(t[threadIdx.x][r]);
}

// CE1 collapse: ceW1[z][d*5+p][n] f32 -> CU[z][n][d] = sum_p embB_p*W,
//                                        CU[z][n][512+d] = sum_p embW_p*W
__global__ void prep_cu(const float* __restrict__ W, const float* __restrict__ embW,
                        const float* __restrict__ embB, __half* __restrict__ CU)
{
    __shared__ float t0[32][33], t1[32][33];
    int z = blockIdx.z;
    int n0 = blockIdx.x << 5, d0 = blockIdx.y << 5;
    const float* Wz = W + (size_t)z * KAIT * NH1;
    float ew[PEN], eb[PEN];
    #pragma unroll
    for (int p = 0; p < PEN; p++) { ew[p] = embW[p]; eb[p] = embB[p]; }
    for (int r = threadIdx.y; r < 32; r += 8) {
        float s0 = 0.f, s1 = 0.f;
        #pragma unroll
        for (int p = 0; p < PEN; p++) {
            float w = Wz[(size_t)((d0 + r) * PEN + p) * NH1 + n0 + threadIdx.x];
            s0 += eb[p] * w;
            s1 += ew[p] * w;
        }
        t0[r][threadIdx.x] = s0;
        t1[r][threadIdx.x] = s1;
    }
    __syncthreads();
    size_t ob = (size_t)z * NH1 * 1024;
    for (int r = threadIdx.y; r < 32; r += 8) {
        CU[ob + (size_t)(n0 + r) * 1024 + d0 + threadIdx.x] =
            __float2half_rn(t0[threadIdx.x][r]);
        CU[ob + (size_t)(n0 + r) * 1024 + 512 + d0 + threadIdx.x] =
            __float2half_rn(t1[threadIdx.x][r]);
    }
}

// cgate collapse: u0[d][e] = sum_p embB_p*cgW[d*5+p][e]; u1 likewise with embW
__global__ void prep_ug(const float* __restrict__ cgW, const float* __restrict__ embW,
                        const float* __restrict__ embB, float* __restrict__ u)
{
    int i = blockIdx.x * blockDim.x + threadIdx.x;
    if (i >= DD * 8) return;
    int d = i >> 3, e = i & 7;
    float s0 = 0.f, s1 = 0.f;
    #pragma unroll
    for (int p = 0; p < PEN; p++) {
        float w = cgW[(size_t)(d * PEN + p) * 8 + e];
        s0 += embB[p] * w;
        s1 += embW[p] * w;
    }
    u[i] = s0;
    u[DD * 8 + i] = s1;
}

// elementwise fp32 -> fp16 (hi only)
__global__ void convert_h(const float* __restrict__ src, __half* __restrict__ hi, size_t n)
{
    size_t i = ((size_t)blockIdx.x * blockDim.x + threadIdx.x) * 4;
    if (i >= n) return;
    float4 v = *(const float4*)(src + i);
    __half2 a, b;
    a.x = __float2half_rn(v.x); a.y = __float2half_rn(v.y);
    b.x = __float2half_rn(v.z); b.y = __float2half_rn(v.w);
    *(__half2*)(hi + i) = a; *(__half2*)(hi + i + 2) = b;
}

// cx[b] = [x[b] | pctr[b]*x[b]] fp16 hi only (CE1 A operand)
__global__ void cx_kernel(const float* __restrict__ x, const float* __restrict__ out,
                          __half* __restrict__ cxh)
{
    int b = blockIdx.x;
    float pc = out[b];
    const float* xr = x + (size_t)b * DD;
    size_t ob = (size_t)b * 1024;
    for (int d = threadIdx.x; d < DD; d += blockDim.x) {
        float v = xr[d];
        cxh[ob + d] = __float2half_rn(v);
        cxh[ob + 512 + d] = __float2half_rn(pc * v);
    }
}

// ================= small fp32 kernels =================
__global__ void gates_kernel(const float* __restrict__ x, const float* __restrict__ gW,
                             const float* __restrict__ gb, float* __restrict__ gates)
{
    int gw = (blockIdx.x * blockDim.x + threadIdx.x) >> 5;
    int lane = threadIdx.x & 31;
    if (gw >= NB * 2) return;
    int b = gw >> 1, t = gw & 1;
    const float* xr = x + (size_t)b * DD;
    float acc[8] = {};
    for (int d = lane; d < DD; d += 32) {
        float xv = xr[d];
        const float* g = gW + ((size_t)t * DD + d) * NE;
        float4 w0 = *(const float4*)g;
        float4 w1 = *(const float4*)(g + 4);
        acc[0] += xv * w0.x; acc[1] += xv * w0.y; acc[2] += xv * w0.z; acc[3] += xv * w0.w;
        acc[4] += xv * w1.x; acc[5] += xv * w1.y; acc[6] += xv * w1.z; acc[7] += xv * w1.w;
    }
    #pragma unroll
    for (int e = 0; e < 8; e++)
        #pragma unroll
        for (int o = 16; o; o >>= 1) acc[e] += __shfl_xor_sync(0xffffffffu, acc[e], o);
    float m = -1e30f;
    #pragma unroll
    for (int e = 0; e < 8; e++) { acc[e] += gb[t * 8 + e]; m = fmaxf(m, acc[e]); }
    float s = 0.f;
    #pragma unroll
    for (int e = 0; e < 8; e++) { acc[e] = expf(acc[e] - m); s += acc[e]; }
    float inv = 1.f / s;
    if (lane < 8) gates[((size_t)b * 2 + t) * 8 + lane] = acc[lane] * inv;
}

// fused combine for both tasks + fp16 split of task_fea (tower input)
__global__ void combine12(const float* __restrict__ fea, const float* __restrict__ gates,
                          float* __restrict__ o3, float* __restrict__ o4,
                          __half* __restrict__ tfh, __half* __restrict__ tfl)
{
    int b = blockIdx.x;
    __shared__ float g[16];
    if (threadIdx.x < 16) g[threadIdx.x] = gates[(size_t)b * 16 + threadIdx.x];
    __syncthreads();
    const float* f = fea + (size_t)b * NH2;
    for (int h = threadIdx.x; h < NH2; h += blockDim.x) {
        float s0 = 0.f, s1 = 0.f;
        #pragma unroll
        for (int e = 0; e < 8; e++) {
            float v = f[(size_t)e * NB * NH2 + h];
            s0 += g[e] * v;
            s1 += g[8 + e] * v;
        }
        o3[(size_t)b * NH2 + h] = s0;
        o4[(size_t)b * NH2 + h] = s1;
        __half hh, ll;
        split_hl(s0, hh, ll);
        tfh[(size_t)b * NH2 + h] = hh;
        tfl[(size_t)b * NH2 + h] = ll;
        split_hl(s1, hh, ll);
        tfh[(size_t)(NB + b) * NH2 + h] = hh;
        tfl[(size_t)(NB + b) * NH2 + h] = ll;
    }
}

// phase-2 combine: ctask -> O5 + fp16 split for cascade tower
__global__ void combine1c(const float* __restrict__ fea, const float* __restrict__ cg,
                          float* __restrict__ o5, __half* __restrict__ cth,
                          __half* __restrict__ ctl)
{
    int b = blockIdx.x;
    __shared__ float g[8];
    if (threadIdx.x < 8) g[threadIdx.x] = cg[(size_t)b * 8 + threadIdx.x];
    __syncthreads();
    const float* f = fea + (size_t)b * NH2;
    for (int h = threadIdx.x; h < NH2; h += blockDim.x) {
        float s = 0.f;
        #pragma unroll
        for (int e = 0; e < 8; e++) s += g[e] * f[(size_t)e * NB * NH2 + h];
        o5[(size_t)b * NH2 + h] = s;
        __half hh, ll;
        split_hl(s, hh, ll);
        cth[(size_t)b * NH2 + h] = hh;
        ctl[(size_t)b * NH2 + h] = ll;
    }
}

__global__ void preds_kernel(const float* __restrict__ outr, const float* __restrict__ pW,
                             const float* __restrict__ pb, float* __restrict__ out)
{
    int gw = (blockIdx.x * blockDim.x + threadIdx.x) >> 5;
    int lane = threadIdx.x & 31;
    if (gw >= NB * 2) return;
    int b = gw >> 1, t = gw & 1;
    const float* th2 = outr + O6 + (size_t)t * NB * TT2 + (size_t)b * TT2;
    const float* w = pW + t * TT2;
    float s = 0.f;
    for (int m = lane; m < TT2; m += 32) s += th2[m] * w[m];
    #pragma unroll
    for (int o = 16; o; o >>= 1) s += __shfl_xor_sync(0xffffffffu, s, o);
    if (lane == 0) {
        s += pb[t];
        out[(size_t)t * NB + b] = 1.f / (1.f + expf(-s));
    }
}

// cgate via collapsed u: logits_e = x.u0[:,e] + pctr*(x.u1[:,e]) + cgb
__global__ void cgate_kernel(const float* __restrict__ x, const float* __restrict__ out,
                             const float* __restrict__ u, const float* __restrict__ cgb,
                             float* __restrict__ cg)
{
    int gw = (blockIdx.x * blockDim.x + threadIdx.x) >> 5;
    int lane = threadIdx.x & 31;
    if (gw >= NB) return;
    const float* xr = x + (size_t)gw * DD;
    float a0[8] = {}, a1[8] = {};
    for (int d = lane; d < DD; d += 32) {
        float xv = xr[d];
        const float* u0 = u + (size_t)d * 8;
        const float* u1 = u + (size_t)(DD + d) * 8;
        float4 w0 = *(const float4*)u0;
        float4 w1 = *(const float4*)(u0 + 4);
        a0[0] += xv * w0.x; a0[1] += xv * w0.y; a0[2] += xv * w0.z; a0[3] += xv * w0.w;
        a0[4] += xv * w1.x; a0[5] += xv * w1.y; a0[6] += xv * w1.z; a0[7] += xv * w1.w;
        float4 v0 = *(const float4*)u1;
        float4 v1 = *(const float4*)(u1 + 4);
        a1[0] += xv * v0.x; a1[1] += xv * v0.y; a1[2] += xv * v0.z; a1[3] += xv * v0.w;
        a1[4] += xv * v1.x; a1[5] += xv * v1.y; a1[6] += xv * v1.z; a1[7] += xv * v1.w;
    }
    #pragma unroll
    for (int e = 0; e < 8; e++) {
        #pragma unroll
        for (int o = 16; o; o >>= 1) {
            a0[e] += __shfl_xor_sync(0xffffffffu, a0[e], o);
            a1[e] += __shfl_xor_sync(0xffffffffu, a1[e], o);
        }
    }
    float pc = out[gw];
    float m = -1e30f;
    float acc[8];
    #pragma unroll
    for (int e = 0; e < 8; e++) {
        acc[e] = a0[e] + pc * a1[e] + cgb[e];
        m = fmaxf(m, acc[e]);
    }
    float s = 0.f;
    #pragma unroll
    for (int e = 0; e < 8; e++) { acc[e] = expf(acc[e] - m); s += acc[e]; }
    float inv = 1.f / s;
    if (lane < 8) cg[(size_t)gw * 8 + lane] = acc[lane] * inv;
}

__global__ void pconv_kernel(const float* __restrict__ outr, const float* __restrict__ cpW,
                             const float* __restrict__ cpb, float* __restrict__ out)
{
    int gw = (blockIdx.x * blockDim.x + threadIdx.x) >> 5;
    int lane = threadIdx.x & 31;
    if (gw >= NB) return;
    const float* ch2 = outr + O8 + (size_t)gw * TT2;
    float s = 0.f;
    for (int m = lane; m < TT2; m += 32) s += ch2[m] * cpW[m];
    #pragma unroll
    for (int o = 16; o; o >>= 1) s += __shfl_xor_sync(0xffffffffu, s, o);
    if (lane == 0) out[O2 + gw] = 1.f / (1.f + expf(-(s + cpb[0])));
}

// ============================================================
extern "C" void kernel_launch(void* const* d_in, const int* in_sizes, int n_in,
                              void* d_out, int out_size)
{
    const float* x    = (const float*)d_in[0];
    const float* eW1  = (const float*)d_in[1];
    const float* eb1  = (const float*)d_in[2];
    const float* eW2  = (const float*)d_in[3];
    const float* eb2  = (const float*)d_in[4];
    const float* gW   = (const float*)d_in[5];
    const float* gb   = (const float*)d_in[6];
    const float* tW1  = (const float*)d_in[7];
    const float* tb1  = (const float*)d_in[8];
    const float* tW2  = (const float*)d_in[9];
    const float* tb2  = (const float*)d_in[10];
    const float* pW   = (const float*)d_in[11];
    const float* pb   = (const float*)d_in[12];
    const float* embW = (const float*)d_in[13];
    const float* embB = (const float*)d_in[14];
    const float* ceW1 = (const float*)d_in[15];
    const float* ceb1 = (const float*)d_in[16];
    const float* ceW2 = (const float*)d_in[17];
    const float* ceb2 = (const float*)d_in[18];
    const float* cgW  = (const float*)d_in[19];
    const float* cgb  = (const float*)d_in[20];
    const float* ctW1 = (const float*)d_in[21];
    const float* ctb1 = (const float*)d_in[22];
    const float* ctW2 = (const float*)d_in[23];
    const float* ctb2 = (const float*)d_in[24];
    const float* cpW  = (const float*)d_in[25];
    const float* cpb  = (const float*)d_in[26];
    float* out = (float*)d_out;

    __half *xh, *cxh, *Hh, *W1h, *W2h, *CUh, *CW2h, *tW1h, *tW2h, *cW1h, *cW2h;
    __half *tfh, *tfl, *th1h, *th1l, *cth, *ctl, *ch1h, *ch1l;
    float *pFEA, *pG, *pCG, *pUG;
    cudaGetSymbolAddress((void**)&xh, g_xh);
    cudaGetSymbolAddress((void**)&cxh, g_cxh);
    cudaGetSymbolAddress((void**)&Hh, g_Hh);
    cudaGetSymbolAddress((void**)&W1h, g_W1h); cudaGetSymbolAddress((void**)&W2h, g_W2h);
    cudaGetSymbolAddress((void**)&CUh, g_CUh); cudaGetSymbolAddress((void**)&CW2h, g_CW2h);
    cudaGetSymbolAddress((void**)&tW1h, g_tW1h); cudaGetSymbolAddress((void**)&tW2h, g_tW2h);
    cudaGetSymbolAddress((void**)&cW1h, g_cW1h); cudaGetSymbolAddress((void**)&cW2h, g_cW2h);
    cudaGetSymbolAddress((void**)&tfh, g_tfh); cudaGetSymbolAddress((void**)&tfl, g_tfl);
    cudaGetSymbolAddress((void**)&th1h, g_th1h); cudaGetSymbolAddress((void**)&th1l, g_th1l);
    cudaGetSymbolAddress((void**)&cth, g_cth); cudaGetSymbolAddress((void**)&ctl, g_ctl);
    cudaGetSymbolAddress((void**)&ch1h, g_ch1h); cudaGetSymbolAddress((void**)&ch1l, g_ch1l);
    cudaGetSymbolAddress((void**)&pFEA, g_FEA);
    cudaGetSymbolAddress((void**)&pG, g_GATES);
    cudaGetSymbolAddress((void**)&pCG, g_CGATE);
    cudaGetSymbolAddress((void**)&pUG, g_UG);

    const int SM2 = 4 * 2 * 24576;   // 196608
    const int SM1 = 4 * 2 * 16384;   // 131072
    cudaFuncSetAttribute(hmma_t<1>, cudaFuncAttributeMaxDynamicSharedMemorySize, SM2);
    cudaFuncSetAttribute(hmma_t<0>, cudaFuncAttributeMaxDynamicSharedMemorySize, SM1);
    dim3 blk(256);
    dim3 tb(32, 8);

    // ---- weight prep ----
    transpose_h<<<dim3(NH1 / 32, DD / 32, NE), tb>>>(eW1, W1h, DD, NH1);
    transpose_h<<<dim3(NH2 / 32, NH1 / 32, NE), tb>>>(eW2, W2h, NH1, NH2);
    prep_cu<<<dim3(NH1 / 32, DD / 32, NE), tb>>>(ceW1, embW, embB, CUh);
    transpose_h<<<dim3(NH2 / 32, NH1 / 32, NE), tb>>>(ceW2, CW2h, NH1, NH2);
    transpose_h<<<dim3(TT1 / 32, NH2 / 32, 2), tb>>>(tW1, tW1h, NH2, TT1);
    transpose_h<<<dim3(TT2 / 32, TT1 / 32, 2), tb>>>(tW2, tW2h, TT1, TT2);
    transpose_h<<<dim3(TT1 / 32, NH2 / 32, 1), tb>>>(ctW1, cW1h, NH2, TT1);
    transpose_h<<<dim3(TT2 / 32, TT1 / 32, 1), tb>>>(ctW2, cW2h, TT1, TT2);
    prep_ug<<<(DD * 8 + 255) / 256, 256>>>(cgW, embW, embB, pUG);
    convert_h<<<NB * DD / 4 / 256, 256>>>(x, xh, (size_t)NB * DD);

    // ---- phase 1: experts (one-pass) ----
    hmma_t<0><<<dim3(NH1 / 128, NB / 128, NE), blk, SM1>>>(
        xh, nullptr, W1h, eb1, nullptr, Hh, nullptr,
        NH1, DD, 15, DD, 0, (size_t)NH1 * DD, NH1, (size_t)NB * NH1, 2);
    hmma_t<0><<<dim3(NH2 / 128, NB / 128, NE), blk, SM1>>>(
        Hh, nullptr, W2h, eb2, pFEA, nullptr, nullptr,
        NH2, NH1, 31, NH1, (size_t)NB * NH1, (size_t)NH2 * NH1, NH2, (size_t)NB * NH2, 0);

    gates_kernel<<<NB * 2 / 8, 256>>>(x, gW, gb, pG);
    combine12<<<NB, 256>>>(pFEA, pG, out + O3, out + O4, tfh, tfl);

    // towers (2-pass, protects output precision)
    hmma_t<1><<<dim3(TT1 / 128, NB / 128, 2), blk, SM2>>>(
        tfh, tfl, tW1h, tb1, nullptr, th1h, th1l,
        TT1, NH2, 15, NH2, (size_t)NB * NH2, (size_t)TT1 * NH2, TT1, (size_t)NB * TT1, 1);
    hmma_t<1><<<dim3(1, NB / 128, 2), blk, SM2>>>(
        th1h, th1l, tW2h, tb2, out + O6, nullptr, nullptr,
        TT2, TT1, 7, TT1, (size_t)NB * TT1, (size_t)TT2 * TT1, TT2, (size_t)NB * TT2, 0);
    preds_kernel<<<NB * 2 / 8, 256>>>(out, pW, pb, out);

    // ---- phase 2: cascade (CE1 collapsed, one-pass) ----
    cx_kernel<<<NB, 256>>>(x, out, cxh);
    hmma_t<0><<<dim3(NH1 / 128, NB / 128, NE), blk, SM1>>>(
        cxh, nullptr, CUh, ceb1, nullptr, Hh, nullptr,
        NH1, 1024, 31, 1024, 0, (size_t)NH1 * 1024, NH1, (size_t)NB * NH1, 2);
    hmma_t<0><<<dim3(NH2 / 128, NB / 128, NE), blk, SM1>>>(
        Hh, nullptr, CW2h, ceb2, pFEA, nullptr, nullptr,
        NH2, NH1, 31, NH1, (size_t)NB * NH1, (size_t)NH2 * NH1, NH2, (size_t)NB * NH2, 0);
    cgate_kernel<<<NB / 8, 256>>>(x, out, pUG, cgb, pCG);
    combine1c<<<NB, 256>>>(pFEA, pCG, out + O5, cth, ctl);

    hmma_t<1><<<dim3(TT1 / 128, NB / 128, 1), blk, SM2>>>(
        cth, ctl, cW1h, ctb1, nullptr, ch1h, ch1l,
        TT1, NH2, 15, NH2, 0, 0, 0, (size_t)NB * TT1, 1);
    hmma_t<1><<<dim3(1, NB / 128, 1), blk, SM2>>>(
        ch1h, ch1l, cW2h, ctb2, out + O8, nullptr, nullptr,
        TT2, TT1, 7, TT1, 0, 0, 0, 0, 0);
    pconv_kernel<<<NB / 8, 256>>>(out, cpW, cpb, out);
}

// round 8
// speedup vs baseline: 10.2103x; 1.2173x over previous
#include <cuda_runtime.h>
#include <cuda_fp16.h>
#include <math.h>

typedef unsigned long long ull;
typedef unsigned int u32;

#define NB   16384
#define DD   512
#define NE   8
#define NH1  1024
#define NH2  512
#define TT1  256
#define TT2  128
#define PEN  5
#define KAIT 2560   // D*PE

// ---- output layout ----
#define O0 ((size_t)0)
#define O1 ((size_t)NB)
#define O2 ((size_t)2*NB)
#define O3 ((size_t)3*NB)
#define O4 (O3 + (size_t)NB*512)
#define O5 (O4 + (size_t)NB*512)
#define O6 (O5 + (size_t)NB*512)
#define O7 (O6 + (size_t)NB*128)
#define O8 (O7 + (size_t)NB*128)

// ---- scratch ----
__device__ __half g_xh [(size_t)NB*DD];
__device__ __half g_cxh[(size_t)NB*1024];   // [x | pctr*x] hi only
__device__ __half g_Hh [(size_t)NE*NB*NH1];
__device__ __half g_W1h[(size_t)NE*NH1*DD];
__device__ __half g_W2h[(size_t)NE*NH2*NH1];
__device__ __half g_CUh[(size_t)NE*NH1*1024];  // [U0;U1] per expert, [N][1024]
__device__ __half g_CW2h[(size_t)NE*NH2*NH1];
__device__ __half g_tW1h[(size_t)2*TT1*NH2];
__device__ __half g_tW2h[(size_t)2*TT2*TT1];
__device__ __half g_cW1h[(size_t)TT1*NH2];
__device__ __half g_cW2h[(size_t)TT2*TT1];
__device__ __half g_tfh[(size_t)2*NB*NH2];
__device__ __half g_tfl[(size_t)2*NB*NH2];
__device__ __half g_th1h[(size_t)2*NB*TT1];
__device__ __half g_th1l[(size_t)2*NB*TT1];
__device__ __half g_cth[(size_t)NB*NH2];
__device__ __half g_ctl[(size_t)NB*NH2];
__device__ __half g_ch1h[(size_t)NB*TT1];
__device__ __half g_ch1l[(size_t)NB*TT1];
__device__ float g_FEA [(size_t)NE*NB*NH2];
__device__ float g_GATES[(size_t)NB*2*8];
__device__ float g_CGATE[(size_t)NB*8];
__device__ float g_UG  [(size_t)2*DD*8];    // cgate u0/u1

// ================= helpers =================
__device__ __forceinline__ u32 smem_u32(const void* p) {
    u32 a;
    asm("{ .reg .u64 t; cvta.to.shared.u64 t, %1; cvt.u32.u64 %0, t; }" : "=r"(a) : "l"(p));
    return a;
}
__device__ __forceinline__ void cpa16(u32 dst, const void* src) {
    asm volatile("cp.async.cg.shared.global [%0], [%1], 16;" :: "r"(dst), "l"(src) : "memory");
}
#define CPA_COMMIT() asm volatile("cp.async.commit_group;" ::: "memory")
#define CPA_WAIT1()  asm volatile("cp.async.wait_group 1;" ::: "memory")

__device__ __forceinline__ void mma16816(float* c, const u32* a, const u32* b) {
    asm volatile(
        "mma.sync.aligned.m16n8k16.row.col.f32.f16.f16.f32 "
        "{%0,%1,%2,%3}, {%4,%5,%6,%7}, {%8,%9}, {%0,%1,%2,%3};"
        : "+f"(c[0]), "+f"(c[1]), "+f"(c[2]), "+f"(c[3])
        : "r"(a[0]), "r"(a[1]), "r"(a[2]), "r"(a[3]), "r"(b[0]), "r"(b[1]));
}

// swizzled smem offset (64B rows, 4x16B chunks)
__device__ __forceinline__ u32 swz(int row, int ch) {
    return (u32)(row * 64 + ((ch ^ ((row >> 1) & 3)) << 4));
}

__device__ __forceinline__ void ldA(u32 tb, int row0, int s, u32* a) {
    int lane = threadIdx.x & 31;
    int g = lane >> 3, li = lane & 7;
    int row = row0 + ((g & 1) << 3) + li;
    int ch = 2 * s + (g >> 1);
    u32 addr = tb + swz(row, ch);
    asm volatile("ldmatrix.sync.aligned.m8n8.x4.shared.b16 {%0,%1,%2,%3}, [%4];"
        : "=r"(a[0]), "=r"(a[1]), "=r"(a[2]), "=r"(a[3]) : "r"(addr));
}
__device__ __forceinline__ void ldB(u32 tb, int n0, int s, u32* r) {
    int lane = threadIdx.x & 31;
    int g = lane >> 3, li = lane & 7;
    int row = n0 + ((g >> 1) << 3) + li;
    int ch = 2 * s + (g & 1);
    u32 addr = tb + swz(row, ch);
    asm volatile("ldmatrix.sync.aligned.m8n8.x4.shared.b16 {%0,%1,%2,%3}, [%4];"
        : "=r"(r[0]), "=r"(r[1]), "=r"(r[2]), "=r"(r[3]) : "r"(addr));
}
__device__ __forceinline__ void split_hl(float v, __half& h, __half& l) {
    h = __float2half_rn(v);
    l = __float2half_rn(v - __half2float(h));
}

// ============================================================
// HMMA GEMM template, k=64 chunks, 3-stage cp.async pipeline.
//   C[z] = relu(A[z] @ B[z]^T + bias[z])
// A [M, aK] fp16 (hi + optional lo); B [N, K] fp16 (pre-transposed).
// A k-col for 32-chunk c32 = (c32 & acolmask)*32.  K % 64 == 0, K >= 256.
// One-pass: 96KB smem -> 2 CTAs/SM. Two-pass: 144KB -> 1 CTA/SM.
// mode: 0 = fp32 C, 1 = fp16 hi/lo C, 2 = fp16 hi-only C.
// ============================================================
template<int TWOPASS>
__global__ void __launch_bounds__(256, TWOPASS ? 1 : 2) hmma_t(
    const __half* __restrict__ Ah, const __half* __restrict__ Al,
    const __half* __restrict__ Bh, const float* __restrict__ bias,
    float* __restrict__ Cf, __half* __restrict__ Ch, __half* __restrict__ Cl,
    int N, int K, int acolmask, int aK,
    size_t sA, size_t sB, size_t sBias, size_t sC, int mode)
{
    extern __shared__ char dsm[];
    const int SUB   = TWOPASS ? 24576 : 16384;
    const int STAGE = 2 * SUB;
    const int NSLOT = TWOPASS ? 6 : 4;
    const int tid = threadIdx.x;
    const int wid = tid >> 5;
    const int lane = tid & 31;
    const int z = blockIdx.z;
    const int bm = blockIdx.y << 7;
    const int bn = blockIdx.x << 7;

    Ah += (size_t)z * sA;
    if (TWOPASS) Al += (size_t)z * sA;
    Bh += (size_t)z * sB;  bias += (size_t)z * sBias;

    const u32 sbase = smem_u32(dsm);

    u32 soff[NSLOT];
    const __half* gsrc[NSLOT];
    u32 amask[NSLOT];
    #pragma unroll
    for (int j = 0; j < NSLOT; j++) {
        int sid = tid + (j << 8);
        int buf = sid >> 9;
        int rem = sid & 511;
        int r = rem >> 2;
        int ch = rem & 3;
        soff[j] = (u32)(buf * 8192) + swz(r, ch);
        bool isA = TWOPASS ? (buf < 2) : (buf == 0);
        const __half* base = isA ? ((TWOPASS && buf == 1) ? Al : Ah) : Bh;
        int grow = (isA ? bm : bn) + r;
        gsrc[j] = base + (size_t)grow * (isA ? aK : K) + ch * 8;
        amask[j] = isA ? (u32)acolmask : 0xFFFFFFFFu;
    }

    const int nch = K >> 6;   // 64-k chunks

    // prologue: fill stages 0,1
    #pragma unroll
    for (int p = 0; p < 2; p++) {
        u32 sb = sbase + (u32)p * STAGE;
        #pragma unroll
        for (int sc = 0; sc < 2; sc++)
            #pragma unroll
            for (int j = 0; j < NSLOT; j++)
                cpa16(sb + (u32)sc * SUB + soff[j],
                      gsrc[j] + (((u32)(2 * p + sc) & amask[j]) << 5));
        CPA_COMMIT();
    }

    const int wm = (wid & 3) << 5;
    const int wn = (wid >> 2) << 6;
    const u32 Boff = TWOPASS ? 16384u : 8192u;

    float acc[2][8][4];
    #pragma unroll
    for (int i = 0; i < 2; i++)
        #pragma unroll
        for (int j = 0; j < 8; j++)
            #pragma unroll
            for (int q = 0; q < 4; q++) acc[i][j][q] = 0.f;

    int stg = 0;   // i % 3
    for (int i = 0; i < nch; i++) {
        CPA_WAIT1();
        __syncthreads();
        int pf = i + 2;
        if (pf < nch) {
            int pstg = stg + 2; if (pstg >= 3) pstg -= 3;
            u32 sb = sbase + (u32)pstg * STAGE;
            #pragma unroll
            for (int sc = 0; sc < 2; sc++)
                #pragma unroll
                for (int j = 0; j < NSLOT; j++)
                    cpa16(sb + (u32)sc * SUB + soff[j],
                          gsrc[j] + (((u32)(2 * pf + sc) & amask[j]) << 5));
        }
        CPA_COMMIT();

        #pragma unroll
        for (int sc = 0; sc < 2; sc++) {
            u32 stb = sbase + (u32)stg * STAGE + (u32)sc * SUB;
            #pragma unroll
            for (int s = 0; s < 2; s++) {
                u32 ah[2][4], b[8][2];
                ldA(stb, wm,      s, ah[0]);
                ldA(stb, wm + 16, s, ah[1]);
                #pragma unroll
                for (int j4 = 0; j4 < 4; j4++) {
                    u32 r[4];
                    ldB(stb + Boff, wn + j4 * 16, s, r);
                    b[2 * j4][0] = r[0]; b[2 * j4][1] = r[1];
                    b[2 * j4 + 1][0] = r[2]; b[2 * j4 + 1][1] = r[3];
                }
                #pragma unroll
                for (int i2 = 0; i2 < 2; i2++)
                    #pragma unroll
                    for (int j8 = 0; j8 < 8; j8++) mma16816(acc[i2][j8], ah[i2], b[j8]);
                if (TWOPASS) {
                    u32 al[2][4];
                    ldA(stb + 8192, wm,      s, al[0]);
                    ldA(stb + 8192, wm + 16, s, al[1]);
                    #pragma unroll
                    for (int i2 = 0; i2 < 2; i2++)
                        #pragma unroll
                        for (int j8 = 0; j8 < 8; j8++) mma16816(acc[i2][j8], al[i2], b[j8]);
                }
            }
        }
        if (++stg == 3) stg = 0;
    }

    // epilogue
    const int r0b = bm + wm + (lane >> 2);
    const int c0b = bn + wn + ((lane & 3) << 1);
    #pragma unroll
    for (int i2 = 0; i2 < 2; i2++) {
        #pragma unroll
        for (int j8 = 0; j8 < 8; j8++) {
            int col = c0b + j8 * 8;
            float b0 = bias[col], b1 = bias[col + 1];
            #pragma unroll
            for (int h = 0; h < 2; h++) {
                int row = r0b + i2 * 16 + h * 8;
                float v0 = fmaxf(acc[i2][j8][2 * h]     + b0, 0.f);
                float v1 = fmaxf(acc[i2][j8][2 * h + 1] + b1, 0.f);
                if (mode == 0) {
                    *(float2*)(Cf + (size_t)z * sC + (size_t)row * N + col) = make_float2(v0, v1);
                } else {
                    __half h0, l0, h1, l1;
                    split_hl(v0, h0, l0);
                    split_hl(v1, h1, l1);
                    __half2 hp; hp.x = h0; hp.y = h1;
                    *(__half2*)(Ch + (size_t)z * sC + (size_t)row * N + col) = hp;
                    if (mode == 1) {
                        __half2 lp; lp.x = l0; lp.y = l1;
                        *(__half2*)(Cl + (size_t)z * sC + (size_t)row * N + col) = lp;
                    }
                }
            }
        }
    }
}

// ============================================================
// weight transpose: W[z][K][N] f32 -> T[z][N][K] fp16
// ============================================================
__global__ void transpose_h(const float* __restrict__ W, __half* __restrict__ Th,
                            int Kd, int Nd)
{
    __shared__ float t[32][33];
    int z = blockIdx.z;
    const float* Wz = W + (size_t)z * Kd * Nd;
    int n0 = blockIdx.x << 5, k0 = blockIdx.y << 5;
    for (int r = threadIdx.y; r < 32; r += 8)
        t[r][threadIdx.x] = Wz[(size_t)(k0 + r) * Nd + n0 + threadIdx.x];
    __syncthreads();
    size_t ob = (size_t)z * Nd * Kd;
    for (int r = threadIdx.y; r < 32; r += 8)
        Th[ob + (size_t)(n0 + r) * Kd + k0 + threadIdx.x] = __float2half_rn(t[threadIdx.x][r]);
}

// CE1 collapse: ceW1[z][d*5+p][n] f32 -> CU[z][n][d] = sum_p embB_p*W,
//                                        CU[z][n][512+d] = sum_p embW_p*W
__global__ void prep_cu(const float* __restrict__ W, const float* __restrict__ embW,
                        const float* __restrict__ embB, __half* __restrict__ CU)
{
    __shared__ float t0[32][33], t1[32][33];
    int z = blockIdx.z;
    int n0 = blockIdx.x << 5, d0 = blockIdx.y << 5;
    const float* Wz = W + (size_t)z * KAIT * NH1;
    float ew[PEN], eb[PEN];
    #pragma unroll
    for (int p = 0; p < PEN; p++) { ew[p] = embW[p]; eb[p] = embB[p]; }
    for (int r = threadIdx.y; r < 32; r += 8) {
        float s0 = 0.f, s1 = 0.f;
        #pragma unroll
        for (int p = 0; p < PEN; p++) {
            float w = Wz[(size_t)((d0 + r) * PEN + p) * NH1 + n0 + threadIdx.x];
            s0 += eb[p] * w;
            s1 += ew[p] * w;
        }
        t0[r][threadIdx.x] = s0;
        t1[r][threadIdx.x] = s1;
    }
    __syncthreads();
    size_t ob = (size_t)z * NH1 * 1024;
    for (int r = threadIdx.y; r < 32; r += 8) {
        CU[ob + (size_t)(n0 + r) * 1024 + d0 + threadIdx.x] =
            __float2half_rn(t0[threadIdx.x][r]);
        CU[ob + (size_t)(n0 + r) * 1024 + 512 + d0 + threadIdx.x] =
            __float2half_rn(t1[threadIdx.x][r]);
    }
}

// cgate collapse: u0[d][e] = sum_p embB_p*cgW[d*5+p][e]; u1 likewise with embW
__global__ void prep_ug(const float* __restrict__ cgW, const float* __restrict__ embW,
                        const float* __restrict__ embB, float* __restrict__ u)
{
    int i = blockIdx.x * blockDim.x + threadIdx.x;
    if (i >= DD * 8) return;
    int d = i >> 3, e = i & 7;
    float s0 = 0.f, s1 = 0.f;
    #pragma unroll
    for (int p = 0; p < PEN; p++) {
        float w = cgW[(size_t)(d * PEN + p) * 8 + e];
        s0 += embB[p] * w;
        s1 += embW[p] * w;
    }
    u[i] = s0;
    u[DD * 8 + i] = s1;
}

// elementwise fp32 -> fp16 (hi only)
__global__ void convert_h(const float* __restrict__ src, __half* __restrict__ hi, size_t n)
{
    size_t i = ((size_t)blockIdx.x * blockDim.x + threadIdx.x) * 4;
    if (i >= n) return;
    float4 v = *(const float4*)(src + i);
    __half2 a, b;
    a.x = __float2half_rn(v.x); a.y = __float2half_rn(v.y);
    b.x = __float2half_rn(v.z); b.y = __float2half_rn(v.w);
    *(__half2*)(hi + i) = a; *(__half2*)(hi + i + 2) = b;
}

// cx[b] = [x[b] | pctr[b]*x[b]] fp16 hi only (CE1 A operand)
__global__ void cx_kernel(const float* __restrict__ x, const float* __restrict__ out,
                          __half* __restrict__ cxh)
{
    int b = blockIdx.x;
    float pc = out[b];
    const float* xr = x + (size_t)b * DD;
    size_t ob = (size_t)b * 1024;
    for (int d = threadIdx.x; d < DD; d += blockDim.x) {
        float v = xr[d];
        cxh[ob + d] = __float2half_rn(v);
        cxh[ob + 512 + d] = __float2half_rn(pc * v);
    }
}

// ================= small fp32 kernels =================
__global__ void gates_kernel(const float* __restrict__ x, const float* __restrict__ gW,
                             const float* __restrict__ gb, float* __restrict__ gates)
{
    int gw = (blockIdx.x * blockDim.x + threadIdx.x) >> 5;
    int lane = threadIdx.x & 31;
    if (gw >= NB * 2) return;
    int b = gw >> 1, t = gw & 1;
    const float* xr = x + (size_t)b * DD;
    float acc[8] = {};
    for (int d = lane; d < DD; d += 32) {
        float xv = xr[d];
        const float* g = gW + ((size_t)t * DD + d) * NE;
        float4 w0 = *(const float4*)g;
        float4 w1 = *(const float4*)(g + 4);
        acc[0] += xv * w0.x; acc[1] += xv * w0.y; acc[2] += xv * w0.z; acc[3] += xv * w0.w;
        acc[4] += xv * w1.x; acc[5] += xv * w1.y; acc[6] += xv * w1.z; acc[7] += xv * w1.w;
    }
    #pragma unroll
    for (int e = 0; e < 8; e++)
        #pragma unroll
        for (int o = 16; o; o >>= 1) acc[e] += __shfl_xor_sync(0xffffffffu, acc[e], o);
    float m = -1e30f;
    #pragma unroll
    for (int e = 0; e < 8; e++) { acc[e] += gb[t * 8 + e]; m = fmaxf(m, acc[e]); }
    float s = 0.f;
    #pragma unroll
    for (int e = 0; e < 8; e++) { acc[e] = expf(acc[e] - m); s += acc[e]; }
    float inv = 1.f / s;
    if (lane < 8) gates[((size_t)b * 2 + t) * 8 + lane] = acc[lane] * inv;
}

// fused combine for both tasks + fp16 split of task_fea (tower input)
__global__ void combine12(const float* __restrict__ fea, const float* __restrict__ gates,
                          float* __restrict__ o3, float* __restrict__ o4,
                          __half* __restrict__ tfh, __half* __restrict__ tfl)
{
    int b = blockIdx.x;
    __shared__ float g[16];
    if (threadIdx.x < 16) g[threadIdx.x] = gates[(size_t)b * 16 + threadIdx.x];
    __syncthreads();
    const float* f = fea + (size_t)b * NH2;
    for (int h = threadIdx.x; h < NH2; h += blockDim.x) {
        float s0 = 0.f, s1 = 0.f;
        #pragma unroll
        for (int e = 0; e < 8; e++) {
            float v = f[(size_t)e * NB * NH2 + h];
            s0 += g[e] * v;
            s1 += g[8 + e] * v;
        }
        o3[(size_t)b * NH2 + h] = s0;
        o4[(size_t)b * NH2 + h] = s1;
        __half hh, ll;
        split_hl(s0, hh, ll);
        tfh[(size_t)b * NH2 + h] = hh;
        tfl[(size_t)b * NH2 + h] = ll;
        split_hl(s1, hh, ll);
        tfh[(size_t)(NB + b) * NH2 + h] = hh;
        tfl[(size_t)(NB + b) * NH2 + h] = ll;
    }
}

// phase-2 combine: ctask -> O5 + fp16 split for cascade tower
__global__ void combine1c(const float* __restrict__ fea, const float* __restrict__ cg,
                          float* __restrict__ o5, __half* __restrict__ cth,
                          __half* __restrict__ ctl)
{
    int b = blockIdx.x;
    __shared__ float g[8];
    if (threadIdx.x < 8) g[threadIdx.x] = cg[(size_t)b * 8 + threadIdx.x];
    __syncthreads();
    const float* f = fea + (size_t)b * NH2;
    for (int h = threadIdx.x; h < NH2; h += blockDim.x) {
        float s = 0.f;
        #pragma unroll
        for (int e = 0; e < 8; e++) s += g[e] * f[(size_t)e * NB * NH2 + h];
        o5[(size_t)b * NH2 + h] = s;
        __half hh, ll;
        split_hl(s, hh, ll);
        cth[(size_t)b * NH2 + h] = hh;
        ctl[(size_t)b * NH2 + h] = ll;
    }
}

__global__ void preds_kernel(const float* __restrict__ outr, const float* __restrict__ pW,
                             const float* __restrict__ pb, float* __restrict__ out)
{
    int gw = (blockIdx.x * blockDim.x + threadIdx.x) >> 5;
    int lane = threadIdx.x & 31;
    if (gw >= NB * 2) return;
    int b = gw >> 1, t = gw & 1;
    const float* th2 = outr + O6 + (size_t)t * NB * TT2 + (size_t)b * TT2;
    const float* w = pW + t * TT2;
    float s = 0.f;
    for (int m = lane; m < TT2; m += 32) s += th2[m] * w[m];
    #pragma unroll
    for (int o = 16; o; o >>= 1) s += __shfl_xor_sync(0xffffffffu, s, o);
    if (lane == 0) {
        s += pb[t];
        out[(size_t)t * NB + b] = 1.f / (1.f + expf(-s));
    }
}

// cgate via collapsed u: logits_e = x.u0[:,e] + pctr*(x.u1[:,e]) + cgb
__global__ void cgate_kernel(const float* __restrict__ x, const float* __restrict__ out,
                             const float* __restrict__ u, const float* __restrict__ cgb,
                             float* __restrict__ cg)
{
    int gw = (blockIdx.x * blockDim.x + threadIdx.x) >> 5;
    int lane = threadIdx.x & 31;
    if (gw >= NB) return;
    const float* xr = x + (size_t)gw * DD;
    float a0[8] = {}, a1[8] = {};
    for (int d = lane; d < DD; d += 32) {
        float xv = xr[d];
        const float* u0 = u + (size_t)d * 8;
        const float* u1 = u + (size_t)(DD + d) * 8;
        float4 w0 = *(const float4*)u0;
        float4 w1 = *(const float4*)(u0 + 4);
        a0[0] += xv * w0.x; a0[1] += xv * w0.y; a0[2] += xv * w0.z; a0[3] += xv * w0.w;
        a0[4] += xv * w1.x; a0[5] += xv * w1.y; a0[6] += xv * w1.z; a0[7] += xv * w1.w;
        float4 v0 = *(const float4*)u1;
        float4 v1 = *(const float4*)(u1 + 4);
        a1[0] += xv * v0.x; a1[1] += xv * v0.y; a1[2] += xv * v0.z; a1[3] += xv * v0.w;
        a1[4] += xv * v1.x; a1[5] += xv * v1.y; a1[6] += xv * v1.z; a1[7] += xv * v1.w;
    }
    #pragma unroll
    for (int e = 0; e < 8; e++) {
        #pragma unroll
        for (int o = 16; o; o >>= 1) {
            a0[e] += __shfl_xor_sync(0xffffffffu, a0[e], o);
            a1[e] += __shfl_xor_sync(0xffffffffu, a1[e], o);
        }
    }
    float pc = out[gw];
    float m = -1e30f;
    float acc[8];
    #pragma unroll
    for (int e = 0; e < 8; e++) {
        acc[e] = a0[e] + pc * a1[e] + cgb[e];
        m = fmaxf(m, acc[e]);
    }
    float s = 0.f;
    #pragma unroll
    for (int e = 0; e < 8; e++) { acc[e] = expf(acc[e] - m); s += acc[e]; }
    float inv = 1.f / s;
    if (lane < 8) cg[(size_t)gw * 8 + lane] = acc[lane] * inv;
}

__global__ void pconv_kernel(const float* __restrict__ outr, const float* __restrict__ cpW,
                             const float* __restrict__ cpb, float* __restrict__ out)
{
    int gw = (blockIdx.x * blockDim.x + threadIdx.x) >> 5;
    int lane = threadIdx.x & 31;
    if (gw >= NB) return;
    const float* ch2 = outr + O8 + (size_t)gw * TT2;
    float s = 0.f;
    for (int m = lane; m < TT2; m += 32) s += ch2[m] * cpW[m];
    #pragma unroll
    for (int o = 16; o; o >>= 1) s += __shfl_xor_sync(0xffffffffu, s, o);
    if (lane == 0) out[O2 + gw] = 1.f / (1.f + expf(-(s + cpb[0])));
}

// ============================================================
extern "C" void kernel_launch(void* const* d_in, const int* in_sizes, int n_in,
                              void* d_out, int out_size)
{
    const float* x    = (const float*)d_in[0];
    const float* eW1  = (const float*)d_in[1];
    const float* eb1  = (const float*)d_in[2];
    const float* eW2  = (const float*)d_in[3];
    const float* eb2  = (const float*)d_in[4];
    const float* gW   = (const float*)d_in[5];
    const float* gb   = (const float*)d_in[6];
    const float* tW1  = (const float*)d_in[7];
    const float* tb1  = (const float*)d_in[8];
    const float* tW2  = (const float*)d_in[9];
    const float* tb2  = (const float*)d_in[10];
    const float* pW   = (const float*)d_in[11];
    const float* pb   = (const float*)d_in[12];
    const float* embW = (const float*)d_in[13];
    const float* embB = (const float*)d_in[14];
    const float* ceW1 = (const float*)d_in[15];
    const float* ceb1 = (const float*)d_in[16];
    const float* ceW2 = (const float*)d_in[17];
    const float* ceb2 = (const float*)d_in[18];
    const float* cgW  = (const float*)d_in[19];
    const float* cgb  = (const float*)d_in[20];
    const float* ctW1 = (const float*)d_in[21];
    const float* ctb1 = (const float*)d_in[22];
    const float* ctW2 = (const float*)d_in[23];
    const float* ctb2 = (const float*)d_in[24];
    const float* cpW  = (const float*)d_in[25];
    const float* cpb  = (const float*)d_in[26];
    float* out = (float*)d_out;

    __half *xh, *cxh, *Hh, *W1h, *W2h, *CUh, *CW2h, *tW1h, *tW2h, *cW1h, *cW2h;
    __half *tfh, *tfl, *th1h, *th1l, *cth, *ctl, *ch1h, *ch1l;
    float *pFEA, *pG, *pCG, *pUG;
    cudaGetSymbolAddress((void**)&xh, g_xh);
    cudaGetSymbolAddress((void**)&cxh, g_cxh);
    cudaGetSymbolAddress((void**)&Hh, g_Hh);
    cudaGetSymbolAddress((void**)&W1h, g_W1h); cudaGetSymbolAddress((void**)&W2h, g_W2h);
    cudaGetSymbolAddress((void**)&CUh, g_CUh); cudaGetSymbolAddress((void**)&CW2h, g_CW2h);
    cudaGetSymbolAddress((void**)&tW1h, g_tW1h); cudaGetSymbolAddress((void**)&tW2h, g_tW2h);
    cudaGetSymbolAddress((void**)&cW1h, g_cW1h); cudaGetSymbolAddress((void**)&cW2h, g_cW2h);
    cudaGetSymbolAddress((void**)&tfh, g_tfh); cudaGetSymbolAddress((void**)&tfl, g_tfl);
    cudaGetSymbolAddress((void**)&th1h, g_th1h); cudaGetSymbolAddress((void**)&th1l, g_th1l);
    cudaGetSymbolAddress((void**)&cth, g_cth); cudaGetSymbolAddress((void**)&ctl, g_ctl);
    cudaGetSymbolAddress((void**)&ch1h, g_ch1h); cudaGetSymbolAddress((void**)&ch1l, g_ch1l);
    cudaGetSymbolAddress((void**)&pFEA, g_FEA);
    cudaGetSymbolAddress((void**)&pG, g_GATES);
    cudaGetSymbolAddress((void**)&pCG, g_CGATE);
    cudaGetSymbolAddress((void**)&pUG, g_UG);

    const int SM2 = 3 * 2 * 24576;   // 147456, 1 CTA/SM
    const int SM1 = 3 * 2 * 16384;   // 98304,  2 CTAs/SM
    cudaFuncSetAttribute(hmma_t<1>, cudaFuncAttributeMaxDynamicSharedMemorySize, SM2);
    cudaFuncSetAttribute(hmma_t<0>, cudaFuncAttributeMaxDynamicSharedMemorySize, SM1);
    dim3 blk(256);
    dim3 tb(32, 8);

    // ---- weight prep ----
    transpose_h<<<dim3(NH1 / 32, DD / 32, NE), tb>>>(eW1, W1h, DD, NH1);
    transpose_h<<<dim3(NH2 / 32, NH1 / 32, NE), tb>>>(eW2, W2h, NH1, NH2);
    prep_cu<<<dim3(NH1 / 32, DD / 32, NE), tb>>>(ceW1, embW, embB, CUh);
    transpose_h<<<dim3(NH2 / 32, NH1 / 32, NE), tb>>>(ceW2, CW2h, NH1, NH2);
    transpose_h<<<dim3(TT1 / 32, NH2 / 32, 2), tb>>>(tW1, tW1h, NH2, TT1);
    transpose_h<<<dim3(TT2 / 32, TT1 / 32, 2), tb>>>(tW2, tW2h, TT1, TT2);
    transpose_h<<<dim3(TT1 / 32, NH2 / 32, 1), tb>>>(ctW1, cW1h, NH2, TT1);
    transpose_h<<<dim3(TT2 / 32, TT1 / 32, 1), tb>>>(ctW2, cW2h, TT1, TT2);
    prep_ug<<<(DD * 8 + 255) / 256, 256>>>(cgW, embW, embB, pUG);
    convert_h<<<NB * DD / 4 / 256, 256>>>(x, xh, (size_t)NB * DD);

    // ---- phase 1: experts (one-pass) ----
    hmma_t<0><<<dim3(NH1 / 128, NB / 128, NE), blk, SM1>>>(
        xh, nullptr, W1h, eb1, nullptr, Hh, nullptr,
        NH1, DD, 15, DD, 0, (size_t)NH1 * DD, NH1, (size_t)NB * NH1, 2);
    hmma_t<0><<<dim3(NH2 / 128, NB / 128, NE), blk, SM1>>>(
        Hh, nullptr, W2h, eb2, pFEA, nullptr, nullptr,
        NH2, NH1, 31, NH1, (size_t)NB * NH1, (size_t)NH2 * NH1, NH2, (size_t)NB * NH2, 0);

    gates_kernel<<<NB * 2 / 8, 256>>>(x, gW, gb, pG);
    combine12<<<NB, 256>>>(pFEA, pG, out + O3, out + O4, tfh, tfl);

    // towers (2-pass, protects output precision)
    hmma_t<1><<<dim3(TT1 / 128, NB / 128, 2), blk, SM2>>>(
        tfh, tfl, tW1h, tb1, nullptr, th1h, th1l,
        TT1, NH2, 15, NH2, (size_t)NB * NH2, (size_t)TT1 * NH2, TT1, (size_t)NB * TT1, 1);
    hmma_t<1><<<dim3(1, NB / 128, 2), blk, SM2>>>(
        th1h, th1l, tW2h, tb2, out + O6, nullptr, nullptr,
        TT2, TT1, 7, TT1, (size_t)NB * TT1, (size_t)TT2 * TT1, TT2, (size_t)NB * TT2, 0);
    preds_kernel<<<NB * 2 / 8, 256>>>(out, pW, pb, out);

    // ---- phase 2: cascade (CE1 collapsed, one-pass) ----
    cx_kernel<<<NB, 256>>>(x, out, cxh);
    hmma_t<0><<<dim3(NH1 / 128, NB / 128, NE), blk, SM1>>>(
        cxh, nullptr, CUh, ceb1, nullptr, Hh, nullptr,
        NH1, 1024, 31, 1024, 0, (size_t)NH1 * 1024, NH1, (size_t)NB * NH1, 2);
    hmma_t<0><<<dim3(NH2 / 128, NB / 128, NE), blk, SM1>>>(
        Hh, nullptr, CW2h, ceb2, pFEA, nullptr, nullptr,
        NH2, NH1, 31, NH1, (size_t)NB * NH1, (size_t)NH2 * NH1, NH2, (size_t)NB * NH2, 0);
    cgate_kernel<<<NB / 8, 256>>>(x, out, pUG, cgb, pCG);
    combine1c<<<NB, 256>>>(pFEA, pCG, out + O5, cth, ctl);

    hmma_t<1><<<dim3(TT1 / 128, NB / 128, 1), blk, SM2>>>(
        cth, ctl, cW1h, ctb1, nullptr, ch1h, ch1l,
        TT1, NH2, 15, NH2, 0, 0, 0, (size_t)NB * TT1, 1);
    hmma_t<1><<<dim3(1, NB / 128, 1), blk, SM2>>>(
        ch1h, ch1l, cW2h, ctb2, out + O8, nullptr, nullptr,
        TT2, TT1, 7, TT1, 0, 0, 0, 0, 0);
    pconv_kernel<<<NB / 8, 256>>>(out, cpW, cpb, out);
}